// round 7
// baseline (speedup 1.0000x reference)
#include <cuda_runtime.h>
#include <cuda_bf16.h>
#include <math.h>
#include <stdint.h>

#define Bsz 128
#define Tt  512
#define H3  1536
#define BT  65536
#define NCTA 128

__device__ float g_G[201326592];    // [dir][b*T+t][1536]
__device__ float g_out[67108864];   // [b][t][1024] fp32
__device__ __nv_bfloat16 g_outh[67108864];
__device__ __nv_bfloat16 g_outl[67108864];
__device__ float g_scores[65536];
__device__ int   g_tok2[131072];
__device__ unsigned g_cnt4[4], g_gen4[4], g_done;

// bf16 split operands
__device__ __nv_bfloat16 g_Xh[67108864];  // [2*BT][512]
__device__ __nv_bfloat16 g_Xl[67108864];
__device__ __nv_bfloat16 g_Wh[1572864];   // [2][1536][512]
__device__ __nv_bfloat16 g_Wl[1572864];
__device__ __nv_bfloat16 g_Wph[524288];   // [512][1024]
__device__ __nv_bfloat16 g_Wpl[524288];
__device__ __nv_bfloat16 g_hbh[262144];   // [ph][d][128][512]
__device__ __nv_bfloat16 g_hbl[262144];

// ---------------------------------------------------------------- helpers
__device__ __forceinline__ uint32_t smem_u32(const void* p)
{
    uint32_t a;
    asm("{ .reg .u64 t; cvta.to.shared.u64 t, %1; cvt.u32.u64 %0, t; }" : "=r"(a) : "l"(p));
    return a;
}
__device__ __forceinline__ void cp16(uint32_t dst, const void* src)
{
    asm volatile("cp.async.cg.shared.global [%0], [%1], 16;" :: "r"(dst), "l"(src) : "memory");
}
__device__ __forceinline__ void cp_commit()
{
    asm volatile("cp.async.commit_group;" ::: "memory");
}
__device__ __forceinline__ void ldsm4(uint32_t* r, uint32_t addr)
{
    asm volatile("ldmatrix.sync.aligned.m8n8.x4.shared.b16 {%0,%1,%2,%3}, [%4];"
                 : "=r"(r[0]), "=r"(r[1]), "=r"(r[2]), "=r"(r[3]) : "r"(addr));
}
__device__ __forceinline__ void ldsm2(uint32_t* r, uint32_t addr)
{
    asm volatile("ldmatrix.sync.aligned.m8n8.x2.shared.b16 {%0,%1}, [%2];"
                 : "=r"(r[0]), "=r"(r[1]) : "r"(addr));
}
__device__ __forceinline__ void mma16816(float* c, const uint32_t* a, uint32_t b0, uint32_t b1)
{
    asm volatile("mma.sync.aligned.m16n8k16.row.col.f32.bf16.bf16.f32 "
                 "{%0,%1,%2,%3}, {%4,%5,%6,%7}, {%8,%9}, {%0,%1,%2,%3};"
                 : "+f"(c[0]), "+f"(c[1]), "+f"(c[2]), "+f"(c[3])
                 : "r"(a[0]), "r"(a[1]), "r"(a[2]), "r"(a[3]), "r"(b0), "r"(b1));
}
__device__ __forceinline__ void split_bf16(float v, __nv_bfloat16& h, __nv_bfloat16& l)
{
    h = __float2bfloat16(v);
    l = __float2bfloat16(v - __bfloat162float(h));
}

// ---------------------------------------------------------------- K0
__global__ void k_init(const int* __restrict__ tokens, const int* __restrict__ lengths)
{
    int i = blockIdx.x * blockDim.x + threadIdx.x;
    if (i >= BT) return;
    int b = i >> 9, t = i & 511;
    g_tok2[i] = tokens[i];
    int rt = lengths[b] - 1 - t;
    if (rt < 0) rt = 0;
    g_tok2[BT + i] = tokens[(b << 9) + rt];
    g_scores[i] = 0.f;
    ((uint2*)g_hbh)[i] = make_uint2(0u, 0u);
    ((uint2*)g_hbl)[i] = make_uint2(0u, 0u);
}

// ---------------------------------------------------------------- conv kernels
__global__ void k_convX(const float* __restrict__ emb)
{
    size_t idx = (size_t)blockIdx.x * 256 + threadIdx.x;
    size_t e = idx * 4;
    size_t row = e >> 9;
    int k = (int)(e & 511);
    int tok = g_tok2[row];
    float4 v = *(const float4*)(emb + (size_t)tok * 512 + k);
    float vv[4] = {v.x, v.y, v.z, v.w};
    __nv_bfloat16 h[4], l[4];
    #pragma unroll
    for (int j = 0; j < 4; j++) split_bf16(vv[j], h[j], l[j]);
    __nv_bfloat162* ph = (__nv_bfloat162*)(g_Xh + row * 512 + k);
    __nv_bfloat162* pl = (__nv_bfloat162*)(g_Xl + row * 512 + k);
    ph[0] = __nv_bfloat162{h[0], h[1]}; ph[1] = __nv_bfloat162{h[2], h[3]};
    pl[0] = __nv_bfloat162{l[0], l[1]}; pl[1] = __nv_bfloat162{l[2], l[3]};
}

__global__ void k_convW(const float* __restrict__ Wf, const float* __restrict__ Wb)
{
    size_t idx = (size_t)blockIdx.x * 256 + threadIdx.x;
    size_t e = idx * 4;
    size_t row = e >> 9;
    int k = (int)(e & 511);
    int d = (int)(row >= 1536);
    size_t n = row - (size_t)d * 1536;
    const float* W = d ? Wb : Wf;
    float4 v = *(const float4*)(W + n * 512 + k);
    float vv[4] = {v.x, v.y, v.z, v.w};
    __nv_bfloat16 h[4], l[4];
    #pragma unroll
    for (int j = 0; j < 4; j++) split_bf16(vv[j], h[j], l[j]);
    __nv_bfloat162* ph = (__nv_bfloat162*)(g_Wh + row * 512 + k);
    __nv_bfloat162* pl = (__nv_bfloat162*)(g_Wl + row * 512 + k);
    ph[0] = __nv_bfloat162{h[0], h[1]}; ph[1] = __nv_bfloat162{h[2], h[3]};
    pl[0] = __nv_bfloat162{l[0], l[1]}; pl[1] = __nv_bfloat162{l[2], l[3]};
}

__global__ void k_convP(const float* __restrict__ Wp)
{
    size_t idx = (size_t)blockIdx.x * 256 + threadIdx.x;
    size_t e = idx * 4;
    float4 v = *(const float4*)(Wp + e);
    float vv[4] = {v.x, v.y, v.z, v.w};
    __nv_bfloat16 h[4], l[4];
    #pragma unroll
    for (int j = 0; j < 4; j++) split_bf16(vv[j], h[j], l[j]);
    __nv_bfloat162* ph = (__nv_bfloat162*)(g_Wph + e);
    __nv_bfloat162* pl = (__nv_bfloat162*)(g_Wpl + e);
    ph[0] = __nv_bfloat162{h[0], h[1]}; ph[1] = __nv_bfloat162{h[2], h[3]};
    pl[0] = __nv_bfloat162{l[0], l[1]}; pl[1] = __nv_bfloat162{l[2], l[3]};
}

// ---------------------------------------------------------------- shared GEMM staging
// Per buffer (40960 B): Ah@0, Al@10240, Bh@20480, Bl@30720; rows stride 80 B
#define TBUF 40960
#define SMEM_TC (3 * TBUF)
extern __shared__ char sm_tc[];

__device__ __forceinline__ void issue_chunk(
    uint32_t sbase, const __nv_bfloat16* Ah, const __nv_bfloat16* Al,
    const __nv_bfloat16* Bh, const __nv_bfloat16* Bl, int k0, int tid, int ldk)
{
    const __nv_bfloat16* srcs[4] = {Ah, Al, Bh, Bl};
    #pragma unroll
    for (int j = 0; j < 8; j++) {
        int L = tid + j * 256;
        int mat = L >> 9, rem = L & 511, row = rem >> 2, q = rem & 3;
        const char* gp = (const char*)(srcs[mat] + (size_t)row * ldk + k0) + q * 16;
        cp16(sbase + mat * 10240 + row * 80 + q * 16, gp);
    }
    cp_commit();
}

// ---------------------------------------------------------------- K1: input-gate GEMM (tensor)
__global__ void __launch_bounds__(256) k_gemm_ih_tc(
    const float* __restrict__ bf, const float* __restrict__ bb)
{
    uint32_t sb = smem_u32(sm_tc);
    int tid = threadIdx.x, wid = tid >> 5, lane = tid & 31;
    int d = blockIdx.z, mb = blockIdx.y * 128, nb = blockIdx.x * 128;
    const float* bias = (d ? bb : bf) + nb;

    const __nv_bfloat16* Xh = g_Xh + (size_t)(d * BT + mb) * 512;
    const __nv_bfloat16* Xl = g_Xl + (size_t)(d * BT + mb) * 512;
    const __nv_bfloat16* Wh = g_Wh + (size_t)(d * 1536 + nb) * 512;
    const __nv_bfloat16* Wl = g_Wl + (size_t)(d * 1536 + nb) * 512;

    int wm = (wid & 1) * 64;
    int wn = (wid >> 1) * 32;

    float acc[4][4][4];
    #pragma unroll
    for (int f = 0; f < 4; f++)
        #pragma unroll
        for (int n = 0; n < 4; n++)
            #pragma unroll
            for (int r = 0; r < 4; r++) acc[f][n][r] = 0.f;

    issue_chunk(sb,        Xh, Xl, Wh, Wl, 0,  tid, 512);
    issue_chunk(sb + TBUF, Xh, Xl, Wh, Wl, 32, tid, 512);

    int arow = (lane & 15);
    int ahk  = ((lane >> 4) & 1) * 16;
    int brow = (lane & 7) + ((lane >> 4) & 1) * 8;
    int bhk  = ((lane >> 3) & 1) * 16;

    for (int c = 0; c < 16; c++) {
        if (c < 15) asm volatile("cp.async.wait_group 1;" ::: "memory");
        else        asm volatile("cp.async.wait_group 0;" ::: "memory");
        __syncthreads();
        if (c + 2 < 16)
            issue_chunk(sb + ((c + 2) % 3) * TBUF, Xh, Xl, Wh, Wl, (c + 2) * 32, tid, 512);
        uint32_t base = sb + (c % 3) * TBUF;
        uint32_t aA = base +         (wm + arow) * 80 + ahk;
        uint32_t aB = base + 20480 + (wn + brow) * 80 + bhk;

        #pragma unroll
        for (int s = 0; s < 2; s++) {
            uint32_t ah[4][4], al[4][4], bh[2][4], bl[2][4];
            #pragma unroll
            for (int f = 0; f < 4; f++) {
                ldsm4(ah[f], aA + f * 16 * 80 + s * 32);
                ldsm4(al[f], aA + 10240 + f * 16 * 80 + s * 32);
            }
            #pragma unroll
            for (int g = 0; g < 2; g++) {
                ldsm4(bh[g], aB + g * 16 * 80 + s * 32);
                ldsm4(bl[g], aB + 10240 + g * 16 * 80 + s * 32);
            }
            #pragma unroll
            for (int f = 0; f < 4; f++)
                #pragma unroll
                for (int n = 0; n < 4; n++) {
                    mma16816(acc[f][n], ah[f], bh[n >> 1][(n & 1) * 2], bh[n >> 1][(n & 1) * 2 + 1]);
                    mma16816(acc[f][n], ah[f], bl[n >> 1][(n & 1) * 2], bl[n >> 1][(n & 1) * 2 + 1]);
                    mma16816(acc[f][n], al[f], bh[n >> 1][(n & 1) * 2], bh[n >> 1][(n & 1) * 2 + 1]);
                }
        }
    }

    #pragma unroll
    for (int f = 0; f < 4; f++) {
        int row = mb + wm + f * 16 + (lane >> 2);
        float* gp0 = g_G + ((size_t)d * BT + row) * H3 + nb;
        float* gp1 = gp0 + 8 * H3;
        #pragma unroll
        for (int n = 0; n < 4; n++) {
            int col = wn + n * 8 + (lane & 3) * 2;
            float b0 = __ldg(bias + col), b1 = __ldg(bias + col + 1);
            *(float2*)(gp0 + col) = make_float2(acc[f][n][0] + b0, acc[f][n][1] + b1);
            *(float2*)(gp1 + col) = make_float2(acc[f][n][2] + b0, acc[f][n][3] + b1);
        }
    }
}

// ---------------------------------------------------------------- group barrier
__device__ __forceinline__ void group_barrier(int gid, unsigned target)
{
    __syncthreads();
    if (threadIdx.x == 0) {
        __threadfence();
        unsigned a = atomicAdd(&g_cnt4[gid], 1u) + 1u;
        if (a == target * 32u) {
            atomicAdd(&g_gen4[gid], 1u);
        } else {
            while (*(volatile unsigned*)&g_gen4[gid] < target) { }
        }
        __threadfence();
    }
    __syncthreads();
}

// ---------------------------------------------------------------- K2: tensor-core bi-GRU recurrence
// smem: Wh 49920 | Wl 49920 | H 3 bufs x 34816 | gate 64x52 fp32
#define K2_WH   0
#define K2_WL   49920
#define K2_H    99840
#define K2_GATE 204288
#define K2_SMEM 217600
extern __shared__ char sm2[];

__device__ __forceinline__ void k2_stage(uint32_t dsth, size_t hsrc, int kc, int tid)
{
    #pragma unroll
    for (int j = 0; j < 4; j++) {
        int L = tid + j * 256;
        int row = L >> 4, q = L & 15;
        cp16(dsth + row * 272 + q * 16,         (const char*)(g_hbh + hsrc + (size_t)row * 512 + kc) + q * 16);
        cp16(dsth + 17408 + row * 272 + q * 16, (const char*)(g_hbl + hsrc + (size_t)row * 512 + kc) + q * 16);
    }
    cp_commit();
}

__global__ void __launch_bounds__(256) k_gru_tc(
    const float* __restrict__ Whh_f, const float* __restrict__ bhh_f,
    const float* __restrict__ Whh_b, const float* __restrict__ bhh_b,
    const int*   __restrict__ lengths)
{
    uint32_t sb = smem_u32(sm2);
    int tid = threadIdx.x, wid = tid >> 5, lane = tid & 31;
    int cid = blockIdx.x;
    int d = cid >> 6, bg = (cid >> 5) & 1, ng = cid & 31;
    int gid = d * 2 + bg;
    const float* Whh = d ? Whh_b : Whh_f;
    const float* bhh = d ? bhh_b : bhh_f;

    for (int i = tid; i < 48 * 128; i += 256) {
        int row = i >> 7, k4 = (i & 127) << 2;
        int g = row >> 4, ul = row & 15;
        float4 w = *(const float4*)(Whh + (size_t)(g * 512 + ng * 16 + ul) * 512 + k4);
        float vv[4] = {w.x, w.y, w.z, w.w};
        __nv_bfloat16 h[4], l[4];
        #pragma unroll
        for (int j = 0; j < 4; j++) split_bf16(vv[j], h[j], l[j]);
        char* ph = sm2 + K2_WH + row * 1040 + k4 * 2;
        char* pl = sm2 + K2_WL + row * 1040 + k4 * 2;
        *(__nv_bfloat162*)ph       = __nv_bfloat162{h[0], h[1]};
        *(__nv_bfloat162*)(ph + 4) = __nv_bfloat162{h[2], h[3]};
        *(__nv_bfloat162*)pl       = __nv_bfloat162{l[0], l[1]};
        *(__nv_bfloat162*)(pl + 4) = __nv_bfloat162{l[2], l[3]};
    }

    int b_loc  = tid >> 2;
    int u0     = (tid & 3) * 4;
    int b_glob = bg * 64 + b_loc;
    int len_b  = lengths[b_glob];
    float bh_r[4], bh_z[4], bh_n[4];
    #pragma unroll
    for (int j = 0; j < 4; j++) {
        int u = ng * 16 + u0 + j;
        bh_r[j] = bhh[u]; bh_z[j] = bhh[512 + u]; bh_n[j] = bhh[1024 + u];
    }
    float hprev[4] = {0.f, 0.f, 0.f, 0.f};

    int m0  = (wid & 3) * 16;
    int n0w = (wid >> 2) * 24;
    uint32_t aoffA  = (uint32_t)((m0 + (lane & 15)) * 272 + ((lane >> 4) & 1) * 16);
    uint32_t aoffB4 = (uint32_t)((n0w + (lane & 7) + ((lane >> 4) & 1) * 8) * 1040 + ((lane >> 3) & 1) * 16);
    uint32_t aoffB2 = (uint32_t)((n0w + 16 + (lane & 7)) * 1040 + ((lane >> 3) & 1) * 16);

    float* gsm = (float*)(sm2 + K2_GATE);
    __syncthreads();

    for (int t = 0; t < 512; t++) {
        int ph = t & 1;
        const float* gp = g_G + (size_t)d * BT * H3 + ((size_t)b_glob * 512 + t) * H3 + ng * 16 + u0;
        float4 gir = __ldg((const float4*)gp);
        float4 giz = __ldg((const float4*)(gp + 512));
        float4 gin = __ldg((const float4*)(gp + 1024));

        size_t hsrc = ((size_t)(ph * 2 + d) * 128 + bg * 64) * 512;
        k2_stage(sb + K2_H,         hsrc, 0,   tid);
        k2_stage(sb + K2_H + 34816, hsrc, 128, tid);

        float acc[3][4];
        #pragma unroll
        for (int n = 0; n < 3; n++)
            #pragma unroll
            for (int r = 0; r < 4; r++) acc[n][r] = 0.f;

        for (int c = 0; c < 4; c++) {
            if (c < 3) asm volatile("cp.async.wait_group 1;" ::: "memory");
            else       asm volatile("cp.async.wait_group 0;" ::: "memory");
            __syncthreads();
            if (c + 2 < 4)
                k2_stage(sb + K2_H + ((c + 2) % 3) * 34816, hsrc, (c + 2) * 128, tid);
            uint32_t hb_hi = sb + K2_H + (c % 3) * 34816;
            uint32_t hb_lo = hb_hi + 17408;
            #pragma unroll
            for (int kt = 0; kt < 8; kt++) {
                uint32_t koffH = kt * 32;
                uint32_t koffW = (uint32_t)(c * 128 + kt * 16) * 2;
                uint32_t ah[4], al[4], bh4[4], b2h[2], bl4[4], b2l[2];
                ldsm4(ah, hb_hi + aoffA + koffH);
                ldsm4(al, hb_lo + aoffA + koffH);
                ldsm4(bh4, sb + K2_WH + aoffB4 + koffW);
                ldsm2(b2h, sb + K2_WH + aoffB2 + koffW);
                ldsm4(bl4, sb + K2_WL + aoffB4 + koffW);
                ldsm2(b2l, sb + K2_WL + aoffB2 + koffW);
                mma16816(acc[0], ah, bh4[0], bh4[1]);
                mma16816(acc[1], ah, bh4[2], bh4[3]);
                mma16816(acc[2], ah, b2h[0], b2h[1]);
                mma16816(acc[0], ah, bl4[0], bl4[1]);
                mma16816(acc[1], ah, bl4[2], bl4[3]);
                mma16816(acc[2], ah, b2l[0], b2l[1]);
                mma16816(acc[0], al, bh4[0], bh4[1]);
                mma16816(acc[1], al, bh4[2], bh4[3]);
                mma16816(acc[2], al, b2h[0], b2h[1]);
            }
        }

        // write gate pre-activations to smem (per-warp disjoint regions)
        int grow = m0 + (lane >> 2);
        #pragma unroll
        for (int j = 0; j < 3; j++) {
            int col = n0w + j * 8 + (lane & 3) * 2;
            gsm[grow * 52 + col]           = acc[j][0];
            gsm[grow * 52 + col + 1]       = acc[j][1];
            gsm[(grow + 8) * 52 + col]     = acc[j][2];
            gsm[(grow + 8) * 52 + col + 1] = acc[j][3];
        }
        __syncthreads();

        // gate math + vectorized outputs
        float gi_r[4], gi_z[4], gi_n[4];
        *(float4*)gi_r = gir; *(float4*)gi_z = giz; *(float4*)gi_n = gin;
        bool m = (t < len_b);
        size_t hwb = ((size_t)((ph ^ 1) * 2 + d) * 128 + b_glob) * 512 + ng * 16;
        int orow = (d == 0) ? t : (m ? (len_b - 1 - t) : t);
        size_t ob = ((size_t)b_glob * 512 + orow) * 1024 + d * 512 + ng * 16;

        float hm[4], ov[4];
        #pragma unroll
        for (int j = 0; j < 4; j++) {
            int u = u0 + j;
            float ar = gsm[b_loc * 52 + u];
            float az = gsm[b_loc * 52 + 16 + u];
            float an = gsm[b_loc * 52 + 32 + u];
            float rr = 1.f / (1.f + expf(-(gi_r[j] + ar + bh_r[j])));
            float zz = 1.f / (1.f + expf(-(gi_z[j] + az + bh_z[j])));
            float nn = tanhf(gi_n[j] + rr * (an + bh_n[j]));
            float hn = (1.f - zz) * nn + zz * hprev[j];
            hm[j] = m ? hn : hprev[j];
            hprev[j] = hm[j];
            ov[j] = m ? hn : 0.f;
        }
        __nv_bfloat16 hh[4], hl[4], oh[4], ol[4];
        #pragma unroll
        for (int j = 0; j < 4; j++) {
            split_bf16(hm[j], hh[j], hl[j]);
            split_bf16(ov[j], oh[j], ol[j]);
        }
        *(__nv_bfloat162*)(g_hbh + hwb + u0)     = __nv_bfloat162{hh[0], hh[1]};
        *(__nv_bfloat162*)(g_hbh + hwb + u0 + 2) = __nv_bfloat162{hh[2], hh[3]};
        *(__nv_bfloat162*)(g_hbl + hwb + u0)     = __nv_bfloat162{hl[0], hl[1]};
        *(__nv_bfloat162*)(g_hbl + hwb + u0 + 2) = __nv_bfloat162{hl[2], hl[3]};
        *(float4*)(g_out + ob + u0) = make_float4(ov[0], ov[1], ov[2], ov[3]);
        *(__nv_bfloat162*)(g_outh + ob + u0)     = __nv_bfloat162{oh[0], oh[1]};
        *(__nv_bfloat162*)(g_outh + ob + u0 + 2) = __nv_bfloat162{oh[2], oh[3]};
        *(__nv_bfloat162*)(g_outl + ob + u0)     = __nv_bfloat162{ol[0], ol[1]};
        *(__nv_bfloat162*)(g_outl + ob + u0 + 2) = __nv_bfloat162{ol[2], ol[3]};

        group_barrier(gid, (unsigned)(t + 1));
    }

    if (tid == 0) {
        unsigned old = atomicAdd(&g_done, 1u);
        if (old == NCTA - 1) {
            #pragma unroll
            for (int g = 0; g < 4; g++) { g_cnt4[g] = 0; g_gen4[g] = 0; }
            g_done = 0;
            __threadfence();
        }
    }
}

// ---------------------------------------------------------------- K3: tensor proj + fused ctx-dot
__global__ void __launch_bounds__(256) k_gemm_proj_tc(
    const float* __restrict__ bp, const float* __restrict__ ctx)
{
    uint32_t sb = smem_u32(sm_tc);
    int tid = threadIdx.x, wid = tid >> 5, lane = tid & 31;
    int mb = blockIdx.y * 128, nb = blockIdx.x * 128;

    const __nv_bfloat16* Ah = g_outh + (size_t)mb * 1024;
    const __nv_bfloat16* Al = g_outl + (size_t)mb * 1024;
    const __nv_bfloat16* Bh = g_Wph + (size_t)nb * 1024;
    const __nv_bfloat16* Bl = g_Wpl + (size_t)nb * 1024;

    int wm = (wid & 1) * 64;
    int wn = (wid >> 1) * 32;

    float acc[4][4][4];
    #pragma unroll
    for (int f = 0; f < 4; f++)
        #pragma unroll
        for (int n = 0; n < 4; n++)
            #pragma unroll
            for (int r = 0; r < 4; r++) acc[f][n][r] = 0.f;

    issue_chunk(sb,        Ah, Al, Bh, Bl, 0,  tid, 1024);
    issue_chunk(sb + TBUF, Ah, Al, Bh, Bl, 32, tid, 1024);

    int arow = (lane & 15);
    int ahk  = ((lane >> 4) & 1) * 16;
    int brow = (lane & 7) + ((lane >> 4) & 1) * 8;
    int bhk  = ((lane >> 3) & 1) * 16;

    for (int c = 0; c < 32; c++) {
        if (c < 31) asm volatile("cp.async.wait_group 1;" ::: "memory");
        else        asm volatile("cp.async.wait_group 0;" ::: "memory");
        __syncthreads();
        if (c + 2 < 32)
            issue_chunk(sb + ((c + 2) % 3) * TBUF, Ah, Al, Bh, Bl, (c + 2) * 32, tid, 1024);
        uint32_t base = sb + (c % 3) * TBUF;
        uint32_t aA = base +         (wm + arow) * 80 + ahk;
        uint32_t aB = base + 20480 + (wn + brow) * 80 + bhk;

        #pragma unroll
        for (int s = 0; s < 2; s++) {
            uint32_t ah[4][4], al[4][4], bh[2][4], bl[2][4];
            #pragma unroll
            for (int f = 0; f < 4; f++) {
                ldsm4(ah[f], aA + f * 16 * 80 + s * 32);
                ldsm4(al[f], aA + 10240 + f * 16 * 80 + s * 32);
            }
            #pragma unroll
            for (int g = 0; g < 2; g++) {
                ldsm4(bh[g], aB + g * 16 * 80 + s * 32);
                ldsm4(bl[g], aB + 10240 + g * 16 * 80 + s * 32);
            }
            #pragma unroll
            for (int f = 0; f < 4; f++)
                #pragma unroll
                for (int n = 0; n < 4; n++) {
                    mma16816(acc[f][n], ah[f], bh[n >> 1][(n & 1) * 2], bh[n >> 1][(n & 1) * 2 + 1]);
                    mma16816(acc[f][n], ah[f], bl[n >> 1][(n & 1) * 2], bl[n >> 1][(n & 1) * 2 + 1]);
                    mma16816(acc[f][n], al[f], bh[n >> 1][(n & 1) * 2], bh[n >> 1][(n & 1) * 2 + 1]);
                }
        }
    }

    #pragma unroll
    for (int f = 0; f < 4; f++) {
        int r0 = mb + wm + f * 16 + (lane >> 2);
        float p0 = 0.f, p1 = 0.f;
        #pragma unroll
        for (int n = 0; n < 4; n++) {
            int col = nb + wn + n * 8 + (lane & 3) * 2;
            float c0 = __ldg(ctx + col), c1 = __ldg(ctx + col + 1);
            float b0 = __ldg(bp + col),  b1 = __ldg(bp + col + 1);
            p0 += tanhf(acc[f][n][0] + b0) * c0 + tanhf(acc[f][n][1] + b1) * c1;
            p1 += tanhf(acc[f][n][2] + b0) * c0 + tanhf(acc[f][n][3] + b1) * c1;
        }
        p0 += __shfl_xor_sync(0xffffffffu, p0, 1);
        p0 += __shfl_xor_sync(0xffffffffu, p0, 2);
        p1 += __shfl_xor_sync(0xffffffffu, p1, 1);
        p1 += __shfl_xor_sync(0xffffffffu, p1, 2);
        if ((lane & 3) == 0) {
            atomicAdd(&g_scores[r0], p0);
            atomicAdd(&g_scores[r0 + 8], p1);
        }
    }
}

// ---------------------------------------------------------------- K4: softmax + pooling + SELU + logits
__global__ void __launch_bounds__(512) k_final(
    const int* __restrict__ lengths,
    const float* __restrict__ Wl, const float* __restrict__ bl,
    float* __restrict__ out, int out_size)
{
    __shared__ float sh[512];
    __shared__ float attn[512];
    __shared__ float lg[2];
    int b = blockIdx.x, tid = threadIdx.x;
    int len = lengths[b];
    float s = (tid < len) ? g_scores[b * 512 + tid] : -1e30f;
    sh[tid] = s; __syncthreads();
    for (int o = 256; o > 0; o >>= 1) { if (tid < o) sh[tid] = fmaxf(sh[tid], sh[tid + o]); __syncthreads(); }
    float mx = sh[0]; __syncthreads();
    float e = (tid < len) ? expf(s - mx) : 0.f;
    sh[tid] = e; __syncthreads();
    for (int o = 256; o > 0; o >>= 1) { if (tid < o) sh[tid] += sh[tid + o]; __syncthreads(); }
    float a = e / sh[0];
    attn[tid] = a;
    int attn_ofs = (out_size >= 65792) ? 256 : 0;
    if (out_size != 256) out[attn_ofs + b * 512 + tid] = a;
    if (tid == 0) { lg[0] = 0.f; lg[1] = 0.f; }
    __syncthreads();

    const float* ob = g_out + (long)b * 512 * 1024;
    float s0 = 0.f, s1 = 0.f;
    for (int t = 0; t < 512; t++) {
        float at = attn[t];
        s0 = fmaf(at, ob[(long)t * 1024 + tid],       s0);
        s1 = fmaf(at, ob[(long)t * 1024 + 512 + tid], s1);
    }
    const float SC = 1.0507009873554805f, AL = 1.6732632423543772f;
    s0 = (s0 > 0.f) ? SC * s0 : SC * AL * (expf(s0) - 1.f);
    s1 = (s1 > 0.f) ? SC * s1 : SC * AL * (expf(s1) - 1.f);
    float p0 = s0 * Wl[tid]        + s1 * Wl[512 + tid];
    float p1 = s0 * Wl[1024 + tid] + s1 * Wl[1536 + tid];
    #pragma unroll
    for (int o = 16; o > 0; o >>= 1) {
        p0 += __shfl_xor_sync(0xffffffffu, p0, o);
        p1 += __shfl_xor_sync(0xffffffffu, p1, o);
    }
    if ((tid & 31) == 0) { atomicAdd(&lg[0], p0); atomicAdd(&lg[1], p1); }
    __syncthreads();
    if (tid < 2 && out_size != 65536) out[b * 2 + tid] = lg[tid] + bl[tid];
}

// ---------------------------------------------------------------- launch
extern "C" void kernel_launch(void* const* d_in, const int* in_sizes, int n_in,
                              void* d_out, int out_size)
{
    const int*   tokens  = (const int*)d_in[0];
    const int*   lengths = (const int*)d_in[1];
    const float* emb     = (const float*)d_in[2];
    const float* Wih_f   = (const float*)d_in[3];
    const float* Whh_f   = (const float*)d_in[4];
    const float* bih_f   = (const float*)d_in[5];
    const float* bhh_f   = (const float*)d_in[6];
    const float* Wih_b   = (const float*)d_in[7];
    const float* Whh_b   = (const float*)d_in[8];
    const float* bih_b   = (const float*)d_in[9];
    const float* bhh_b   = (const float*)d_in[10];
    const float* Wp      = (const float*)d_in[11];
    const float* bp      = (const float*)d_in[12];
    const float* ctx     = (const float*)d_in[13];
    const float* Wl      = (const float*)d_in[14];
    const float* bl      = (const float*)d_in[15];
    float* out = (float*)d_out;

    k_init<<<BT / 256, 256>>>(tokens, lengths);
    k_convW<<<1536, 256>>>(Wih_f, Wih_b);
    k_convX<<<65536, 256>>>(emb);
    k_convP<<<512, 256>>>(Wp);

    cudaFuncSetAttribute(k_gemm_ih_tc, cudaFuncAttributeMaxDynamicSharedMemorySize, SMEM_TC);
    dim3 g1(12, 512, 2);
    k_gemm_ih_tc<<<g1, 256, SMEM_TC>>>(bih_f, bih_b);

    cudaFuncSetAttribute(k_gru_tc, cudaFuncAttributeMaxDynamicSharedMemorySize, K2_SMEM);
    k_gru_tc<<<NCTA, 256, K2_SMEM>>>(Whh_f, bhh_f, Whh_b, bhh_b, lengths);

    cudaFuncSetAttribute(k_gemm_proj_tc, cudaFuncAttributeMaxDynamicSharedMemorySize, SMEM_TC);
    dim3 g3(4, 512);
    k_gemm_proj_tc<<<g3, 256, SMEM_TC>>>(bp, ctx);

    k_final<<<Bsz, 512>>>(lengths, Wl, bl, out, out_size);
}

// round 9
// speedup vs baseline: 1.0296x; 1.0296x over previous
#include <cuda_runtime.h>
#include <cuda_bf16.h>
#include <math.h>
#include <stdint.h>

#define Bsz 128
#define Tt  512
#define H3  1536
#define BT  65536
#define NCTA 128

__device__ float g_G[201326592];    // [dir][b*T+t][1536]
__device__ float g_out[67108864];   // [b][t][1024] fp32
__device__ __nv_bfloat16 g_outh[67108864];
__device__ __nv_bfloat16 g_outl[67108864];
__device__ float g_scores[65536];
__device__ int   g_tok2[131072];
__device__ unsigned g_cnt4[4], g_gen4[4], g_done;

// bf16 split operands
__device__ __nv_bfloat16 g_Xh[67108864];  // [2*BT][512]
__device__ __nv_bfloat16 g_Xl[67108864];
__device__ __nv_bfloat16 g_Wh[1572864];   // [2][1536][512]
__device__ __nv_bfloat16 g_Wl[1572864];
__device__ __nv_bfloat16 g_Wph[524288];   // [512][1024]
__device__ __nv_bfloat16 g_Wpl[524288];
__device__ __nv_bfloat16 g_hbh[262144];   // [ph][d][128][512]
__device__ __nv_bfloat16 g_hbl[262144];

// ---------------------------------------------------------------- helpers
__device__ __forceinline__ uint32_t smem_u32(const void* p)
{
    uint32_t a;
    asm("{ .reg .u64 t; cvta.to.shared.u64 t, %1; cvt.u32.u64 %0, t; }" : "=r"(a) : "l"(p));
    return a;
}
__device__ __forceinline__ void cp16(uint32_t dst, const void* src)
{
    asm volatile("cp.async.cg.shared.global [%0], [%1], 16;" :: "r"(dst), "l"(src) : "memory");
}
__device__ __forceinline__ void cp_commit()
{
    asm volatile("cp.async.commit_group;" ::: "memory");
}
__device__ __forceinline__ void ldsm4(uint32_t* r, uint32_t addr)
{
    asm volatile("ldmatrix.sync.aligned.m8n8.x4.shared.b16 {%0,%1,%2,%3}, [%4];"
                 : "=r"(r[0]), "=r"(r[1]), "=r"(r[2]), "=r"(r[3]) : "r"(addr));
}
__device__ __forceinline__ void ldsm2(uint32_t* r, uint32_t addr)
{
    asm volatile("ldmatrix.sync.aligned.m8n8.x2.shared.b16 {%0,%1}, [%2];"
                 : "=r"(r[0]), "=r"(r[1]) : "r"(addr));
}
__device__ __forceinline__ void mma16816(float* c, const uint32_t* a, uint32_t b0, uint32_t b1)
{
    asm volatile("mma.sync.aligned.m16n8k16.row.col.f32.bf16.bf16.f32 "
                 "{%0,%1,%2,%3}, {%4,%5,%6,%7}, {%8,%9}, {%0,%1,%2,%3};"
                 : "+f"(c[0]), "+f"(c[1]), "+f"(c[2]), "+f"(c[3])
                 : "r"(a[0]), "r"(a[1]), "r"(a[2]), "r"(a[3]), "r"(b0), "r"(b1));
}
__device__ __forceinline__ void split_bf16(float v, __nv_bfloat16& h, __nv_bfloat16& l)
{
    h = __float2bfloat16(v);
    l = __float2bfloat16(v - __bfloat162float(h));
}

// ---------------------------------------------------------------- K0
__global__ void k_init(const int* __restrict__ tokens, const int* __restrict__ lengths)
{
    int i = blockIdx.x * blockDim.x + threadIdx.x;
    if (i >= BT) return;
    int b = i >> 9, t = i & 511;
    g_tok2[i] = tokens[i];
    int rt = lengths[b] - 1 - t;
    if (rt < 0) rt = 0;
    g_tok2[BT + i] = tokens[(b << 9) + rt];
    g_scores[i] = 0.f;
    ((uint2*)g_hbh)[i] = make_uint2(0u, 0u);
    ((uint2*)g_hbl)[i] = make_uint2(0u, 0u);
}

// ---------------------------------------------------------------- conv kernels
__global__ void k_convX(const float* __restrict__ emb)
{
    size_t idx = (size_t)blockIdx.x * 256 + threadIdx.x;
    size_t e = idx * 4;
    size_t row = e >> 9;
    int k = (int)(e & 511);
    int tok = g_tok2[row];
    float4 v = *(const float4*)(emb + (size_t)tok * 512 + k);
    float vv[4] = {v.x, v.y, v.z, v.w};
    __nv_bfloat16 h[4], l[4];
    #pragma unroll
    for (int j = 0; j < 4; j++) split_bf16(vv[j], h[j], l[j]);
    __nv_bfloat162* ph = (__nv_bfloat162*)(g_Xh + row * 512 + k);
    __nv_bfloat162* pl = (__nv_bfloat162*)(g_Xl + row * 512 + k);
    ph[0] = __nv_bfloat162{h[0], h[1]}; ph[1] = __nv_bfloat162{h[2], h[3]};
    pl[0] = __nv_bfloat162{l[0], l[1]}; pl[1] = __nv_bfloat162{l[2], l[3]};
}

__global__ void k_convW(const float* __restrict__ Wf, const float* __restrict__ Wb)
{
    size_t idx = (size_t)blockIdx.x * 256 + threadIdx.x;
    size_t e = idx * 4;
    size_t row = e >> 9;
    int k = (int)(e & 511);
    int d = (int)(row >= 1536);
    size_t n = row - (size_t)d * 1536;
    const float* W = d ? Wb : Wf;
    float4 v = *(const float4*)(W + n * 512 + k);
    float vv[4] = {v.x, v.y, v.z, v.w};
    __nv_bfloat16 h[4], l[4];
    #pragma unroll
    for (int j = 0; j < 4; j++) split_bf16(vv[j], h[j], l[j]);
    __nv_bfloat162* ph = (__nv_bfloat162*)(g_Wh + row * 512 + k);
    __nv_bfloat162* pl = (__nv_bfloat162*)(g_Wl + row * 512 + k);
    ph[0] = __nv_bfloat162{h[0], h[1]}; ph[1] = __nv_bfloat162{h[2], h[3]};
    pl[0] = __nv_bfloat162{l[0], l[1]}; pl[1] = __nv_bfloat162{l[2], l[3]};
}

__global__ void k_convP(const float* __restrict__ Wp)
{
    size_t idx = (size_t)blockIdx.x * 256 + threadIdx.x;
    size_t e = idx * 4;
    float4 v = *(const float4*)(Wp + e);
    float vv[4] = {v.x, v.y, v.z, v.w};
    __nv_bfloat16 h[4], l[4];
    #pragma unroll
    for (int j = 0; j < 4; j++) split_bf16(vv[j], h[j], l[j]);
    __nv_bfloat162* ph = (__nv_bfloat162*)(g_Wph + e);
    __nv_bfloat162* pl = (__nv_bfloat162*)(g_Wpl + e);
    ph[0] = __nv_bfloat162{h[0], h[1]}; ph[1] = __nv_bfloat162{h[2], h[3]};
    pl[0] = __nv_bfloat162{l[0], l[1]}; pl[1] = __nv_bfloat162{l[2], l[3]};
}

// ---------------------------------------------------------------- big-tile GEMM staging
// CTA tile 256(M) x 128(N), 512 threads. Per buffer 61440 B:
//   Ah@0 (256x80), Al@20480, Bh@40960 (128x80), Bl@51200
// Chunk = 32 bf16 = 64 bytes/row -> q in 0..3 ONLY (16 B pad stays unwritten).
#define TB2 61440
#define SMEM_TC2 (2 * TB2)
extern __shared__ char sm_tc[];

__device__ __forceinline__ void issue_chunk2(
    uint32_t sbase, const __nv_bfloat16* Ah, const __nv_bfloat16* Al,
    const __nv_bfloat16* Bh, const __nv_bfloat16* Bl, int k0, int tid, int ldk)
{
    #pragma unroll
    for (int j = 0; j < 6; j++) {
        int L = tid + j * 512;          // 0..3071
        if (L < 2048) {                 // A: 2 mats x 256 rows x 4 q
            int mat = (L >= 1024);
            int r = L - mat * 1024;
            int row = r >> 2, q = r & 3;
            const __nv_bfloat16* src = mat ? Al : Ah;
            cp16(sbase + mat * 20480 + row * 80 + q * 16,
                 (const char*)(src + (size_t)row * ldk + k0) + q * 16);
        } else {                        // B: 2 mats x 128 rows x 4 q
            int r = L - 2048;
            int mat = (r >= 512);
            r -= mat * 512;
            int row = r >> 2, q = r & 3;
            const __nv_bfloat16* src = mat ? Bl : Bh;
            cp16(sbase + 40960 + mat * 10240 + row * 80 + q * 16,
                 (const char*)(src + (size_t)row * ldk + k0) + q * 16);
        }
    }
    cp_commit();
}

// ---------------------------------------------------------------- K1: input-gate GEMM (tensor, 256x128)
__global__ void __launch_bounds__(512) k_gemm_ih_tc(
    const float* __restrict__ bf, const float* __restrict__ bb)
{
    uint32_t sb = smem_u32(sm_tc);
    int tid = threadIdx.x, wid = tid >> 5, lane = tid & 31;
    int d = blockIdx.z, mb = blockIdx.y * 256, nb = blockIdx.x * 128;
    const float* bias = (d ? bb : bf) + nb;

    const __nv_bfloat16* Xh = g_Xh + (size_t)(d * BT + mb) * 512;
    const __nv_bfloat16* Xl = g_Xl + (size_t)(d * BT + mb) * 512;
    const __nv_bfloat16* Wh = g_Wh + (size_t)(d * 1536 + nb) * 512;
    const __nv_bfloat16* Wl = g_Wl + (size_t)(d * 1536 + nb) * 512;

    int wm = (wid & 3) * 64;
    int wn = (wid >> 2) * 32;

    float acc[4][4][4];
    #pragma unroll
    for (int f = 0; f < 4; f++)
        #pragma unroll
        for (int n = 0; n < 4; n++)
            #pragma unroll
            for (int r = 0; r < 4; r++) acc[f][n][r] = 0.f;

    issue_chunk2(sb,       Xh, Xl, Wh, Wl, 0,  tid, 512);
    issue_chunk2(sb + TB2, Xh, Xl, Wh, Wl, 32, tid, 512);

    int arow = (lane & 15);
    int ahk  = ((lane >> 4) & 1) * 16;
    int brow = (lane & 7) + ((lane >> 4) & 1) * 8;
    int bhk  = ((lane >> 3) & 1) * 16;

    for (int c = 0; c < 16; c++) {
        if (c < 15) asm volatile("cp.async.wait_group 1;" ::: "memory");
        else        asm volatile("cp.async.wait_group 0;" ::: "memory");
        __syncthreads();
        uint32_t base = sb + (c & 1) * TB2;
        uint32_t aA = base +         (wm + arow) * 80 + ahk;
        uint32_t aB = base + 40960 + (wn + brow) * 80 + bhk;

        #pragma unroll
        for (int s = 0; s < 2; s++) {
            uint32_t ah[4][4], al[4][4], bh[2][4], bl[2][4];
            #pragma unroll
            for (int f = 0; f < 4; f++) {
                ldsm4(ah[f], aA + f * 16 * 80 + s * 32);
                ldsm4(al[f], aA + 20480 + f * 16 * 80 + s * 32);
            }
            #pragma unroll
            for (int g = 0; g < 2; g++) {
                ldsm4(bh[g], aB + g * 16 * 80 + s * 32);
                ldsm4(bl[g], aB + 10240 + g * 16 * 80 + s * 32);
            }
            #pragma unroll
            for (int f = 0; f < 4; f++)
                #pragma unroll
                for (int n = 0; n < 4; n++) {
                    mma16816(acc[f][n], ah[f], bh[n >> 1][(n & 1) * 2], bh[n >> 1][(n & 1) * 2 + 1]);
                    mma16816(acc[f][n], ah[f], bl[n >> 1][(n & 1) * 2], bl[n >> 1][(n & 1) * 2 + 1]);
                    mma16816(acc[f][n], al[f], bh[n >> 1][(n & 1) * 2], bh[n >> 1][(n & 1) * 2 + 1]);
                }
        }
        __syncthreads();
        if (c + 2 < 16)
            issue_chunk2(sb + (c & 1) * TB2, Xh, Xl, Wh, Wl, (c + 2) * 32, tid, 512);
    }

    #pragma unroll
    for (int f = 0; f < 4; f++) {
        int row = mb + wm + f * 16 + (lane >> 2);
        float* gp0 = g_G + ((size_t)d * BT + row) * H3 + nb;
        float* gp1 = gp0 + 8 * H3;
        #pragma unroll
        for (int n = 0; n < 4; n++) {
            int col = wn + n * 8 + (lane & 3) * 2;
            float b0 = __ldg(bias + col), b1 = __ldg(bias + col + 1);
            *(float2*)(gp0 + col) = make_float2(acc[f][n][0] + b0, acc[f][n][1] + b1);
            *(float2*)(gp1 + col) = make_float2(acc[f][n][2] + b0, acc[f][n][3] + b1);
        }
    }
}

// ---------------------------------------------------------------- group barrier
__device__ __forceinline__ void group_barrier(int gid, unsigned target)
{
    __syncthreads();
    if (threadIdx.x == 0) {
        __threadfence();
        unsigned a = atomicAdd(&g_cnt4[gid], 1u) + 1u;
        if (a == target * 32u) {
            atomicAdd(&g_gen4[gid], 1u);
        } else {
            while (*(volatile unsigned*)&g_gen4[gid] < target) { }
        }
        __threadfence();
    }
    __syncthreads();
}

// ---------------------------------------------------------------- K2: tensor-core bi-GRU recurrence (at mma floor)
#define K2_WH   0
#define K2_WL   49920
#define K2_H    99840
#define K2_GATE 204288
#define K2_SMEM 217600
extern __shared__ char sm2[];

__device__ __forceinline__ void k2_stage(uint32_t dsth, size_t hsrc, int kc, int tid)
{
    #pragma unroll
    for (int j = 0; j < 4; j++) {
        int L = tid + j * 256;
        int row = L >> 4, q = L & 15;
        cp16(dsth + row * 272 + q * 16,         (const char*)(g_hbh + hsrc + (size_t)row * 512 + kc) + q * 16);
        cp16(dsth + 17408 + row * 272 + q * 16, (const char*)(g_hbl + hsrc + (size_t)row * 512 + kc) + q * 16);
    }
    cp_commit();
}

__global__ void __launch_bounds__(256) k_gru_tc(
    const float* __restrict__ Whh_f, const float* __restrict__ bhh_f,
    const float* __restrict__ Whh_b, const float* __restrict__ bhh_b,
    const int*   __restrict__ lengths)
{
    uint32_t sb = smem_u32(sm2);
    int tid = threadIdx.x, wid = tid >> 5, lane = tid & 31;
    int cid = blockIdx.x;
    int d = cid >> 6, bg = (cid >> 5) & 1, ng = cid & 31;
    int gid = d * 2 + bg;
    const float* Whh = d ? Whh_b : Whh_f;
    const float* bhh = d ? bhh_b : bhh_f;

    for (int i = tid; i < 48 * 128; i += 256) {
        int row = i >> 7, k4 = (i & 127) << 2;
        int g = row >> 4, ul = row & 15;
        float4 w = *(const float4*)(Whh + (size_t)(g * 512 + ng * 16 + ul) * 512 + k4);
        float vv[4] = {w.x, w.y, w.z, w.w};
        __nv_bfloat16 h[4], l[4];
        #pragma unroll
        for (int j = 0; j < 4; j++) split_bf16(vv[j], h[j], l[j]);
        char* ph = sm2 + K2_WH + row * 1040 + k4 * 2;
        char* pl = sm2 + K2_WL + row * 1040 + k4 * 2;
        *(__nv_bfloat162*)ph       = __nv_bfloat162{h[0], h[1]};
        *(__nv_bfloat162*)(ph + 4) = __nv_bfloat162{h[2], h[3]};
        *(__nv_bfloat162*)pl       = __nv_bfloat162{l[0], l[1]};
        *(__nv_bfloat162*)(pl + 4) = __nv_bfloat162{l[2], l[3]};
    }

    int b_loc  = tid >> 2;
    int u0     = (tid & 3) * 4;
    int b_glob = bg * 64 + b_loc;
    int len_b  = lengths[b_glob];
    float bh_r[4], bh_z[4], bh_n[4];
    #pragma unroll
    for (int j = 0; j < 4; j++) {
        int u = ng * 16 + u0 + j;
        bh_r[j] = bhh[u]; bh_z[j] = bhh[512 + u]; bh_n[j] = bhh[1024 + u];
    }
    float hprev[4] = {0.f, 0.f, 0.f, 0.f};

    int m0  = (wid & 3) * 16;
    int n0w = (wid >> 2) * 24;
    uint32_t aoffA  = (uint32_t)((m0 + (lane & 15)) * 272 + ((lane >> 4) & 1) * 16);
    uint32_t aoffB4 = (uint32_t)((n0w + (lane & 7) + ((lane >> 4) & 1) * 8) * 1040 + ((lane >> 3) & 1) * 16);
    uint32_t aoffB2 = (uint32_t)((n0w + 16 + (lane & 7)) * 1040 + ((lane >> 3) & 1) * 16);

    float* gsm = (float*)(sm2 + K2_GATE);
    __syncthreads();

    for (int t = 0; t < 512; t++) {
        int ph = t & 1;
        const float* gp = g_G + (size_t)d * BT * H3 + ((size_t)b_glob * 512 + t) * H3 + ng * 16 + u0;
        float4 gir = __ldg((const float4*)gp);
        float4 giz = __ldg((const float4*)(gp + 512));
        float4 gin = __ldg((const float4*)(gp + 1024));

        size_t hsrc = ((size_t)(ph * 2 + d) * 128 + bg * 64) * 512;
        k2_stage(sb + K2_H,         hsrc, 0,   tid);
        k2_stage(sb + K2_H + 34816, hsrc, 128, tid);

        float acc[3][4];
        #pragma unroll
        for (int n = 0; n < 3; n++)
            #pragma unroll
            for (int r = 0; r < 4; r++) acc[n][r] = 0.f;

        for (int c = 0; c < 4; c++) {
            if (c < 3) asm volatile("cp.async.wait_group 1;" ::: "memory");
            else       asm volatile("cp.async.wait_group 0;" ::: "memory");
            __syncthreads();
            if (c + 2 < 4)
                k2_stage(sb + K2_H + ((c + 2) % 3) * 34816, hsrc, (c + 2) * 128, tid);
            uint32_t hb_hi = sb + K2_H + (c % 3) * 34816;
            uint32_t hb_lo = hb_hi + 17408;
            #pragma unroll
            for (int kt = 0; kt < 8; kt++) {
                uint32_t koffH = kt * 32;
                uint32_t koffW = (uint32_t)(c * 128 + kt * 16) * 2;
                uint32_t ah[4], al[4], bh4[4], b2h[2], bl4[4], b2l[2];
                ldsm4(ah, hb_hi + aoffA + koffH);
                ldsm4(al, hb_lo + aoffA + koffH);
                ldsm4(bh4, sb + K2_WH + aoffB4 + koffW);
                ldsm2(b2h, sb + K2_WH + aoffB2 + koffW);
                ldsm4(bl4, sb + K2_WL + aoffB4 + koffW);
                ldsm2(b2l, sb + K2_WL + aoffB2 + koffW);
                mma16816(acc[0], ah, bh4[0], bh4[1]);
                mma16816(acc[1], ah, bh4[2], bh4[3]);
                mma16816(acc[2], ah, b2h[0], b2h[1]);
                mma16816(acc[0], ah, bl4[0], bl4[1]);
                mma16816(acc[1], ah, bl4[2], bl4[3]);
                mma16816(acc[2], ah, b2l[0], b2l[1]);
                mma16816(acc[0], al, bh4[0], bh4[1]);
                mma16816(acc[1], al, bh4[2], bh4[3]);
                mma16816(acc[2], al, b2h[0], b2h[1]);
            }
        }

        int grow = m0 + (lane >> 2);
        #pragma unroll
        for (int j = 0; j < 3; j++) {
            int col = n0w + j * 8 + (lane & 3) * 2;
            gsm[grow * 52 + col]           = acc[j][0];
            gsm[grow * 52 + col + 1]       = acc[j][1];
            gsm[(grow + 8) * 52 + col]     = acc[j][2];
            gsm[(grow + 8) * 52 + col + 1] = acc[j][3];
        }
        __syncthreads();

        float gi_r[4], gi_z[4], gi_n[4];
        *(float4*)gi_r = gir; *(float4*)gi_z = giz; *(float4*)gi_n = gin;
        bool m = (t < len_b);
        size_t hwb = ((size_t)((ph ^ 1) * 2 + d) * 128 + b_glob) * 512 + ng * 16;
        int orow = (d == 0) ? t : (m ? (len_b - 1 - t) : t);
        size_t ob = ((size_t)b_glob * 512 + orow) * 1024 + d * 512 + ng * 16;

        float hm[4], ov[4];
        #pragma unroll
        for (int j = 0; j < 4; j++) {
            int u = u0 + j;
            float ar = gsm[b_loc * 52 + u];
            float az = gsm[b_loc * 52 + 16 + u];
            float an = gsm[b_loc * 52 + 32 + u];
            float rr = 1.f / (1.f + expf(-(gi_r[j] + ar + bh_r[j])));
            float zz = 1.f / (1.f + expf(-(gi_z[j] + az + bh_z[j])));
            float nn = tanhf(gi_n[j] + rr * (an + bh_n[j]));
            float hn = (1.f - zz) * nn + zz * hprev[j];
            hm[j] = m ? hn : hprev[j];
            hprev[j] = hm[j];
            ov[j] = m ? hn : 0.f;
        }
        __nv_bfloat16 hh[4], hl[4], oh[4], ol[4];
        #pragma unroll
        for (int j = 0; j < 4; j++) {
            split_bf16(hm[j], hh[j], hl[j]);
            split_bf16(ov[j], oh[j], ol[j]);
        }
        *(__nv_bfloat162*)(g_hbh + hwb + u0)     = __nv_bfloat162{hh[0], hh[1]};
        *(__nv_bfloat162*)(g_hbh + hwb + u0 + 2) = __nv_bfloat162{hh[2], hh[3]};
        *(__nv_bfloat162*)(g_hbl + hwb + u0)     = __nv_bfloat162{hl[0], hl[1]};
        *(__nv_bfloat162*)(g_hbl + hwb + u0 + 2) = __nv_bfloat162{hl[2], hl[3]};
        *(float4*)(g_out + ob + u0) = make_float4(ov[0], ov[1], ov[2], ov[3]);
        *(__nv_bfloat162*)(g_outh + ob + u0)     = __nv_bfloat162{oh[0], oh[1]};
        *(__nv_bfloat162*)(g_outh + ob + u0 + 2) = __nv_bfloat162{oh[2], oh[3]};
        *(__nv_bfloat162*)(g_outl + ob + u0)     = __nv_bfloat162{ol[0], ol[1]};
        *(__nv_bfloat162*)(g_outl + ob + u0 + 2) = __nv_bfloat162{ol[2], ol[3]};

        group_barrier(gid, (unsigned)(t + 1));
    }

    if (tid == 0) {
        unsigned old = atomicAdd(&g_done, 1u);
        if (old == NCTA - 1) {
            #pragma unroll
            for (int g = 0; g < 4; g++) { g_cnt4[g] = 0; g_gen4[g] = 0; }
            g_done = 0;
            __threadfence();
        }
    }
}

// ---------------------------------------------------------------- K3: tensor proj + fused ctx-dot (256x128)
__global__ void __launch_bounds__(512) k_gemm_proj_tc(
    const float* __restrict__ bp, const float* __restrict__ ctx)
{
    uint32_t sb = smem_u32(sm_tc);
    int tid = threadIdx.x, wid = tid >> 5, lane = tid & 31;
    int mb = blockIdx.y * 256, nb = blockIdx.x * 128;

    const __nv_bfloat16* Ah = g_outh + (size_t)mb * 1024;
    const __nv_bfloat16* Al = g_outl + (size_t)mb * 1024;
    const __nv_bfloat16* Bh = g_Wph + (size_t)nb * 1024;
    const __nv_bfloat16* Bl = g_Wpl + (size_t)nb * 1024;

    int wm = (wid & 3) * 64;
    int wn = (wid >> 2) * 32;

    float acc[4][4][4];
    #pragma unroll
    for (int f = 0; f < 4; f++)
        #pragma unroll
        for (int n = 0; n < 4; n++)
            #pragma unroll
            for (int r = 0; r < 4; r++) acc[f][n][r] = 0.f;

    issue_chunk2(sb,       Ah, Al, Bh, Bl, 0,  tid, 1024);
    issue_chunk2(sb + TB2, Ah, Al, Bh, Bl, 32, tid, 1024);

    int arow = (lane & 15);
    int ahk  = ((lane >> 4) & 1) * 16;
    int brow = (lane & 7) + ((lane >> 4) & 1) * 8;
    int bhk  = ((lane >> 3) & 1) * 16;

    for (int c = 0; c < 32; c++) {
        if (c < 31) asm volatile("cp.async.wait_group 1;" ::: "memory");
        else        asm volatile("cp.async.wait_group 0;" ::: "memory");
        __syncthreads();
        uint32_t base = sb + (c & 1) * TB2;
        uint32_t aA = base +         (wm + arow) * 80 + ahk;
        uint32_t aB = base + 40960 + (wn + brow) * 80 + bhk;

        #pragma unroll
        for (int s = 0; s < 2; s++) {
            uint32_t ah[4][4], al[4][4], bh[2][4], bl[2][4];
            #pragma unroll
            for (int f = 0; f < 4; f++) {
                ldsm4(ah[f], aA + f * 16 * 80 + s * 32);
                ldsm4(al[f], aA + 20480 + f * 16 * 80 + s * 32);
            }
            #pragma unroll
            for (int g = 0; g < 2; g++) {
                ldsm4(bh[g], aB + g * 16 * 80 + s * 32);
                ldsm4(bl[g], aB + 10240 + g * 16 * 80 + s * 32);
            }
            #pragma unroll
            for (int f = 0; f < 4; f++)
                #pragma unroll
                for (int n = 0; n < 4; n++) {
                    mma16816(acc[f][n], ah[f], bh[n >> 1][(n & 1) * 2], bh[n >> 1][(n & 1) * 2 + 1]);
                    mma16816(acc[f][n], ah[f], bl[n >> 1][(n & 1) * 2], bl[n >> 1][(n & 1) * 2 + 1]);
                    mma16816(acc[f][n], al[f], bh[n >> 1][(n & 1) * 2], bh[n >> 1][(n & 1) * 2 + 1]);
                }
        }
        __syncthreads();
        if (c + 2 < 32)
            issue_chunk2(sb + (c & 1) * TB2, Ah, Al, Bh, Bl, (c + 2) * 32, tid, 1024);
    }

    #pragma unroll
    for (int f = 0; f < 4; f++) {
        int r0 = mb + wm + f * 16 + (lane >> 2);
        float p0 = 0.f, p1 = 0.f;
        #pragma unroll
        for (int n = 0; n < 4; n++) {
            int col = nb + wn + n * 8 + (lane & 3) * 2;
            float c0 = __ldg(ctx + col), c1 = __ldg(ctx + col + 1);
            float b0 = __ldg(bp + col),  b1 = __ldg(bp + col + 1);
            p0 += tanhf(acc[f][n][0] + b0) * c0 + tanhf(acc[f][n][1] + b1) * c1;
            p1 += tanhf(acc[f][n][2] + b0) * c0 + tanhf(acc[f][n][3] + b1) * c1;
        }
        p0 += __shfl_xor_sync(0xffffffffu, p0, 1);
        p0 += __shfl_xor_sync(0xffffffffu, p0, 2);
        p1 += __shfl_xor_sync(0xffffffffu, p1, 1);
        p1 += __shfl_xor_sync(0xffffffffu, p1, 2);
        if ((lane & 3) == 0) {
            atomicAdd(&g_scores[r0], p0);
            atomicAdd(&g_scores[r0 + 8], p1);
        }
    }
}

// ---------------------------------------------------------------- K4: softmax + pooling + SELU + logits
__global__ void __launch_bounds__(512) k_final(
    const int* __restrict__ lengths,
    const float* __restrict__ Wl, const float* __restrict__ bl,
    float* __restrict__ out, int out_size)
{
    __shared__ float sh[512];
    __shared__ float attn[512];
    __shared__ float lg[2];
    int b = blockIdx.x, tid = threadIdx.x;
    int len = lengths[b];
    float s = (tid < len) ? g_scores[b * 512 + tid] : -1e30f;
    sh[tid] = s; __syncthreads();
    for (int o = 256; o > 0; o >>= 1) { if (tid < o) sh[tid] = fmaxf(sh[tid], sh[tid + o]); __syncthreads(); }
    float mx = sh[0]; __syncthreads();
    float e = (tid < len) ? expf(s - mx) : 0.f;
    sh[tid] = e; __syncthreads();
    for (int o = 256; o > 0; o >>= 1) { if (tid < o) sh[tid] += sh[tid + o]; __syncthreads(); }
    float a = e / sh[0];
    attn[tid] = a;
    int attn_ofs = (out_size >= 65792) ? 256 : 0;
    if (out_size != 256) out[attn_ofs + b * 512 + tid] = a;
    if (tid == 0) { lg[0] = 0.f; lg[1] = 0.f; }
    __syncthreads();

    const float* ob = g_out + (long)b * 512 * 1024;
    float s0 = 0.f, s1 = 0.f;
    for (int t = 0; t < 512; t++) {
        float at = attn[t];
        s0 = fmaf(at, ob[(long)t * 1024 + tid],       s0);
        s1 = fmaf(at, ob[(long)t * 1024 + 512 + tid], s1);
    }
    const float SC = 1.0507009873554805f, AL = 1.6732632423543772f;
    s0 = (s0 > 0.f) ? SC * s0 : SC * AL * (expf(s0) - 1.f);
    s1 = (s1 > 0.f) ? SC * s1 : SC * AL * (expf(s1) - 1.f);
    float p0 = s0 * Wl[tid]        + s1 * Wl[512 + tid];
    float p1 = s0 * Wl[1024 + tid] + s1 * Wl[1536 + tid];
    #pragma unroll
    for (int o = 16; o > 0; o >>= 1) {
        p0 += __shfl_xor_sync(0xffffffffu, p0, o);
        p1 += __shfl_xor_sync(0xffffffffu, p1, o);
    }
    if ((tid & 31) == 0) { atomicAdd(&lg[0], p0); atomicAdd(&lg[1], p1); }
    __syncthreads();
    if (tid < 2 && out_size != 65536) out[b * 2 + tid] = lg[tid] + bl[tid];
}

// ---------------------------------------------------------------- launch
extern "C" void kernel_launch(void* const* d_in, const int* in_sizes, int n_in,
                              void* d_out, int out_size)
{
    const int*   tokens  = (const int*)d_in[0];
    const int*   lengths = (const int*)d_in[1];
    const float* emb     = (const float*)d_in[2];
    const float* Wih_f   = (const float*)d_in[3];
    const float* Whh_f   = (const float*)d_in[4];
    const float* bih_f   = (const float*)d_in[5];
    const float* bhh_f   = (const float*)d_in[6];
    const float* Wih_b   = (const float*)d_in[7];
    const float* Whh_b   = (const float*)d_in[8];
    const float* bih_b   = (const float*)d_in[9];
    const float* bhh_b   = (const float*)d_in[10];
    const float* Wp      = (const float*)d_in[11];
    const float* bp      = (const float*)d_in[12];
    const float* ctx     = (const float*)d_in[13];
    const float* Wl      = (const float*)d_in[14];
    const float* bl      = (const float*)d_in[15];
    float* out = (float*)d_out;

    k_init<<<BT / 256, 256>>>(tokens, lengths);
    k_convW<<<1536, 256>>>(Wih_f, Wih_b);
    k_convX<<<65536, 256>>>(emb);
    k_convP<<<512, 256>>>(Wp);

    cudaFuncSetAttribute(k_gemm_ih_tc, cudaFuncAttributeMaxDynamicSharedMemorySize, SMEM_TC2);
    dim3 g1(12, 256, 2);
    k_gemm_ih_tc<<<g1, 512, SMEM_TC2>>>(bih_f, bih_b);

    cudaFuncSetAttribute(k_gru_tc, cudaFuncAttributeMaxDynamicSharedMemorySize, K2_SMEM);
    k_gru_tc<<<NCTA, 256, K2_SMEM>>>(Whh_f, bhh_f, Whh_b, bhh_b, lengths);

    cudaFuncSetAttribute(k_gemm_proj_tc, cudaFuncAttributeMaxDynamicSharedMemorySize, SMEM_TC2);
    dim3 g3(4, 256);
    k_gemm_proj_tc<<<g3, 512, SMEM_TC2>>>(bp, ctx);

    k_final<<<Bsz, 512>>>(lengths, Wl, bl, out, out_size);
}

// round 10
// speedup vs baseline: 1.2761x; 1.2394x over previous
#include <cuda_runtime.h>
#include <cuda_fp16.h>
#include <math.h>
#include <stdint.h>

#define Bsz 128
#define Tt  512
#define H3  1536
#define BT  65536
#define NCTA 128

__device__ float g_G[201326592];    // [dir][b*T+t][1536]
__device__ float g_out[67108864];   // [b][t][1024] fp32 (for K4)
__device__ __half g_outh[67108864]; // fp16 split of out (A side of K3)
__device__ __half g_outl[67108864];
__device__ float g_scores[65536];
__device__ int   g_tok2[131072];
__device__ unsigned g_cnt4[4], g_gen4[4], g_done;

// fp16 operands: dynamic side split hi/lo, weight side hi only
__device__ __half g_Xh[67108864];   // [2*BT][512]
__device__ __half g_Xl[67108864];
__device__ __half g_Wh[1572864];    // [2][1536][512]  Wih hi
__device__ __half g_Wph[524288];    // [512][1024]     Wp  hi
__device__ __half g_hbh[262144];    // [ph][d][128][512]
__device__ __half g_hbl[262144];

// ---------------------------------------------------------------- helpers
__device__ __forceinline__ uint32_t smem_u32(const void* p)
{
    uint32_t a;
    asm("{ .reg .u64 t; cvta.to.shared.u64 t, %1; cvt.u32.u64 %0, t; }" : "=r"(a) : "l"(p));
    return a;
}
__device__ __forceinline__ void cp16(uint32_t dst, const void* src)
{
    asm volatile("cp.async.cg.shared.global [%0], [%1], 16;" :: "r"(dst), "l"(src) : "memory");
}
__device__ __forceinline__ void cp_commit()
{
    asm volatile("cp.async.commit_group;" ::: "memory");
}
__device__ __forceinline__ void ldsm4(uint32_t* r, uint32_t addr)
{
    asm volatile("ldmatrix.sync.aligned.m8n8.x4.shared.b16 {%0,%1,%2,%3}, [%4];"
                 : "=r"(r[0]), "=r"(r[1]), "=r"(r[2]), "=r"(r[3]) : "r"(addr));
}
__device__ __forceinline__ void ldsm2(uint32_t* r, uint32_t addr)
{
    asm volatile("ldmatrix.sync.aligned.m8n8.x2.shared.b16 {%0,%1}, [%2];"
                 : "=r"(r[0]), "=r"(r[1]) : "r"(addr));
}
__device__ __forceinline__ void mma16816(float* c, const uint32_t* a, uint32_t b0, uint32_t b1)
{
    asm volatile("mma.sync.aligned.m16n8k16.row.col.f32.f16.f16.f32 "
                 "{%0,%1,%2,%3}, {%4,%5,%6,%7}, {%8,%9}, {%0,%1,%2,%3};"
                 : "+f"(c[0]), "+f"(c[1]), "+f"(c[2]), "+f"(c[3])
                 : "r"(a[0]), "r"(a[1]), "r"(a[2]), "r"(a[3]), "r"(b0), "r"(b1));
}
__device__ __forceinline__ void split_fp16(float v, __half& h, __half& l)
{
    h = __float2half_rn(v);
    l = __float2half_rn(v - __half2float(h));
}

// ---------------------------------------------------------------- K0
__global__ void k_init(const int* __restrict__ tokens, const int* __restrict__ lengths)
{
    int i = blockIdx.x * blockDim.x + threadIdx.x;
    if (i >= BT) return;
    int b = i >> 9, t = i & 511;
    g_tok2[i] = tokens[i];
    int rt = lengths[b] - 1 - t;
    if (rt < 0) rt = 0;
    g_tok2[BT + i] = tokens[(b << 9) + rt];
    g_scores[i] = 0.f;
    ((uint2*)g_hbh)[i] = make_uint2(0u, 0u);
    ((uint2*)g_hbl)[i] = make_uint2(0u, 0u);
}

// ---------------------------------------------------------------- conv kernels
__global__ void k_convX(const float* __restrict__ emb)
{
    size_t idx = (size_t)blockIdx.x * 256 + threadIdx.x;
    size_t e = idx * 4;
    size_t row = e >> 9;
    int k = (int)(e & 511);
    int tok = g_tok2[row];
    float4 v = *(const float4*)(emb + (size_t)tok * 512 + k);
    float vv[4] = {v.x, v.y, v.z, v.w};
    __half h[4], l[4];
    #pragma unroll
    for (int j = 0; j < 4; j++) split_fp16(vv[j], h[j], l[j]);
    __half2* ph = (__half2*)(g_Xh + row * 512 + k);
    __half2* pl = (__half2*)(g_Xl + row * 512 + k);
    ph[0] = __half2{h[0], h[1]}; ph[1] = __half2{h[2], h[3]};
    pl[0] = __half2{l[0], l[1]}; pl[1] = __half2{l[2], l[3]};
}

__global__ void k_convW(const float* __restrict__ Wf, const float* __restrict__ Wb)
{
    size_t idx = (size_t)blockIdx.x * 256 + threadIdx.x;
    size_t e = idx * 4;
    size_t row = e >> 9;
    int k = (int)(e & 511);
    int d = (int)(row >= 1536);
    size_t n = row - (size_t)d * 1536;
    const float* W = d ? Wb : Wf;
    float4 v = *(const float4*)(W + n * 512 + k);
    __half2* ph = (__half2*)(g_Wh + row * 512 + k);
    ph[0] = __half2{__float2half_rn(v.x), __float2half_rn(v.y)};
    ph[1] = __half2{__float2half_rn(v.z), __float2half_rn(v.w)};
}

__global__ void k_convP(const float* __restrict__ Wp)
{
    size_t idx = (size_t)blockIdx.x * 256 + threadIdx.x;
    size_t e = idx * 4;
    float4 v = *(const float4*)(Wp + e);
    __half2* ph = (__half2*)(g_Wph + e);
    ph[0] = __half2{__float2half_rn(v.x), __float2half_rn(v.y)};
    ph[1] = __half2{__float2half_rn(v.z), __float2half_rn(v.w)};
}

// ---------------------------------------------------------------- big-tile GEMM staging
// CTA tile 256(M) x 128(N), 512 threads. Per buffer 51200 B:
//   Ah@0 (256x80), Al@20480, Bh@40960 (128x80)
// Chunk = 32 fp16 = 64 B/row -> q in 0..3 only (16 B pad unwritten).
#define TB2 51200
#define SMEM_TC2 (2 * TB2)
extern __shared__ char sm_tc[];

__device__ __forceinline__ void issue_chunk2(
    uint32_t sbase, const __half* Ah, const __half* Al,
    const __half* Bh, int k0, int tid, int ldk)
{
    #pragma unroll
    for (int j = 0; j < 5; j++) {
        int L = tid + j * 512;          // 0..2559
        if (L < 2048) {                 // A: 2 mats x 256 rows x 4 q
            int mat = (L >= 1024);
            int r = L - mat * 1024;
            int row = r >> 2, q = r & 3;
            const __half* src = mat ? Al : Ah;
            cp16(sbase + mat * 20480 + row * 80 + q * 16,
                 (const char*)(src + (size_t)row * ldk + k0) + q * 16);
        } else {                        // B: 128 rows x 4 q
            int r = L - 2048;
            int row = r >> 2, q = r & 3;
            cp16(sbase + 40960 + row * 80 + q * 16,
                 (const char*)(Bh + (size_t)row * ldk + k0) + q * 16);
        }
    }
    cp_commit();
}

// ---------------------------------------------------------------- K1: input-gate GEMM (fp16 2-pass, 256x128)
__global__ void __launch_bounds__(512) k_gemm_ih_tc(
    const float* __restrict__ bf, const float* __restrict__ bb)
{
    uint32_t sb = smem_u32(sm_tc);
    int tid = threadIdx.x, wid = tid >> 5, lane = tid & 31;
    int d = blockIdx.z, mb = blockIdx.y * 256, nb = blockIdx.x * 128;
    const float* bias = (d ? bb : bf) + nb;

    const __half* Xh = g_Xh + (size_t)(d * BT + mb) * 512;
    const __half* Xl = g_Xl + (size_t)(d * BT + mb) * 512;
    const __half* Wh = g_Wh + (size_t)(d * 1536 + nb) * 512;

    int wm = (wid & 3) * 64;
    int wn = (wid >> 2) * 32;

    float acc[4][4][4];
    #pragma unroll
    for (int f = 0; f < 4; f++)
        #pragma unroll
        for (int n = 0; n < 4; n++)
            #pragma unroll
            for (int r = 0; r < 4; r++) acc[f][n][r] = 0.f;

    issue_chunk2(sb,       Xh, Xl, Wh, 0,  tid, 512);
    issue_chunk2(sb + TB2, Xh, Xl, Wh, 32, tid, 512);

    int arow = (lane & 15);
    int ahk  = ((lane >> 4) & 1) * 16;
    int brow = (lane & 7) + ((lane >> 4) & 1) * 8;
    int bhk  = ((lane >> 3) & 1) * 16;

    for (int c = 0; c < 16; c++) {
        if (c < 15) asm volatile("cp.async.wait_group 1;" ::: "memory");
        else        asm volatile("cp.async.wait_group 0;" ::: "memory");
        __syncthreads();
        uint32_t base = sb + (c & 1) * TB2;
        uint32_t aA = base +         (wm + arow) * 80 + ahk;
        uint32_t aB = base + 40960 + (wn + brow) * 80 + bhk;

        #pragma unroll
        for (int s = 0; s < 2; s++) {
            uint32_t ah[4][4], al[4][4], bh[2][4];
            #pragma unroll
            for (int f = 0; f < 4; f++) {
                ldsm4(ah[f], aA + f * 16 * 80 + s * 32);
                ldsm4(al[f], aA + 20480 + f * 16 * 80 + s * 32);
            }
            #pragma unroll
            for (int g = 0; g < 2; g++)
                ldsm4(bh[g], aB + g * 16 * 80 + s * 32);
            #pragma unroll
            for (int f = 0; f < 4; f++)
                #pragma unroll
                for (int n = 0; n < 4; n++) {
                    mma16816(acc[f][n], ah[f], bh[n >> 1][(n & 1) * 2], bh[n >> 1][(n & 1) * 2 + 1]);
                    mma16816(acc[f][n], al[f], bh[n >> 1][(n & 1) * 2], bh[n >> 1][(n & 1) * 2 + 1]);
                }
        }
        __syncthreads();
        if (c + 2 < 16)
            issue_chunk2(sb + (c & 1) * TB2, Xh, Xl, Wh, (c + 2) * 32, tid, 512);
    }

    #pragma unroll
    for (int f = 0; f < 4; f++) {
        int row = mb + wm + f * 16 + (lane >> 2);
        float* gp0 = g_G + ((size_t)d * BT + row) * H3 + nb;
        float* gp1 = gp0 + 8 * H3;
        #pragma unroll
        for (int n = 0; n < 4; n++) {
            int col = wn + n * 8 + (lane & 3) * 2;
            float b0 = __ldg(bias + col), b1 = __ldg(bias + col + 1);
            *(float2*)(gp0 + col) = make_float2(acc[f][n][0] + b0, acc[f][n][1] + b1);
            *(float2*)(gp1 + col) = make_float2(acc[f][n][2] + b0, acc[f][n][3] + b1);
        }
    }
}

// ---------------------------------------------------------------- group barrier
__device__ __forceinline__ void group_barrier(int gid, unsigned target)
{
    __syncthreads();
    if (threadIdx.x == 0) {
        __threadfence();
        unsigned a = atomicAdd(&g_cnt4[gid], 1u) + 1u;
        if (a == target * 32u) {
            atomicAdd(&g_gen4[gid], 1u);
        } else {
            while (*(volatile unsigned*)&g_gen4[gid] < target) { }
        }
        __threadfence();
    }
    __syncthreads();
}

// ---------------------------------------------------------------- K2: fp16 2-pass bi-GRU recurrence
// smem: Wh 49920 | H 3 bufs x 34816 | gate 64x52 fp32
#define K2_WH   0
#define K2_H    49920
#define K2_GATE 154368
#define K2_SMEM 167680
extern __shared__ char sm2[];

__device__ __forceinline__ void k2_stage(uint32_t dsth, size_t hsrc, int kc, int tid)
{
    #pragma unroll
    for (int j = 0; j < 4; j++) {
        int L = tid + j * 256;
        int row = L >> 4, q = L & 15;
        cp16(dsth + row * 272 + q * 16,         (const char*)(g_hbh + hsrc + (size_t)row * 512 + kc) + q * 16);
        cp16(dsth + 17408 + row * 272 + q * 16, (const char*)(g_hbl + hsrc + (size_t)row * 512 + kc) + q * 16);
    }
    cp_commit();
}

__global__ void __launch_bounds__(256) k_gru_tc(
    const float* __restrict__ Whh_f, const float* __restrict__ bhh_f,
    const float* __restrict__ Whh_b, const float* __restrict__ bhh_b,
    const int*   __restrict__ lengths)
{
    uint32_t sb = smem_u32(sm2);
    int tid = threadIdx.x, wid = tid >> 5, lane = tid & 31;
    int cid = blockIdx.x;
    int d = cid >> 6, bg = (cid >> 5) & 1, ng = cid & 31;
    int gid = d * 2 + bg;
    const float* Whh = d ? Whh_b : Whh_f;
    const float* bhh = d ? bhh_b : bhh_f;

    // Whh slice -> smem fp16 hi (rows: 0-15 r, 16-31 z, 32-47 n for units ng*16..+15)
    for (int i = tid; i < 48 * 128; i += 256) {
        int row = i >> 7, k4 = (i & 127) << 2;
        int g = row >> 4, ul = row & 15;
        float4 w = *(const float4*)(Whh + (size_t)(g * 512 + ng * 16 + ul) * 512 + k4);
        char* ph = sm2 + K2_WH + row * 1040 + k4 * 2;
        *(__half2*)ph       = __half2{__float2half_rn(w.x), __float2half_rn(w.y)};
        *(__half2*)(ph + 4) = __half2{__float2half_rn(w.z), __float2half_rn(w.w)};
    }

    int b_loc  = tid >> 2;
    int u0     = (tid & 3) * 4;
    int b_glob = bg * 64 + b_loc;
    int len_b  = lengths[b_glob];
    float bh_r[4], bh_z[4], bh_n[4];
    #pragma unroll
    for (int j = 0; j < 4; j++) {
        int u = ng * 16 + u0 + j;
        bh_r[j] = bhh[u]; bh_z[j] = bhh[512 + u]; bh_n[j] = bhh[1024 + u];
    }
    float hprev[4] = {0.f, 0.f, 0.f, 0.f};

    int m0  = (wid & 3) * 16;
    int n0w = (wid >> 2) * 24;
    uint32_t aoffA  = (uint32_t)((m0 + (lane & 15)) * 272 + ((lane >> 4) & 1) * 16);
    uint32_t aoffB4 = (uint32_t)((n0w + (lane & 7) + ((lane >> 4) & 1) * 8) * 1040 + ((lane >> 3) & 1) * 16);
    uint32_t aoffB2 = (uint32_t)((n0w + 16 + (lane & 7)) * 1040 + ((lane >> 3) & 1) * 16);

    float* gsm = (float*)(sm2 + K2_GATE);
    __syncthreads();

    for (int t = 0; t < 512; t++) {
        int ph = t & 1;
        const float* gp = g_G + (size_t)d * BT * H3 + ((size_t)b_glob * 512 + t) * H3 + ng * 16 + u0;
        float4 gir = __ldg((const float4*)gp);
        float4 giz = __ldg((const float4*)(gp + 512));
        float4 gin = __ldg((const float4*)(gp + 1024));

        size_t hsrc = ((size_t)(ph * 2 + d) * 128 + bg * 64) * 512;
        k2_stage(sb + K2_H,         hsrc, 0,   tid);
        k2_stage(sb + K2_H + 34816, hsrc, 128, tid);

        float acc[3][4];
        #pragma unroll
        for (int n = 0; n < 3; n++)
            #pragma unroll
            for (int r = 0; r < 4; r++) acc[n][r] = 0.f;

        for (int c = 0; c < 4; c++) {
            if (c < 3) asm volatile("cp.async.wait_group 1;" ::: "memory");
            else       asm volatile("cp.async.wait_group 0;" ::: "memory");
            __syncthreads();
            if (c + 2 < 4)
                k2_stage(sb + K2_H + ((c + 2) % 3) * 34816, hsrc, (c + 2) * 128, tid);
            uint32_t hb_hi = sb + K2_H + (c % 3) * 34816;
            uint32_t hb_lo = hb_hi + 17408;
            #pragma unroll
            for (int kt = 0; kt < 8; kt++) {
                uint32_t koffH = kt * 32;
                uint32_t koffW = (uint32_t)(c * 128 + kt * 16) * 2;
                uint32_t ah[4], al[4], bh4[4], b2h[2];
                ldsm4(ah, hb_hi + aoffA + koffH);
                ldsm4(al, hb_lo + aoffA + koffH);
                ldsm4(bh4, sb + K2_WH + aoffB4 + koffW);
                ldsm2(b2h, sb + K2_WH + aoffB2 + koffW);
                mma16816(acc[0], ah, bh4[0], bh4[1]);
                mma16816(acc[1], ah, bh4[2], bh4[3]);
                mma16816(acc[2], ah, b2h[0], b2h[1]);
                mma16816(acc[0], al, bh4[0], bh4[1]);
                mma16816(acc[1], al, bh4[2], bh4[3]);
                mma16816(acc[2], al, b2h[0], b2h[1]);
            }
        }

        int grow = m0 + (lane >> 2);
        #pragma unroll
        for (int j = 0; j < 3; j++) {
            int col = n0w + j * 8 + (lane & 3) * 2;
            gsm[grow * 52 + col]           = acc[j][0];
            gsm[grow * 52 + col + 1]       = acc[j][1];
            gsm[(grow + 8) * 52 + col]     = acc[j][2];
            gsm[(grow + 8) * 52 + col + 1] = acc[j][3];
        }
        __syncthreads();

        float gi_r[4], gi_z[4], gi_n[4];
        *(float4*)gi_r = gir; *(float4*)gi_z = giz; *(float4*)gi_n = gin;
        bool m = (t < len_b);
        size_t hwb = ((size_t)((ph ^ 1) * 2 + d) * 128 + b_glob) * 512 + ng * 16;
        int orow = (d == 0) ? t : (m ? (len_b - 1 - t) : t);
        size_t ob = ((size_t)b_glob * 512 + orow) * 1024 + d * 512 + ng * 16;

        float hm[4], ov[4];
        #pragma unroll
        for (int j = 0; j < 4; j++) {
            int u = u0 + j;
            float ar = gsm[b_loc * 52 + u];
            float az = gsm[b_loc * 52 + 16 + u];
            float an = gsm[b_loc * 52 + 32 + u];
            float rr = 1.f / (1.f + expf(-(gi_r[j] + ar + bh_r[j])));
            float zz = 1.f / (1.f + expf(-(gi_z[j] + az + bh_z[j])));
            float nn = tanhf(gi_n[j] + rr * (an + bh_n[j]));
            float hn = (1.f - zz) * nn + zz * hprev[j];
            hm[j] = m ? hn : hprev[j];
            hprev[j] = hm[j];
            ov[j] = m ? hn : 0.f;
        }
        __half hh[4], hl[4], oh[4], ol[4];
        #pragma unroll
        for (int j = 0; j < 4; j++) {
            split_fp16(hm[j], hh[j], hl[j]);
            split_fp16(ov[j], oh[j], ol[j]);
        }
        *(__half2*)(g_hbh + hwb + u0)     = __half2{hh[0], hh[1]};
        *(__half2*)(g_hbh + hwb + u0 + 2) = __half2{hh[2], hh[3]};
        *(__half2*)(g_hbl + hwb + u0)     = __half2{hl[0], hl[1]};
        *(__half2*)(g_hbl + hwb + u0 + 2) = __half2{hl[2], hl[3]};
        *(float4*)(g_out + ob + u0) = make_float4(ov[0], ov[1], ov[2], ov[3]);
        *(__half2*)(g_outh + ob + u0)     = __half2{oh[0], oh[1]};
        *(__half2*)(g_outh + ob + u0 + 2) = __half2{oh[2], oh[3]};
        *(__half2*)(g_outl + ob + u0)     = __half2{ol[0], ol[1]};
        *(__half2*)(g_outl + ob + u0 + 2) = __half2{ol[2], ol[3]};

        group_barrier(gid, (unsigned)(t + 1));
    }

    if (tid == 0) {
        unsigned old = atomicAdd(&g_done, 1u);
        if (old == NCTA - 1) {
            #pragma unroll
            for (int g = 0; g < 4; g++) { g_cnt4[g] = 0; g_gen4[g] = 0; }
            g_done = 0;
            __threadfence();
        }
    }
}

// ---------------------------------------------------------------- K3: fp16 2-pass proj + fused ctx-dot (256x128)
__global__ void __launch_bounds__(512) k_gemm_proj_tc(
    const float* __restrict__ bp, const float* __restrict__ ctx)
{
    uint32_t sb = smem_u32(sm_tc);
    int tid = threadIdx.x, wid = tid >> 5, lane = tid & 31;
    int mb = blockIdx.y * 256, nb = blockIdx.x * 128;

    const __half* Ah = g_outh + (size_t)mb * 1024;
    const __half* Al = g_outl + (size_t)mb * 1024;
    const __half* Bh = g_Wph + (size_t)nb * 1024;

    int wm = (wid & 3) * 64;
    int wn = (wid >> 2) * 32;

    float acc[4][4][4];
    #pragma unroll
    for (int f = 0; f < 4; f++)
        #pragma unroll
        for (int n = 0; n < 4; n++)
            #pragma unroll
            for (int r = 0; r < 4; r++) acc[f][n][r] = 0.f;

    issue_chunk2(sb,       Ah, Al, Bh, 0,  tid, 1024);
    issue_chunk2(sb + TB2, Ah, Al, Bh, 32, tid, 1024);

    int arow = (lane & 15);
    int ahk  = ((lane >> 4) & 1) * 16;
    int brow = (lane & 7) + ((lane >> 4) & 1) * 8;
    int bhk  = ((lane >> 3) & 1) * 16;

    for (int c = 0; c < 32; c++) {
        if (c < 31) asm volatile("cp.async.wait_group 1;" ::: "memory");
        else        asm volatile("cp.async.wait_group 0;" ::: "memory");
        __syncthreads();
        uint32_t base = sb + (c & 1) * TB2;
        uint32_t aA = base +         (wm + arow) * 80 + ahk;
        uint32_t aB = base + 40960 + (wn + brow) * 80 + bhk;

        #pragma unroll
        for (int s = 0; s < 2; s++) {
            uint32_t ah[4][4], al[4][4], bh[2][4];
            #pragma unroll
            for (int f = 0; f < 4; f++) {
                ldsm4(ah[f], aA + f * 16 * 80 + s * 32);
                ldsm4(al[f], aA + 20480 + f * 16 * 80 + s * 32);
            }
            #pragma unroll
            for (int g = 0; g < 2; g++)
                ldsm4(bh[g], aB + g * 16 * 80 + s * 32);
            #pragma unroll
            for (int f = 0; f < 4; f++)
                #pragma unroll
                for (int n = 0; n < 4; n++) {
                    mma16816(acc[f][n], ah[f], bh[n >> 1][(n & 1) * 2], bh[n >> 1][(n & 1) * 2 + 1]);
                    mma16816(acc[f][n], al[f], bh[n >> 1][(n & 1) * 2], bh[n >> 1][(n & 1) * 2 + 1]);
                }
        }
        __syncthreads();
        if (c + 2 < 32)
            issue_chunk2(sb + (c & 1) * TB2, Ah, Al, Bh, (c + 2) * 32, tid, 1024);
    }

    #pragma unroll
    for (int f = 0; f < 4; f++) {
        int r0 = mb + wm + f * 16 + (lane >> 2);
        float p0 = 0.f, p1 = 0.f;
        #pragma unroll
        for (int n = 0; n < 4; n++) {
            int col = nb + wn + n * 8 + (lane & 3) * 2;
            float c0 = __ldg(ctx + col), c1 = __ldg(ctx + col + 1);
            float b0 = __ldg(bp + col),  b1 = __ldg(bp + col + 1);
            p0 += tanhf(acc[f][n][0] + b0) * c0 + tanhf(acc[f][n][1] + b1) * c1;
            p1 += tanhf(acc[f][n][2] + b0) * c0 + tanhf(acc[f][n][3] + b1) * c1;
        }
        p0 += __shfl_xor_sync(0xffffffffu, p0, 1);
        p0 += __shfl_xor_sync(0xffffffffu, p0, 2);
        p1 += __shfl_xor_sync(0xffffffffu, p1, 1);
        p1 += __shfl_xor_sync(0xffffffffu, p1, 2);
        if ((lane & 3) == 0) {
            atomicAdd(&g_scores[r0], p0);
            atomicAdd(&g_scores[r0 + 8], p1);
        }
    }
}

// ---------------------------------------------------------------- K4: softmax + pooling + SELU + logits
__global__ void __launch_bounds__(512) k_final(
    const int* __restrict__ lengths,
    const float* __restrict__ Wl, const float* __restrict__ bl,
    float* __restrict__ out, int out_size)
{
    __shared__ float sh[512];
    __shared__ float attn[512];
    __shared__ float lg[2];
    int b = blockIdx.x, tid = threadIdx.x;
    int len = lengths[b];
    float s = (tid < len) ? g_scores[b * 512 + tid] : -1e30f;
    sh[tid] = s; __syncthreads();
    for (int o = 256; o > 0; o >>= 1) { if (tid < o) sh[tid] = fmaxf(sh[tid], sh[tid + o]); __syncthreads(); }
    float mx = sh[0]; __syncthreads();
    float e = (tid < len) ? expf(s - mx) : 0.f;
    sh[tid] = e; __syncthreads();
    for (int o = 256; o > 0; o >>= 1) { if (tid < o) sh[tid] += sh[tid + o]; __syncthreads(); }
    float a = e / sh[0];
    attn[tid] = a;
    int attn_ofs = (out_size >= 65792) ? 256 : 0;
    if (out_size != 256) out[attn_ofs + b * 512 + tid] = a;
    if (tid == 0) { lg[0] = 0.f; lg[1] = 0.f; }
    __syncthreads();

    const float* ob = g_out + (long)b * 512 * 1024;
    float s0 = 0.f, s1 = 0.f;
    for (int t = 0; t < 512; t++) {
        float at = attn[t];
        s0 = fmaf(at, ob[(long)t * 1024 + tid],       s0);
        s1 = fmaf(at, ob[(long)t * 1024 + 512 + tid], s1);
    }
    const float SC = 1.0507009873554805f, AL = 1.6732632423543772f;
    s0 = (s0 > 0.f) ? SC * s0 : SC * AL * (expf(s0) - 1.f);
    s1 = (s1 > 0.f) ? SC * s1 : SC * AL * (expf(s1) - 1.f);
    float p0 = s0 * Wl[tid]        + s1 * Wl[512 + tid];
    float p1 = s0 * Wl[1024 + tid] + s1 * Wl[1536 + tid];
    #pragma unroll
    for (int o = 16; o > 0; o >>= 1) {
        p0 += __shfl_xor_sync(0xffffffffu, p0, o);
        p1 += __shfl_xor_sync(0xffffffffu, p1, o);
    }
    if ((tid & 31) == 0) { atomicAdd(&lg[0], p0); atomicAdd(&lg[1], p1); }
    __syncthreads();
    if (tid < 2 && out_size != 65536) out[b * 2 + tid] = lg[tid] + bl[tid];
}

// ---------------------------------------------------------------- launch
extern "C" void kernel_launch(void* const* d_in, const int* in_sizes, int n_in,
                              void* d_out, int out_size)
{
    const int*   tokens  = (const int*)d_in[0];
    const int*   lengths = (const int*)d_in[1];
    const float* emb     = (const float*)d_in[2];
    const float* Wih_f   = (const float*)d_in[3];
    const float* Whh_f   = (const float*)d_in[4];
    const float* bih_f   = (const float*)d_in[5];
    const float* bhh_f   = (const float*)d_in[6];
    const float* Wih_b   = (const float*)d_in[7];
    const float* Whh_b   = (const float*)d_in[8];
    const float* bih_b   = (const float*)d_in[9];
    const float* bhh_b   = (const float*)d_in[10];
    const float* Wp      = (const float*)d_in[11];
    const float* bp      = (const float*)d_in[12];
    const float* ctx     = (const float*)d_in[13];
    const float* Wl      = (const float*)d_in[14];
    const float* bl      = (const float*)d_in[15];
    float* out = (float*)d_out;

    k_init<<<BT / 256, 256>>>(tokens, lengths);
    k_convW<<<1536, 256>>>(Wih_f, Wih_b);
    k_convX<<<65536, 256>>>(emb);
    k_convP<<<512, 256>>>(Wp);

    cudaFuncSetAttribute(k_gemm_ih_tc, cudaFuncAttributeMaxDynamicSharedMemorySize, SMEM_TC2);
    dim3 g1(12, 256, 2);
    k_gemm_ih_tc<<<g1, 512, SMEM_TC2>>>(bih_f, bih_b);

    cudaFuncSetAttribute(k_gru_tc, cudaFuncAttributeMaxDynamicSharedMemorySize, K2_SMEM);
    k_gru_tc<<<NCTA, 256, K2_SMEM>>>(Whh_f, bhh_f, Whh_b, bhh_b, lengths);

    cudaFuncSetAttribute(k_gemm_proj_tc, cudaFuncAttributeMaxDynamicSharedMemorySize, SMEM_TC2);
    dim3 g3(4, 256);
    k_gemm_proj_tc<<<g3, 512, SMEM_TC2>>>(bp, ctx);

    k_final<<<Bsz, 512>>>(lengths, Wl, bl, out, out_size);
}

// round 11
// speedup vs baseline: 1.4669x; 1.1495x over previous
#include <cuda_runtime.h>
#include <cuda_fp16.h>
#include <math.h>
#include <stdint.h>

#define Bsz 128
#define Tt  512
#define H3  1536
#define BT  65536
#define NCTA 128

__device__ float g_G[201326592];    // [dir][b*T+t][1536]
__device__ float g_out[67108864];   // [b][t][1024] fp32 (for K4)
__device__ __half g_outh[67108864]; // fp16 of out (A side of K3)
__device__ float g_scores[65536];
__device__ int   g_tok2[131072];
__device__ unsigned g_cnt4[4], g_gen4[4], g_done;

// fp16 operands
__device__ __half g_Xh[67108864];   // [2*BT][512]   X hi only
__device__ __half g_Wh[1572864];    // [2][1536][512] Wih hi
__device__ __half g_Wph[524288];    // [512][1024]    Wp  hi
__device__ __half g_hbh[262144];    // [ph][d][128][512]  h hi
__device__ __half g_hbl[262144];    // [ph][d][128][512]  h lo (recurrence stays split)

// ---------------------------------------------------------------- helpers
__device__ __forceinline__ uint32_t smem_u32(const void* p)
{
    uint32_t a;
    asm("{ .reg .u64 t; cvta.to.shared.u64 t, %1; cvt.u32.u64 %0, t; }" : "=r"(a) : "l"(p));
    return a;
}
__device__ __forceinline__ void cp16(uint32_t dst, const void* src)
{
    asm volatile("cp.async.cg.shared.global [%0], [%1], 16;" :: "r"(dst), "l"(src) : "memory");
}
__device__ __forceinline__ void cp_commit()
{
    asm volatile("cp.async.commit_group;" ::: "memory");
}
__device__ __forceinline__ void ldsm4(uint32_t* r, uint32_t addr)
{
    asm volatile("ldmatrix.sync.aligned.m8n8.x4.shared.b16 {%0,%1,%2,%3}, [%4];"
                 : "=r"(r[0]), "=r"(r[1]), "=r"(r[2]), "=r"(r[3]) : "r"(addr));
}
__device__ __forceinline__ void ldsm2(uint32_t* r, uint32_t addr)
{
    asm volatile("ldmatrix.sync.aligned.m8n8.x2.shared.b16 {%0,%1}, [%2];"
                 : "=r"(r[0]), "=r"(r[1]) : "r"(addr));
}
__device__ __forceinline__ void mma16816(float* c, const uint32_t* a, uint32_t b0, uint32_t b1)
{
    asm volatile("mma.sync.aligned.m16n8k16.row.col.f32.f16.f16.f32 "
                 "{%0,%1,%2,%3}, {%4,%5,%6,%7}, {%8,%9}, {%0,%1,%2,%3};"
                 : "+f"(c[0]), "+f"(c[1]), "+f"(c[2]), "+f"(c[3])
                 : "r"(a[0]), "r"(a[1]), "r"(a[2]), "r"(a[3]), "r"(b0), "r"(b1));
}
__device__ __forceinline__ void split_fp16(float v, __half& h, __half& l)
{
    h = __float2half_rn(v);
    l = __float2half_rn(v - __half2float(h));
}

// ---------------------------------------------------------------- K0
__global__ void k_init(const int* __restrict__ tokens, const int* __restrict__ lengths)
{
    int i = blockIdx.x * blockDim.x + threadIdx.x;
    if (i >= BT) return;
    int b = i >> 9, t = i & 511;
    g_tok2[i] = tokens[i];
    int rt = lengths[b] - 1 - t;
    if (rt < 0) rt = 0;
    g_tok2[BT + i] = tokens[(b << 9) + rt];
    g_scores[i] = 0.f;
    ((uint2*)g_hbh)[i] = make_uint2(0u, 0u);
    ((uint2*)g_hbl)[i] = make_uint2(0u, 0u);
}

// ---------------------------------------------------------------- conv kernels
__global__ void k_convX(const float* __restrict__ emb)
{
    size_t idx = (size_t)blockIdx.x * 256 + threadIdx.x;
    size_t e = idx * 4;
    size_t row = e >> 9;
    int k = (int)(e & 511);
    int tok = g_tok2[row];
    float4 v = *(const float4*)(emb + (size_t)tok * 512 + k);
    __half2* ph = (__half2*)(g_Xh + row * 512 + k);
    ph[0] = __half2{__float2half_rn(v.x), __float2half_rn(v.y)};
    ph[1] = __half2{__float2half_rn(v.z), __float2half_rn(v.w)};
}

__global__ void k_convW(const float* __restrict__ Wf, const float* __restrict__ Wb)
{
    size_t idx = (size_t)blockIdx.x * 256 + threadIdx.x;
    size_t e = idx * 4;
    size_t row = e >> 9;
    int k = (int)(e & 511);
    int d = (int)(row >= 1536);
    size_t n = row - (size_t)d * 1536;
    const float* W = d ? Wb : Wf;
    float4 v = *(const float4*)(W + n * 512 + k);
    __half2* ph = (__half2*)(g_Wh + row * 512 + k);
    ph[0] = __half2{__float2half_rn(v.x), __float2half_rn(v.y)};
    ph[1] = __half2{__float2half_rn(v.z), __float2half_rn(v.w)};
}

__global__ void k_convP(const float* __restrict__ Wp)
{
    size_t idx = (size_t)blockIdx.x * 256 + threadIdx.x;
    size_t e = idx * 4;
    float4 v = *(const float4*)(Wp + e);
    __half2* ph = (__half2*)(g_Wph + e);
    ph[0] = __half2{__float2half_rn(v.x), __float2half_rn(v.y)};
    ph[1] = __half2{__float2half_rn(v.z), __float2half_rn(v.w)};
}

// ---------------------------------------------------------------- 1-pass GEMM staging
// CTA tile 256(M) x 128(N), 512 threads. Per buffer 30720 B:
//   Ah@0 (256x80), Bh@20480 (128x80). Chunk = 32 fp16 = 64 B/row, q in 0..3.
#define TB2 30720
#define SMEM_TC2 (2 * TB2)
extern __shared__ char sm_tc[];

__device__ __forceinline__ void issue_chunk2(
    uint32_t sbase, const __half* Ah, const __half* Bh, int k0, int tid, int ldk)
{
    #pragma unroll
    for (int j = 0; j < 3; j++) {
        int L = tid + j * 512;          // 0..1535
        if (L < 1024) {                 // A: 256 rows x 4 q
            int row = L >> 2, q = L & 3;
            cp16(sbase + row * 80 + q * 16,
                 (const char*)(Ah + (size_t)row * ldk + k0) + q * 16);
        } else {                        // B: 128 rows x 4 q
            int r = L - 1024;
            int row = r >> 2, q = r & 3;
            cp16(sbase + 20480 + row * 80 + q * 16,
                 (const char*)(Bh + (size_t)row * ldk + k0) + q * 16);
        }
    }
    cp_commit();
}

// ---------------------------------------------------------------- K1: input-gate GEMM (fp16 1-pass, 256x128)
__global__ void __launch_bounds__(512) k_gemm_ih_tc(
    const float* __restrict__ bf, const float* __restrict__ bb)
{
    uint32_t sb = smem_u32(sm_tc);
    int tid = threadIdx.x, wid = tid >> 5, lane = tid & 31;
    int d = blockIdx.z, mb = blockIdx.y * 256, nb = blockIdx.x * 128;
    const float* bias = (d ? bb : bf) + nb;

    const __half* Xh = g_Xh + (size_t)(d * BT + mb) * 512;
    const __half* Wh = g_Wh + (size_t)(d * 1536 + nb) * 512;

    int wm = (wid & 3) * 64;
    int wn = (wid >> 2) * 32;

    float acc[4][4][4];
    #pragma unroll
    for (int f = 0; f < 4; f++)
        #pragma unroll
        for (int n = 0; n < 4; n++)
            #pragma unroll
            for (int r = 0; r < 4; r++) acc[f][n][r] = 0.f;

    issue_chunk2(sb,       Xh, Wh, 0,  tid, 512);
    issue_chunk2(sb + TB2, Xh, Wh, 32, tid, 512);

    int arow = (lane & 15);
    int ahk  = ((lane >> 4) & 1) * 16;
    int brow = (lane & 7) + ((lane >> 4) & 1) * 8;
    int bhk  = ((lane >> 3) & 1) * 16;

    for (int c = 0; c < 16; c++) {
        if (c < 15) asm volatile("cp.async.wait_group 1;" ::: "memory");
        else        asm volatile("cp.async.wait_group 0;" ::: "memory");
        __syncthreads();
        uint32_t base = sb + (c & 1) * TB2;
        uint32_t aA = base +         (wm + arow) * 80 + ahk;
        uint32_t aB = base + 20480 + (wn + brow) * 80 + bhk;

        #pragma unroll
        for (int s = 0; s < 2; s++) {
            uint32_t ah[4][4], bh[2][4];
            #pragma unroll
            for (int f = 0; f < 4; f++)
                ldsm4(ah[f], aA + f * 16 * 80 + s * 32);
            #pragma unroll
            for (int g = 0; g < 2; g++)
                ldsm4(bh[g], aB + g * 16 * 80 + s * 32);
            #pragma unroll
            for (int f = 0; f < 4; f++)
                #pragma unroll
                for (int n = 0; n < 4; n++)
                    mma16816(acc[f][n], ah[f], bh[n >> 1][(n & 1) * 2], bh[n >> 1][(n & 1) * 2 + 1]);
        }
        __syncthreads();
        if (c + 2 < 16)
            issue_chunk2(sb + (c & 1) * TB2, Xh, Wh, (c + 2) * 32, tid, 512);
    }

    #pragma unroll
    for (int f = 0; f < 4; f++) {
        int row = mb + wm + f * 16 + (lane >> 2);
        float* gp0 = g_G + ((size_t)d * BT + row) * H3 + nb;
        float* gp1 = gp0 + 8 * H3;
        #pragma unroll
        for (int n = 0; n < 4; n++) {
            int col = wn + n * 8 + (lane & 3) * 2;
            float b0 = __ldg(bias + col), b1 = __ldg(bias + col + 1);
            *(float2*)(gp0 + col) = make_float2(acc[f][n][0] + b0, acc[f][n][1] + b1);
            *(float2*)(gp1 + col) = make_float2(acc[f][n][2] + b0, acc[f][n][3] + b1);
        }
    }
}

// ---------------------------------------------------------------- group barrier
__device__ __forceinline__ void group_barrier(int gid, unsigned target)
{
    __syncthreads();
    if (threadIdx.x == 0) {
        __threadfence();
        unsigned a = atomicAdd(&g_cnt4[gid], 1u) + 1u;
        if (a == target * 32u) {
            atomicAdd(&g_gen4[gid], 1u);
        } else {
            while (*(volatile unsigned*)&g_gen4[gid] < target) { }
        }
        __threadfence();
    }
    __syncthreads();
}

// ---------------------------------------------------------------- K2: fp16 2-pass bi-GRU recurrence (unchanged)
#define K2_WH   0
#define K2_H    49920
#define K2_GATE 154368
#define K2_SMEM 167680
extern __shared__ char sm2[];

__device__ __forceinline__ void k2_stage(uint32_t dsth, size_t hsrc, int kc, int tid)
{
    #pragma unroll
    for (int j = 0; j < 4; j++) {
        int L = tid + j * 256;
        int row = L >> 4, q = L & 15;
        cp16(dsth + row * 272 + q * 16,         (const char*)(g_hbh + hsrc + (size_t)row * 512 + kc) + q * 16);
        cp16(dsth + 17408 + row * 272 + q * 16, (const char*)(g_hbl + hsrc + (size_t)row * 512 + kc) + q * 16);
    }
    cp_commit();
}

__global__ void __launch_bounds__(256) k_gru_tc(
    const float* __restrict__ Whh_f, const float* __restrict__ bhh_f,
    const float* __restrict__ Whh_b, const float* __restrict__ bhh_b,
    const int*   __restrict__ lengths)
{
    uint32_t sb = smem_u32(sm2);
    int tid = threadIdx.x, wid = tid >> 5, lane = tid & 31;
    int cid = blockIdx.x;
    int d = cid >> 6, bg = (cid >> 5) & 1, ng = cid & 31;
    int gid = d * 2 + bg;
    const float* Whh = d ? Whh_b : Whh_f;
    const float* bhh = d ? bhh_b : bhh_f;

    for (int i = tid; i < 48 * 128; i += 256) {
        int row = i >> 7, k4 = (i & 127) << 2;
        int g = row >> 4, ul = row & 15;
        float4 w = *(const float4*)(Whh + (size_t)(g * 512 + ng * 16 + ul) * 512 + k4);
        char* ph = sm2 + K2_WH + row * 1040 + k4 * 2;
        *(__half2*)ph       = __half2{__float2half_rn(w.x), __float2half_rn(w.y)};
        *(__half2*)(ph + 4) = __half2{__float2half_rn(w.z), __float2half_rn(w.w)};
    }

    int b_loc  = tid >> 2;
    int u0     = (tid & 3) * 4;
    int b_glob = bg * 64 + b_loc;
    int len_b  = lengths[b_glob];
    float bh_r[4], bh_z[4], bh_n[4];
    #pragma unroll
    for (int j = 0; j < 4; j++) {
        int u = ng * 16 + u0 + j;
        bh_r[j] = bhh[u]; bh_z[j] = bhh[512 + u]; bh_n[j] = bhh[1024 + u];
    }
    float hprev[4] = {0.f, 0.f, 0.f, 0.f};

    int m0  = (wid & 3) * 16;
    int n0w = (wid >> 2) * 24;
    uint32_t aoffA  = (uint32_t)((m0 + (lane & 15)) * 272 + ((lane >> 4) & 1) * 16);
    uint32_t aoffB4 = (uint32_t)((n0w + (lane & 7) + ((lane >> 4) & 1) * 8) * 1040 + ((lane >> 3) & 1) * 16);
    uint32_t aoffB2 = (uint32_t)((n0w + 16 + (lane & 7)) * 1040 + ((lane >> 3) & 1) * 16);

    float* gsm = (float*)(sm2 + K2_GATE);
    __syncthreads();

    for (int t = 0; t < 512; t++) {
        int ph = t & 1;
        const float* gp = g_G + (size_t)d * BT * H3 + ((size_t)b_glob * 512 + t) * H3 + ng * 16 + u0;
        float4 gir = __ldg((const float4*)gp);
        float4 giz = __ldg((const float4*)(gp + 512));
        float4 gin = __ldg((const float4*)(gp + 1024));

        size_t hsrc = ((size_t)(ph * 2 + d) * 128 + bg * 64) * 512;
        k2_stage(sb + K2_H,         hsrc, 0,   tid);
        k2_stage(sb + K2_H + 34816, hsrc, 128, tid);

        float acc[3][4];
        #pragma unroll
        for (int n = 0; n < 3; n++)
            #pragma unroll
            for (int r = 0; r < 4; r++) acc[n][r] = 0.f;

        for (int c = 0; c < 4; c++) {
            if (c < 3) asm volatile("cp.async.wait_group 1;" ::: "memory");
            else       asm volatile("cp.async.wait_group 0;" ::: "memory");
            __syncthreads();
            if (c + 2 < 4)
                k2_stage(sb + K2_H + ((c + 2) % 3) * 34816, hsrc, (c + 2) * 128, tid);
            uint32_t hb_hi = sb + K2_H + (c % 3) * 34816;
            uint32_t hb_lo = hb_hi + 17408;
            #pragma unroll
            for (int kt = 0; kt < 8; kt++) {
                uint32_t koffH = kt * 32;
                uint32_t koffW = (uint32_t)(c * 128 + kt * 16) * 2;
                uint32_t ah[4], al[4], bh4[4], b2h[2];
                ldsm4(ah, hb_hi + aoffA + koffH);
                ldsm4(al, hb_lo + aoffA + koffH);
                ldsm4(bh4, sb + K2_WH + aoffB4 + koffW);
                ldsm2(b2h, sb + K2_WH + aoffB2 + koffW);
                mma16816(acc[0], ah, bh4[0], bh4[1]);
                mma16816(acc[1], ah, bh4[2], bh4[3]);
                mma16816(acc[2], ah, b2h[0], b2h[1]);
                mma16816(acc[0], al, bh4[0], bh4[1]);
                mma16816(acc[1], al, bh4[2], bh4[3]);
                mma16816(acc[2], al, b2h[0], b2h[1]);
            }
        }

        int grow = m0 + (lane >> 2);
        #pragma unroll
        for (int j = 0; j < 3; j++) {
            int col = n0w + j * 8 + (lane & 3) * 2;
            gsm[grow * 52 + col]           = acc[j][0];
            gsm[grow * 52 + col + 1]       = acc[j][1];
            gsm[(grow + 8) * 52 + col]     = acc[j][2];
            gsm[(grow + 8) * 52 + col + 1] = acc[j][3];
        }
        __syncthreads();

        float gi_r[4], gi_z[4], gi_n[4];
        *(float4*)gi_r = gir; *(float4*)gi_z = giz; *(float4*)gi_n = gin;
        bool m = (t < len_b);
        size_t hwb = ((size_t)((ph ^ 1) * 2 + d) * 128 + b_glob) * 512 + ng * 16;
        int orow = (d == 0) ? t : (m ? (len_b - 1 - t) : t);
        size_t ob = ((size_t)b_glob * 512 + orow) * 1024 + d * 512 + ng * 16;

        float hm[4], ov[4];
        #pragma unroll
        for (int j = 0; j < 4; j++) {
            int u = u0 + j;
            float ar = gsm[b_loc * 52 + u];
            float az = gsm[b_loc * 52 + 16 + u];
            float an = gsm[b_loc * 52 + 32 + u];
            float rr = 1.f / (1.f + expf(-(gi_r[j] + ar + bh_r[j])));
            float zz = 1.f / (1.f + expf(-(gi_z[j] + az + bh_z[j])));
            float nn = tanhf(gi_n[j] + rr * (an + bh_n[j]));
            float hn = (1.f - zz) * nn + zz * hprev[j];
            hm[j] = m ? hn : hprev[j];
            hprev[j] = hm[j];
            ov[j] = m ? hn : 0.f;
        }
        __half hh[4], hl[4];
        #pragma unroll
        for (int j = 0; j < 4; j++)
            split_fp16(hm[j], hh[j], hl[j]);
        *(__half2*)(g_hbh + hwb + u0)     = __half2{hh[0], hh[1]};
        *(__half2*)(g_hbh + hwb + u0 + 2) = __half2{hh[2], hh[3]};
        *(__half2*)(g_hbl + hwb + u0)     = __half2{hl[0], hl[1]};
        *(__half2*)(g_hbl + hwb + u0 + 2) = __half2{hl[2], hl[3]};
        *(float4*)(g_out + ob + u0) = make_float4(ov[0], ov[1], ov[2], ov[3]);
        *(__half2*)(g_outh + ob + u0)     = __half2{__float2half_rn(ov[0]), __float2half_rn(ov[1])};
        *(__half2*)(g_outh + ob + u0 + 2) = __half2{__float2half_rn(ov[2]), __float2half_rn(ov[3])};

        group_barrier(gid, (unsigned)(t + 1));
    }

    if (tid == 0) {
        unsigned old = atomicAdd(&g_done, 1u);
        if (old == NCTA - 1) {
            #pragma unroll
            for (int g = 0; g < 4; g++) { g_cnt4[g] = 0; g_gen4[g] = 0; }
            g_done = 0;
            __threadfence();
        }
    }
}

// ---------------------------------------------------------------- K3: fp16 1-pass proj + fused ctx-dot (256x128)
__global__ void __launch_bounds__(512) k_gemm_proj_tc(
    const float* __restrict__ bp, const float* __restrict__ ctx)
{
    uint32_t sb = smem_u32(sm_tc);
    int tid = threadIdx.x, wid = tid >> 5, lane = tid & 31;
    int mb = blockIdx.y * 256, nb = blockIdx.x * 128;

    const __half* Ah = g_outh + (size_t)mb * 1024;
    const __half* Bh = g_Wph + (size_t)nb * 1024;

    int wm = (wid & 3) * 64;
    int wn = (wid >> 2) * 32;

    float acc[4][4][4];
    #pragma unroll
    for (int f = 0; f < 4; f++)
        #pragma unroll
        for (int n = 0; n < 4; n++)
            #pragma unroll
            for (int r = 0; r < 4; r++) acc[f][n][r] = 0.f;

    issue_chunk2(sb,       Ah, Bh, 0,  tid, 1024);
    issue_chunk2(sb + TB2, Ah, Bh, 32, tid, 1024);

    int arow = (lane & 15);
    int ahk  = ((lane >> 4) & 1) * 16;
    int brow = (lane & 7) + ((lane >> 4) & 1) * 8;
    int bhk  = ((lane >> 3) & 1) * 16;

    for (int c = 0; c < 32; c++) {
        if (c < 31) asm volatile("cp.async.wait_group 1;" ::: "memory");
        else        asm volatile("cp.async.wait_group 0;" ::: "memory");
        __syncthreads();
        uint32_t base = sb + (c & 1) * TB2;
        uint32_t aA = base +         (wm + arow) * 80 + ahk;
        uint32_t aB = base + 20480 + (wn + brow) * 80 + bhk;

        #pragma unroll
        for (int s = 0; s < 2; s++) {
            uint32_t ah[4][4], bh[2][4];
            #pragma unroll
            for (int f = 0; f < 4; f++)
                ldsm4(ah[f], aA + f * 16 * 80 + s * 32);
            #pragma unroll
            for (int g = 0; g < 2; g++)
                ldsm4(bh[g], aB + g * 16 * 80 + s * 32);
            #pragma unroll
            for (int f = 0; f < 4; f++)
                #pragma unroll
                for (int n = 0; n < 4; n++)
                    mma16816(acc[f][n], ah[f], bh[n >> 1][(n & 1) * 2], bh[n >> 1][(n & 1) * 2 + 1]);
        }
        __syncthreads();
        if (c + 2 < 32)
            issue_chunk2(sb + (c & 1) * TB2, Ah, Bh, (c + 2) * 32, tid, 1024);
    }

    #pragma unroll
    for (int f = 0; f < 4; f++) {
        int r0 = mb + wm + f * 16 + (lane >> 2);
        float p0 = 0.f, p1 = 0.f;
        #pragma unroll
        for (int n = 0; n < 4; n++) {
            int col = nb + wn + n * 8 + (lane & 3) * 2;
            float c0 = __ldg(ctx + col), c1 = __ldg(ctx + col + 1);
            float b0 = __ldg(bp + col),  b1 = __ldg(bp + col + 1);
            p0 += tanhf(acc[f][n][0] + b0) * c0 + tanhf(acc[f][n][1] + b1) * c1;
            p1 += tanhf(acc[f][n][2] + b0) * c0 + tanhf(acc[f][n][3] + b1) * c1;
        }
        p0 += __shfl_xor_sync(0xffffffffu, p0, 1);
        p0 += __shfl_xor_sync(0xffffffffu, p0, 2);
        p1 += __shfl_xor_sync(0xffffffffu, p1, 1);
        p1 += __shfl_xor_sync(0xffffffffu, p1, 2);
        if ((lane & 3) == 0) {
            atomicAdd(&g_scores[r0], p0);
            atomicAdd(&g_scores[r0 + 8], p1);
        }
    }
}

// ---------------------------------------------------------------- K4: softmax + pooling + SELU + logits
__global__ void __launch_bounds__(512) k_final(
    const int* __restrict__ lengths,
    const float* __restrict__ Wl, const float* __restrict__ bl,
    float* __restrict__ out, int out_size)
{
    __shared__ float sh[512];
    __shared__ float attn[512];
    __shared__ float lg[2];
    int b = blockIdx.x, tid = threadIdx.x;
    int len = lengths[b];
    float s = (tid < len) ? g_scores[b * 512 + tid] : -1e30f;
    sh[tid] = s; __syncthreads();
    for (int o = 256; o > 0; o >>= 1) { if (tid < o) sh[tid] = fmaxf(sh[tid], sh[tid + o]); __syncthreads(); }
    float mx = sh[0]; __syncthreads();
    float e = (tid < len) ? expf(s - mx) : 0.f;
    sh[tid] = e; __syncthreads();
    for (int o = 256; o > 0; o >>= 1) { if (tid < o) sh[tid] += sh[tid + o]; __syncthreads(); }
    float a = e / sh[0];
    attn[tid] = a;
    int attn_ofs = (out_size >= 65792) ? 256 : 0;
    if (out_size != 256) out[attn_ofs + b * 512 + tid] = a;
    if (tid == 0) { lg[0] = 0.f; lg[1] = 0.f; }
    __syncthreads();

    const float* ob = g_out + (long)b * 512 * 1024;
    float s0 = 0.f, s1 = 0.f;
    for (int t = 0; t < 512; t++) {
        float at = attn[t];
        s0 = fmaf(at, ob[(long)t * 1024 + tid],       s0);
        s1 = fmaf(at, ob[(long)t * 1024 + 512 + tid], s1);
    }
    const float SC = 1.0507009873554805f, AL = 1.6732632423543772f;
    s0 = (s0 > 0.f) ? SC * s0 : SC * AL * (expf(s0) - 1.f);
    s1 = (s1 > 0.f) ? SC * s1 : SC * AL * (expf(s1) - 1.f);
    float p0 = s0 * Wl[tid]        + s1 * Wl[512 + tid];
    float p1 = s0 * Wl[1024 + tid] + s1 * Wl[1536 + tid];
    #pragma unroll
    for (int o = 16; o > 0; o >>= 1) {
        p0 += __shfl_xor_sync(0xffffffffu, p0, o);
        p1 += __shfl_xor_sync(0xffffffffu, p1, o);
    }
    if ((tid & 31) == 0) { atomicAdd(&lg[0], p0); atomicAdd(&lg[1], p1); }
    __syncthreads();
    if (tid < 2 && out_size != 65536) out[b * 2 + tid] = lg[tid] + bl[tid];
}

// ---------------------------------------------------------------- launch
extern "C" void kernel_launch(void* const* d_in, const int* in_sizes, int n_in,
                              void* d_out, int out_size)
{
    const int*   tokens  = (const int*)d_in[0];
    const int*   lengths = (const int*)d_in[1];
    const float* emb     = (const float*)d_in[2];
    const float* Wih_f   = (const float*)d_in[3];
    const float* Whh_f   = (const float*)d_in[4];
    const float* bih_f   = (const float*)d_in[5];
    const float* bhh_f   = (const float*)d_in[6];
    const float* Wih_b   = (const float*)d_in[7];
    const float* Whh_b   = (const float*)d_in[8];
    const float* bih_b   = (const float*)d_in[9];
    const float* bhh_b   = (const float*)d_in[10];
    const float* Wp      = (const float*)d_in[11];
    const float* bp      = (const float*)d_in[12];
    const float* ctx     = (const float*)d_in[13];
    const float* Wl      = (const float*)d_in[14];
    const float* bl      = (const float*)d_in[15];
    float* out = (float*)d_out;

    k_init<<<BT / 256, 256>>>(tokens, lengths);
    k_convW<<<1536, 256>>>(Wih_f, Wih_b);
    k_convX<<<65536, 256>>>(emb);
    k_convP<<<512, 256>>>(Wp);

    cudaFuncSetAttribute(k_gemm_ih_tc, cudaFuncAttributeMaxDynamicSharedMemorySize, SMEM_TC2);
    dim3 g1(12, 256, 2);
    k_gemm_ih_tc<<<g1, 512, SMEM_TC2>>>(bih_f, bih_b);

    cudaFuncSetAttribute(k_gru_tc, cudaFuncAttributeMaxDynamicSharedMemorySize, K2_SMEM);
    k_gru_tc<<<NCTA, 256, K2_SMEM>>>(Whh_f, bhh_f, Whh_b, bhh_b, lengths);

    cudaFuncSetAttribute(k_gemm_proj_tc, cudaFuncAttributeMaxDynamicSharedMemorySize, SMEM_TC2);
    dim3 g3(4, 256);
    k_gemm_proj_tc<<<g3, 512, SMEM_TC2>>>(bp, ctx);

    k_final<<<Bsz, 512>>>(lengths, Wl, bl, out, out_size);
}

// round 12
// speedup vs baseline: 1.7179x; 1.1711x over previous
#include <cuda_runtime.h>
#include <cuda_fp16.h>
#include <math.h>
#include <stdint.h>

#define Bsz 128
#define Tt  512
#define H3  1536
#define BT  65536
#define NCTA 128

__device__ __half g_G[201326592];   // [dir][b*T+t][1536] fp16 gate preactivations
__device__ float g_out[67108864];   // [b][t][1024] fp32 (for K4)
__device__ __half g_outh[67108864]; // fp16 of out (A side of K3)
__device__ float g_scores[65536];
__device__ int   g_tok2[131072];
__device__ unsigned g_cnt4[4], g_gen4[4], g_done;

// fp16 operands (all hi-only now)
__device__ __half g_Xh[67108864];   // [2*BT][512]
__device__ __half g_Wh[1572864];    // [2][1536][512]
__device__ __half g_Wph[524288];    // [512][1024]
__device__ __half g_hbh[262144];    // [ph][d][128][512]

// ---------------------------------------------------------------- helpers
__device__ __forceinline__ uint32_t smem_u32(const void* p)
{
    uint32_t a;
    asm("{ .reg .u64 t; cvta.to.shared.u64 t, %1; cvt.u32.u64 %0, t; }" : "=r"(a) : "l"(p));
    return a;
}
__device__ __forceinline__ void cp16(uint32_t dst, const void* src)
{
    asm volatile("cp.async.cg.shared.global [%0], [%1], 16;" :: "r"(dst), "l"(src) : "memory");
}
__device__ __forceinline__ void cp_commit()
{
    asm volatile("cp.async.commit_group;" ::: "memory");
}
__device__ __forceinline__ void ldsm4(uint32_t* r, uint32_t addr)
{
    asm volatile("ldmatrix.sync.aligned.m8n8.x4.shared.b16 {%0,%1,%2,%3}, [%4];"
                 : "=r"(r[0]), "=r"(r[1]), "=r"(r[2]), "=r"(r[3]) : "r"(addr));
}
__device__ __forceinline__ void ldsm2(uint32_t* r, uint32_t addr)
{
    asm volatile("ldmatrix.sync.aligned.m8n8.x2.shared.b16 {%0,%1}, [%2];"
                 : "=r"(r[0]), "=r"(r[1]) : "r"(addr));
}
__device__ __forceinline__ void mma16816(float* c, const uint32_t* a, uint32_t b0, uint32_t b1)
{
    asm volatile("mma.sync.aligned.m16n8k16.row.col.f32.f16.f16.f32 "
                 "{%0,%1,%2,%3}, {%4,%5,%6,%7}, {%8,%9}, {%0,%1,%2,%3};"
                 : "+f"(c[0]), "+f"(c[1]), "+f"(c[2]), "+f"(c[3])
                 : "r"(a[0]), "r"(a[1]), "r"(a[2]), "r"(a[3]), "r"(b0), "r"(b1));
}

// ---------------------------------------------------------------- K0
__global__ void k_init(const int* __restrict__ tokens, const int* __restrict__ lengths)
{
    int i = blockIdx.x * blockDim.x + threadIdx.x;
    if (i >= BT) return;
    int b = i >> 9, t = i & 511;
    g_tok2[i] = tokens[i];
    int rt = lengths[b] - 1 - t;
    if (rt < 0) rt = 0;
    g_tok2[BT + i] = tokens[(b << 9) + rt];
    g_scores[i] = 0.f;
    ((uint2*)g_hbh)[i] = make_uint2(0u, 0u);
}

// ---------------------------------------------------------------- conv kernels
__global__ void k_convX(const float* __restrict__ emb)
{
    size_t idx = (size_t)blockIdx.x * 256 + threadIdx.x;
    size_t e = idx * 4;
    size_t row = e >> 9;
    int k = (int)(e & 511);
    int tok = g_tok2[row];
    float4 v = *(const float4*)(emb + (size_t)tok * 512 + k);
    __half2* ph = (__half2*)(g_Xh + row * 512 + k);
    ph[0] = __half2{__float2half_rn(v.x), __float2half_rn(v.y)};
    ph[1] = __half2{__float2half_rn(v.z), __float2half_rn(v.w)};
}

__global__ void k_convW(const float* __restrict__ Wf, const float* __restrict__ Wb)
{
    size_t idx = (size_t)blockIdx.x * 256 + threadIdx.x;
    size_t e = idx * 4;
    size_t row = e >> 9;
    int k = (int)(e & 511);
    int d = (int)(row >= 1536);
    size_t n = row - (size_t)d * 1536;
    const float* W = d ? Wb : Wf;
    float4 v = *(const float4*)(W + n * 512 + k);
    __half2* ph = (__half2*)(g_Wh + row * 512 + k);
    ph[0] = __half2{__float2half_rn(v.x), __float2half_rn(v.y)};
    ph[1] = __half2{__float2half_rn(v.z), __float2half_rn(v.w)};
}

__global__ void k_convP(const float* __restrict__ Wp)
{
    size_t idx = (size_t)blockIdx.x * 256 + threadIdx.x;
    size_t e = idx * 4;
    float4 v = *(const float4*)(Wp + e);
    __half2* ph = (__half2*)(g_Wph + e);
    ph[0] = __half2{__float2half_rn(v.x), __float2half_rn(v.y)};
    ph[1] = __half2{__float2half_rn(v.z), __float2half_rn(v.w)};
}

// ---------------------------------------------------------------- 1-pass GEMM staging
// CTA tile 256(M) x 128(N), 512 threads. Per buffer 30720 B:
//   Ah@0 (256x80), Bh@20480 (128x80). Chunk = 32 fp16 = 64 B/row, q in 0..3.
#define TB2 30720
#define SMEM_TC2 (2 * TB2)
extern __shared__ char sm_tc[];

__device__ __forceinline__ void issue_chunk2(
    uint32_t sbase, const __half* Ah, const __half* Bh, int k0, int tid, int ldk)
{
    #pragma unroll
    for (int j = 0; j < 3; j++) {
        int L = tid + j * 512;          // 0..1535
        if (L < 1024) {                 // A: 256 rows x 4 q
            int row = L >> 2, q = L & 3;
            cp16(sbase + row * 80 + q * 16,
                 (const char*)(Ah + (size_t)row * ldk + k0) + q * 16);
        } else {                        // B: 128 rows x 4 q
            int r = L - 1024;
            int row = r >> 2, q = r & 3;
            cp16(sbase + 20480 + row * 80 + q * 16,
                 (const char*)(Bh + (size_t)row * ldk + k0) + q * 16);
        }
    }
    cp_commit();
}

// ---------------------------------------------------------------- K1: input-gate GEMM (fp16 1-pass, 256x128)
__global__ void __launch_bounds__(512) k_gemm_ih_tc(
    const float* __restrict__ bf, const float* __restrict__ bb)
{
    uint32_t sb = smem_u32(sm_tc);
    int tid = threadIdx.x, wid = tid >> 5, lane = tid & 31;
    int d = blockIdx.z, mb = blockIdx.y * 256, nb = blockIdx.x * 128;
    const float* bias = (d ? bb : bf) + nb;

    const __half* Xh = g_Xh + (size_t)(d * BT + mb) * 512;
    const __half* Wh = g_Wh + (size_t)(d * 1536 + nb) * 512;

    int wm = (wid & 3) * 64;
    int wn = (wid >> 2) * 32;

    float acc[4][4][4];
    #pragma unroll
    for (int f = 0; f < 4; f++)
        #pragma unroll
        for (int n = 0; n < 4; n++)
            #pragma unroll
            for (int r = 0; r < 4; r++) acc[f][n][r] = 0.f;

    issue_chunk2(sb,       Xh, Wh, 0,  tid, 512);
    issue_chunk2(sb + TB2, Xh, Wh, 32, tid, 512);

    int arow = (lane & 15);
    int ahk  = ((lane >> 4) & 1) * 16;
    int brow = (lane & 7) + ((lane >> 4) & 1) * 8;
    int bhk  = ((lane >> 3) & 1) * 16;

    for (int c = 0; c < 16; c++) {
        if (c < 15) asm volatile("cp.async.wait_group 1;" ::: "memory");
        else        asm volatile("cp.async.wait_group 0;" ::: "memory");
        __syncthreads();
        uint32_t base = sb + (c & 1) * TB2;
        uint32_t aA = base +         (wm + arow) * 80 + ahk;
        uint32_t aB = base + 20480 + (wn + brow) * 80 + bhk;

        #pragma unroll
        for (int s = 0; s < 2; s++) {
            uint32_t ah[4][4], bh[2][4];
            #pragma unroll
            for (int f = 0; f < 4; f++)
                ldsm4(ah[f], aA + f * 16 * 80 + s * 32);
            #pragma unroll
            for (int g = 0; g < 2; g++)
                ldsm4(bh[g], aB + g * 16 * 80 + s * 32);
            #pragma unroll
            for (int f = 0; f < 4; f++)
                #pragma unroll
                for (int n = 0; n < 4; n++)
                    mma16816(acc[f][n], ah[f], bh[n >> 1][(n & 1) * 2], bh[n >> 1][(n & 1) * 2 + 1]);
        }
        __syncthreads();
        if (c + 2 < 16)
            issue_chunk2(sb + (c & 1) * TB2, Xh, Wh, (c + 2) * 32, tid, 512);
    }

    #pragma unroll
    for (int f = 0; f < 4; f++) {
        int row = mb + wm + f * 16 + (lane >> 2);
        __half* gp0 = g_G + ((size_t)d * BT + row) * H3 + nb;
        __half* gp1 = gp0 + 8 * H3;
        #pragma unroll
        for (int n = 0; n < 4; n++) {
            int col = wn + n * 8 + (lane & 3) * 2;
            float b0 = __ldg(bias + col), b1 = __ldg(bias + col + 1);
            *(__half2*)(gp0 + col) = __half2{__float2half_rn(acc[f][n][0] + b0),
                                             __float2half_rn(acc[f][n][1] + b1)};
            *(__half2*)(gp1 + col) = __half2{__float2half_rn(acc[f][n][2] + b0),
                                             __float2half_rn(acc[f][n][3] + b1)};
        }
    }
}

// ---------------------------------------------------------------- group barrier
__device__ __forceinline__ void group_barrier(int gid, unsigned target)
{
    __syncthreads();
    if (threadIdx.x == 0) {
        __threadfence();
        unsigned a = atomicAdd(&g_cnt4[gid], 1u) + 1u;
        if (a == target * 32u) {
            atomicAdd(&g_gen4[gid], 1u);
        } else {
            while (*(volatile unsigned*)&g_gen4[gid] < target) { }
        }
        __threadfence();
    }
    __syncthreads();
}

// ---------------------------------------------------------------- K2: fp16 1-pass bi-GRU recurrence
// smem: Wh 49920 | H 3 bufs x 17408 | gate 64x52 fp32
#define K2_WH   0
#define K2_H    49920
#define K2_GATE 102144
#define K2_SMEM 115456
extern __shared__ char sm2[];

__device__ __forceinline__ void k2_stage(uint32_t dsth, size_t hsrc, int kc, int tid)
{
    #pragma unroll
    for (int j = 0; j < 4; j++) {
        int L = tid + j * 256;
        int row = L >> 4, q = L & 15;
        cp16(dsth + row * 272 + q * 16,
             (const char*)(g_hbh + hsrc + (size_t)row * 512 + kc) + q * 16);
    }
    cp_commit();
}

__global__ void __launch_bounds__(256) k_gru_tc(
    const float* __restrict__ Whh_f, const float* __restrict__ bhh_f,
    const float* __restrict__ Whh_b, const float* __restrict__ bhh_b,
    const int*   __restrict__ lengths)
{
    uint32_t sb = smem_u32(sm2);
    int tid = threadIdx.x, wid = tid >> 5, lane = tid & 31;
    int cid = blockIdx.x;
    int d = cid >> 6, bg = (cid >> 5) & 1, ng = cid & 31;
    int gid = d * 2 + bg;
    const float* Whh = d ? Whh_b : Whh_f;
    const float* bhh = d ? bhh_b : bhh_f;

    for (int i = tid; i < 48 * 128; i += 256) {
        int row = i >> 7, k4 = (i & 127) << 2;
        int g = row >> 4, ul = row & 15;
        float4 w = *(const float4*)(Whh + (size_t)(g * 512 + ng * 16 + ul) * 512 + k4);
        char* ph = sm2 + K2_WH + row * 1040 + k4 * 2;
        *(__half2*)ph       = __half2{__float2half_rn(w.x), __float2half_rn(w.y)};
        *(__half2*)(ph + 4) = __half2{__float2half_rn(w.z), __float2half_rn(w.w)};
    }

    int b_loc  = tid >> 2;
    int u0     = (tid & 3) * 4;
    int b_glob = bg * 64 + b_loc;
    int len_b  = lengths[b_glob];
    float bh_r[4], bh_z[4], bh_n[4];
    #pragma unroll
    for (int j = 0; j < 4; j++) {
        int u = ng * 16 + u0 + j;
        bh_r[j] = bhh[u]; bh_z[j] = bhh[512 + u]; bh_n[j] = bhh[1024 + u];
    }
    float hprev[4] = {0.f, 0.f, 0.f, 0.f};

    int m0  = (wid & 3) * 16;
    int n0w = (wid >> 2) * 24;
    uint32_t aoffA  = (uint32_t)((m0 + (lane & 15)) * 272 + ((lane >> 4) & 1) * 16);
    uint32_t aoffB4 = (uint32_t)((n0w + (lane & 7) + ((lane >> 4) & 1) * 8) * 1040 + ((lane >> 3) & 1) * 16);
    uint32_t aoffB2 = (uint32_t)((n0w + 16 + (lane & 7)) * 1040 + ((lane >> 3) & 1) * 16);

    float* gsm = (float*)(sm2 + K2_GATE);
    __syncthreads();

    for (int t = 0; t < 512; t++) {
        int ph = t & 1;
        const __half* gp = g_G + (size_t)d * BT * H3 + ((size_t)b_glob * 512 + t) * H3 + ng * 16 + u0;
        uint2 vir = __ldg((const uint2*)gp);
        uint2 viz = __ldg((const uint2*)(gp + 512));
        uint2 vin = __ldg((const uint2*)(gp + 1024));

        size_t hsrc = ((size_t)(ph * 2 + d) * 128 + bg * 64) * 512;
        k2_stage(sb + K2_H,         hsrc, 0,   tid);
        k2_stage(sb + K2_H + 17408, hsrc, 128, tid);

        float acc[3][4];
        #pragma unroll
        for (int n = 0; n < 3; n++)
            #pragma unroll
            for (int r = 0; r < 4; r++) acc[n][r] = 0.f;

        for (int c = 0; c < 4; c++) {
            if (c < 3) asm volatile("cp.async.wait_group 1;" ::: "memory");
            else       asm volatile("cp.async.wait_group 0;" ::: "memory");
            __syncthreads();
            if (c + 2 < 4)
                k2_stage(sb + K2_H + ((c + 2) % 3) * 17408, hsrc, (c + 2) * 128, tid);
            uint32_t hb_hi = sb + K2_H + (c % 3) * 17408;
            #pragma unroll
            for (int kt = 0; kt < 8; kt++) {
                uint32_t koffH = kt * 32;
                uint32_t koffW = (uint32_t)(c * 128 + kt * 16) * 2;
                uint32_t ah[4], bh4[4], b2h[2];
                ldsm4(ah, hb_hi + aoffA + koffH);
                ldsm4(bh4, sb + K2_WH + aoffB4 + koffW);
                ldsm2(b2h, sb + K2_WH + aoffB2 + koffW);
                mma16816(acc[0], ah, bh4[0], bh4[1]);
                mma16816(acc[1], ah, bh4[2], bh4[3]);
                mma16816(acc[2], ah, b2h[0], b2h[1]);
            }
        }

        int grow = m0 + (lane >> 2);
        #pragma unroll
        for (int j = 0; j < 3; j++) {
            int col = n0w + j * 8 + (lane & 3) * 2;
            gsm[grow * 52 + col]           = acc[j][0];
            gsm[grow * 52 + col + 1]       = acc[j][1];
            gsm[(grow + 8) * 52 + col]     = acc[j][2];
            gsm[(grow + 8) * 52 + col + 1] = acc[j][3];
        }
        __syncthreads();

        float gi_r[4], gi_z[4], gi_n[4];
        {
            __half2 h0 = *(__half2*)&vir.x, h1 = *(__half2*)&vir.y;
            float2 f0 = __half22float2(h0), f1 = __half22float2(h1);
            gi_r[0] = f0.x; gi_r[1] = f0.y; gi_r[2] = f1.x; gi_r[3] = f1.y;
            h0 = *(__half2*)&viz.x; h1 = *(__half2*)&viz.y;
            f0 = __half22float2(h0); f1 = __half22float2(h1);
            gi_z[0] = f0.x; gi_z[1] = f0.y; gi_z[2] = f1.x; gi_z[3] = f1.y;
            h0 = *(__half2*)&vin.x; h1 = *(__half2*)&vin.y;
            f0 = __half22float2(h0); f1 = __half22float2(h1);
            gi_n[0] = f0.x; gi_n[1] = f0.y; gi_n[2] = f1.x; gi_n[3] = f1.y;
        }
        bool m = (t < len_b);
        size_t hwb = ((size_t)((ph ^ 1) * 2 + d) * 128 + b_glob) * 512 + ng * 16;
        int orow = (d == 0) ? t : (m ? (len_b - 1 - t) : t);
        size_t ob = ((size_t)b_glob * 512 + orow) * 1024 + d * 512 + ng * 16;

        float hm[4], ov[4];
        #pragma unroll
        for (int j = 0; j < 4; j++) {
            int u = u0 + j;
            float ar = gsm[b_loc * 52 + u];
            float az = gsm[b_loc * 52 + 16 + u];
            float an = gsm[b_loc * 52 + 32 + u];
            float rr = 1.f / (1.f + expf(-(gi_r[j] + ar + bh_r[j])));
            float zz = 1.f / (1.f + expf(-(gi_z[j] + az + bh_z[j])));
            float nn = tanhf(gi_n[j] + rr * (an + bh_n[j]));
            float hn = (1.f - zz) * nn + zz * hprev[j];
            hm[j] = m ? hn : hprev[j];
            hprev[j] = hm[j];
            ov[j] = m ? hn : 0.f;
        }
        *(__half2*)(g_hbh + hwb + u0)     = __half2{__float2half_rn(hm[0]), __float2half_rn(hm[1])};
        *(__half2*)(g_hbh + hwb + u0 + 2) = __half2{__float2half_rn(hm[2]), __float2half_rn(hm[3])};
        *(float4*)(g_out + ob + u0) = make_float4(ov[0], ov[1], ov[2], ov[3]);
        *(__half2*)(g_outh + ob + u0)     = __half2{__float2half_rn(ov[0]), __float2half_rn(ov[1])};
        *(__half2*)(g_outh + ob + u0 + 2) = __half2{__float2half_rn(ov[2]), __float2half_rn(ov[3])};

        group_barrier(gid, (unsigned)(t + 1));
    }

    if (tid == 0) {
        unsigned old = atomicAdd(&g_done, 1u);
        if (old == NCTA - 1) {
            #pragma unroll
            for (int g = 0; g < 4; g++) { g_cnt4[g] = 0; g_gen4[g] = 0; }
            g_done = 0;
            __threadfence();
        }
    }
}

// ---------------------------------------------------------------- K3: fp16 1-pass proj + fused ctx-dot (256x128)
__global__ void __launch_bounds__(512) k_gemm_proj_tc(
    const float* __restrict__ bp, const float* __restrict__ ctx)
{
    uint32_t sb = smem_u32(sm_tc);
    int tid = threadIdx.x, wid = tid >> 5, lane = tid & 31;
    int mb = blockIdx.y * 256, nb = blockIdx.x * 128;

    const __half* Ah = g_outh + (size_t)mb * 1024;
    const __half* Bh = g_Wph + (size_t)nb * 1024;

    int wm = (wid & 3) * 64;
    int wn = (wid >> 2) * 32;

    float acc[4][4][4];
    #pragma unroll
    for (int f = 0; f < 4; f++)
        #pragma unroll
        for (int n = 0; n < 4; n++)
            #pragma unroll
            for (int r = 0; r < 4; r++) acc[f][n][r] = 0.f;

    issue_chunk2(sb,       Ah, Bh, 0,  tid, 1024);
    issue_chunk2(sb + TB2, Ah, Bh, 32, tid, 1024);

    int arow = (lane & 15);
    int ahk  = ((lane >> 4) & 1) * 16;
    int brow = (lane & 7) + ((lane >> 4) & 1) * 8;
    int bhk  = ((lane >> 3) & 1) * 16;

    for (int c = 0; c < 32; c++) {
        if (c < 31) asm volatile("cp.async.wait_group 1;" ::: "memory");
        else        asm volatile("cp.async.wait_group 0;" ::: "memory");
        __syncthreads();
        uint32_t base = sb + (c & 1) * TB2;
        uint32_t aA = base +         (wm + arow) * 80 + ahk;
        uint32_t aB = base + 20480 + (wn + brow) * 80 + bhk;

        #pragma unroll
        for (int s = 0; s < 2; s++) {
            uint32_t ah[4][4], bh[2][4];
            #pragma unroll
            for (int f = 0; f < 4; f++)
                ldsm4(ah[f], aA + f * 16 * 80 + s * 32);
            #pragma unroll
            for (int g = 0; g < 2; g++)
                ldsm4(bh[g], aB + g * 16 * 80 + s * 32);
            #pragma unroll
            for (int f = 0; f < 4; f++)
                #pragma unroll
                for (int n = 0; n < 4; n++)
                    mma16816(acc[f][n], ah[f], bh[n >> 1][(n & 1) * 2], bh[n >> 1][(n & 1) * 2 + 1]);
        }
        __syncthreads();
        if (c + 2 < 32)
            issue_chunk2(sb + (c & 1) * TB2, Ah, Bh, (c + 2) * 32, tid, 1024);
    }

    #pragma unroll
    for (int f = 0; f < 4; f++) {
        int r0 = mb + wm + f * 16 + (lane >> 2);
        float p0 = 0.f, p1 = 0.f;
        #pragma unroll
        for (int n = 0; n < 4; n++) {
            int col = nb + wn + n * 8 + (lane & 3) * 2;
            float c0 = __ldg(ctx + col), c1 = __ldg(ctx + col + 1);
            float b0 = __ldg(bp + col),  b1 = __ldg(bp + col + 1);
            p0 += tanhf(acc[f][n][0] + b0) * c0 + tanhf(acc[f][n][1] + b1) * c1;
            p1 += tanhf(acc[f][n][2] + b0) * c0 + tanhf(acc[f][n][3] + b1) * c1;
        }
        p0 += __shfl_xor_sync(0xffffffffu, p0, 1);
        p0 += __shfl_xor_sync(0xffffffffu, p0, 2);
        p1 += __shfl_xor_sync(0xffffffffu, p1, 1);
        p1 += __shfl_xor_sync(0xffffffffu, p1, 2);
        if ((lane & 3) == 0) {
            atomicAdd(&g_scores[r0], p0);
            atomicAdd(&g_scores[r0 + 8], p1);
        }
    }
}

// ---------------------------------------------------------------- K4: softmax + pooling + SELU + logits
__global__ void __launch_bounds__(512) k_final(
    const int* __restrict__ lengths,
    const float* __restrict__ Wl, const float* __restrict__ bl,
    float* __restrict__ out, int out_size)
{
    __shared__ float sh[512];
    __shared__ float attn[512];
    __shared__ float lg[2];
    int b = blockIdx.x, tid = threadIdx.x;
    int len = lengths[b];
    float s = (tid < len) ? g_scores[b * 512 + tid] : -1e30f;
    sh[tid] = s; __syncthreads();
    for (int o = 256; o > 0; o >>= 1) { if (tid < o) sh[tid] = fmaxf(sh[tid], sh[tid + o]); __syncthreads(); }
    float mx = sh[0]; __syncthreads();
    float e = (tid < len) ? expf(s - mx) : 0.f;
    sh[tid] = e; __syncthreads();
    for (int o = 256; o > 0; o >>= 1) { if (tid < o) sh[tid] += sh[tid + o]; __syncthreads(); }
    float a = e / sh[0];
    attn[tid] = a;
    int attn_ofs = (out_size >= 65792) ? 256 : 0;
    if (out_size != 256) out[attn_ofs + b * 512 + tid] = a;
    if (tid == 0) { lg[0] = 0.f; lg[1] = 0.f; }
    __syncthreads();

    const float* ob = g_out + (long)b * 512 * 1024;
    float s0 = 0.f, s1 = 0.f;
    for (int t = 0; t < 512; t++) {
        float at = attn[t];
        s0 = fmaf(at, ob[(long)t * 1024 + tid],       s0);
        s1 = fmaf(at, ob[(long)t * 1024 + 512 + tid], s1);
    }
    const float SC = 1.0507009873554805f, AL = 1.6732632423543772f;
    s0 = (s0 > 0.f) ? SC * s0 : SC * AL * (expf(s0) - 1.f);
    s1 = (s1 > 0.f) ? SC * s1 : SC * AL * (expf(s1) - 1.f);
    float p0 = s0 * Wl[tid]        + s1 * Wl[512 + tid];
    float p1 = s0 * Wl[1024 + tid] + s1 * Wl[1536 + tid];
    #pragma unroll
    for (int o = 16; o > 0; o >>= 1) {
        p0 += __shfl_xor_sync(0xffffffffu, p0, o);
        p1 += __shfl_xor_sync(0xffffffffu, p1, o);
    }
    if ((tid & 31) == 0) { atomicAdd(&lg[0], p0); atomicAdd(&lg[1], p1); }
    __syncthreads();
    if (tid < 2 && out_size != 65536) out[b * 2 + tid] = lg[tid] + bl[tid];
}

// ---------------------------------------------------------------- launch
extern "C" void kernel_launch(void* const* d_in, const int* in_sizes, int n_in,
                              void* d_out, int out_size)
{
    const int*   tokens  = (const int*)d_in[0];
    const int*   lengths = (const int*)d_in[1];
    const float* emb     = (const float*)d_in[2];
    const float* Wih_f   = (const float*)d_in[3];
    const float* Whh_f   = (const float*)d_in[4];
    const float* bih_f   = (const float*)d_in[5];
    const float* bhh_f   = (const float*)d_in[6];
    const float* Wih_b   = (const float*)d_in[7];
    const float* Whh_b   = (const float*)d_in[8];
    const float* bih_b   = (const float*)d_in[9];
    const float* bhh_b   = (const float*)d_in[10];
    const float* Wp      = (const float*)d_in[11];
    const float* bp      = (const float*)d_in[12];
    const float* ctx     = (const float*)d_in[13];
    const float* Wl      = (const float*)d_in[14];
    const float* bl      = (const float*)d_in[15];
    float* out = (float*)d_out;

    k_init<<<BT / 256, 256>>>(tokens, lengths);
    k_convW<<<1536, 256>>>(Wih_f, Wih_b);
    k_convX<<<65536, 256>>>(emb);
    k_convP<<<512, 256>>>(Wp);

    cudaFuncSetAttribute(k_gemm_ih_tc, cudaFuncAttributeMaxDynamicSharedMemorySize, SMEM_TC2);
    dim3 g1(12, 256, 2);
    k_gemm_ih_tc<<<g1, 512, SMEM_TC2>>>(bih_f, bih_b);

    cudaFuncSetAttribute(k_gru_tc, cudaFuncAttributeMaxDynamicSharedMemorySize, K2_SMEM);
    k_gru_tc<<<NCTA, 256, K2_SMEM>>>(Whh_f, bhh_f, Whh_b, bhh_b, lengths);

    cudaFuncSetAttribute(k_gemm_proj_tc, cudaFuncAttributeMaxDynamicSharedMemorySize, SMEM_TC2);
    dim3 g3(4, 256);
    k_gemm_proj_tc<<<g3, 512, SMEM_TC2>>>(bp, ctx);

    k_final<<<Bsz, 512>>>(lengths, Wl, bl, out, out_size);
}

// round 13
// speedup vs baseline: 1.8525x; 1.0784x over previous
#include <cuda_runtime.h>
#include <cuda_fp16.h>
#include <math.h>
#include <stdint.h>

#define Bsz 128
#define Tt  512
#define H3  1536
#define BT  65536
#define NCTA 128

__device__ __half g_G[201326592];   // [d][t][b][1536] fp16 gate preactivations (t-major!)
__device__ float g_out[67108864];   // [b][t][1024] fp32 (for K4)
__device__ __half g_outh[67108864]; // fp16 of out (A side of K3)
__device__ float g_scores[65536];
__device__ int   g_tok2[131072];
__device__ int   g_tdone[1024];     // [d][t] completed tiles (24 = ready)
__device__ unsigned g_cnt4[4], g_gen4[4], g_done;

__device__ __half g_Xh[67108864];   // [2*BT][512]
__device__ __half g_Wh[1572864];    // [2][1536][512]
__device__ __half g_Wph[524288];    // [512][1024]
__device__ __half g_hbh[262144];    // [ph][d][128][512]

// ---------------------------------------------------------------- helpers
__device__ __forceinline__ uint32_t smem_u32(const void* p)
{
    uint32_t a;
    asm("{ .reg .u64 t; cvta.to.shared.u64 t, %1; cvt.u32.u64 %0, t; }" : "=r"(a) : "l"(p));
    return a;
}
__device__ __forceinline__ void cp16(uint32_t dst, const void* src)
{
    asm volatile("cp.async.cg.shared.global [%0], [%1], 16;" :: "r"(dst), "l"(src) : "memory");
}
__device__ __forceinline__ void cp_commit()
{
    asm volatile("cp.async.commit_group;" ::: "memory");
}
__device__ __forceinline__ void ldsm4(uint32_t* r, uint32_t addr)
{
    asm volatile("ldmatrix.sync.aligned.m8n8.x4.shared.b16 {%0,%1,%2,%3}, [%4];"
                 : "=r"(r[0]), "=r"(r[1]), "=r"(r[2]), "=r"(r[3]) : "r"(addr));
}
__device__ __forceinline__ void ldsm2(uint32_t* r, uint32_t addr)
{
    asm volatile("ldmatrix.sync.aligned.m8n8.x2.shared.b16 {%0,%1}, [%2];"
                 : "=r"(r[0]), "=r"(r[1]) : "r"(addr));
}
__device__ __forceinline__ void mma16816(float* c, const uint32_t* a, uint32_t b0, uint32_t b1)
{
    asm volatile("mma.sync.aligned.m16n8k16.row.col.f32.f16.f16.f32 "
                 "{%0,%1,%2,%3}, {%4,%5,%6,%7}, {%8,%9}, {%0,%1,%2,%3};"
                 : "+f"(c[0]), "+f"(c[1]), "+f"(c[2]), "+f"(c[3])
                 : "r"(a[0]), "r"(a[1]), "r"(a[2]), "r"(a[3]), "r"(b0), "r"(b1));
}
#define NB_REC()  asm volatile("bar.sync 1, 256;" ::: "memory")
#define NB_PROD() asm volatile("bar.sync 2, 128;" ::: "memory")

// ---------------------------------------------------------------- K0
__global__ void k_init(const int* __restrict__ tokens, const int* __restrict__ lengths)
{
    int i = blockIdx.x * blockDim.x + threadIdx.x;
    if (i >= BT) return;
    int b = i >> 9, t = i & 511;
    g_tok2[i] = tokens[i];
    int rt = lengths[b] - 1 - t;
    if (rt < 0) rt = 0;
    g_tok2[BT + i] = tokens[(b << 9) + rt];
    g_scores[i] = 0.f;
    ((uint2*)g_hbh)[i] = make_uint2(0u, 0u);
    if (i < 1024) g_tdone[i] = 0;
}

// ---------------------------------------------------------------- conv kernels
__global__ void k_convX(const float* __restrict__ emb)
{
    size_t idx = (size_t)blockIdx.x * 256 + threadIdx.x;
    size_t e = idx * 4;
    size_t row = e >> 9;
    int k = (int)(e & 511);
    int tok = g_tok2[row];
    float4 v = *(const float4*)(emb + (size_t)tok * 512 + k);
    __half2* ph = (__half2*)(g_Xh + row * 512 + k);
    ph[0] = __half2{__float2half_rn(v.x), __float2half_rn(v.y)};
    ph[1] = __half2{__float2half_rn(v.z), __float2half_rn(v.w)};
}

__global__ void k_convW(const float* __restrict__ Wf, const float* __restrict__ Wb)
{
    size_t idx = (size_t)blockIdx.x * 256 + threadIdx.x;
    size_t e = idx * 4;
    size_t row = e >> 9;
    int k = (int)(e & 511);
    int d = (int)(row >= 1536);
    size_t n = row - (size_t)d * 1536;
    const float* W = d ? Wb : Wf;
    float4 v = *(const float4*)(W + n * 512 + k);
    __half2* ph = (__half2*)(g_Wh + row * 512 + k);
    ph[0] = __half2{__float2half_rn(v.x), __float2half_rn(v.y)};
    ph[1] = __half2{__float2half_rn(v.z), __float2half_rn(v.w)};
}

__global__ void k_convP(const float* __restrict__ Wp)
{
    size_t idx = (size_t)blockIdx.x * 256 + threadIdx.x;
    size_t e = idx * 4;
    float4 v = *(const float4*)(Wp + e);
    __half2* ph = (__half2*)(g_Wph + e);
    ph[0] = __half2{__float2half_rn(v.x), __float2half_rn(v.y)};
    ph[1] = __half2{__float2half_rn(v.z), __float2half_rn(v.w)};
}

// ---------------------------------------------------------------- fused kernel smem layout
#define F_WH   0        // 48 rows x 1040 B = 49920
#define F_H    49920    // 3 bufs x 17408
#define F_GATE 102144   // 64 x 52 fp32 = 13312
#define F_PROD 115456   // 2 bufs x 15360 (A 128x80 + B 64x80)
#define F_SMEM 146176
extern __shared__ char smf[];

__device__ __forceinline__ void k2_stage(uint32_t dsth, size_t hsrc, int kc, int tid)
{
    #pragma unroll
    for (int j = 0; j < 4; j++) {
        int L = tid + j * 256;
        int row = L >> 4, q = L & 15;
        cp16(dsth + row * 272 + q * 16,
             (const char*)(g_hbh + hsrc + (size_t)row * 512 + kc) + q * 16);
    }
    cp_commit();
}

__device__ __forceinline__ void prod_stage(uint32_t buf, const __half* Xb, int t,
                                           const __half* Wh, int k0, int ptid)
{
    #pragma unroll
    for (int j = 0; j < 6; j++) {
        int L = ptid + j * 128;          // 0..767
        if (L < 512) {                   // A: 128 b-rows x 4 q
            int b = L >> 2, q = L & 3;
            cp16(buf + b * 80 + q * 16,
                 (const char*)(Xb + ((size_t)b * 512 + t) * 512 + k0) + q * 16);
        } else {                         // B: 64 rows x 4 q
            int r = L - 512;
            int row = r >> 2, q = r & 3;
            cp16(buf + 10240 + row * 80 + q * 16,
                 (const char*)(Wh + (size_t)row * 512 + k0) + q * 16);
        }
    }
    cp_commit();
}

// ---------------------------------------------------------------- fused: producer warps (K1) + recurrence warps (K2)
__global__ void __launch_bounds__(384, 1) k_fused(
    const float* __restrict__ Whh_f, const float* __restrict__ bhh_f,
    const float* __restrict__ Whh_b, const float* __restrict__ bhh_b,
    const int*   __restrict__ lengths,
    const float* __restrict__ bihf, const float* __restrict__ bihb)
{
    uint32_t sb = smem_u32(smf);
    int tid = threadIdx.x, wid = tid >> 5, lane = tid & 31;
    int cid = blockIdx.x;

    if (wid < 8) {
        // ======================= recurrence (threads 0..255) =======================
        int d = cid >> 6, bg = (cid >> 5) & 1, ng = cid & 31;
        int gid = d * 2 + bg;
        const float* Whh = d ? Whh_b : Whh_f;
        const float* bhh = d ? bhh_b : bhh_f;

        for (int i = tid; i < 48 * 128; i += 256) {
            int row = i >> 7, k4 = (i & 127) << 2;
            int g = row >> 4, ul = row & 15;
            float4 w = *(const float4*)(Whh + (size_t)(g * 512 + ng * 16 + ul) * 512 + k4);
            char* ph = smf + F_WH + row * 1040 + k4 * 2;
            *(__half2*)ph       = __half2{__float2half_rn(w.x), __float2half_rn(w.y)};
            *(__half2*)(ph + 4) = __half2{__float2half_rn(w.z), __float2half_rn(w.w)};
        }

        int b_loc  = tid >> 2;
        int u0     = (tid & 3) * 4;
        int b_glob = bg * 64 + b_loc;
        int len_b  = lengths[b_glob];
        float bh_r[4], bh_z[4], bh_n[4];
        #pragma unroll
        for (int j = 0; j < 4; j++) {
            int u = ng * 16 + u0 + j;
            bh_r[j] = bhh[u]; bh_z[j] = bhh[512 + u]; bh_n[j] = bhh[1024 + u];
        }
        float hprev[4] = {0.f, 0.f, 0.f, 0.f};

        int m0  = (wid & 3) * 16;
        int n0w = (wid >> 2) * 24;
        uint32_t aoffA  = (uint32_t)((m0 + (lane & 15)) * 272 + ((lane >> 4) & 1) * 16);
        uint32_t aoffB4 = (uint32_t)((n0w + (lane & 7) + ((lane >> 4) & 1) * 8) * 1040 + ((lane >> 3) & 1) * 16);
        uint32_t aoffB2 = (uint32_t)((n0w + 16 + (lane & 7)) * 1040 + ((lane >> 3) & 1) * 16);

        float* gsm = (float*)(smf + F_GATE);
        NB_REC();

        for (int t = 0; t < 512; t++) {
            int ph = t & 1;
            // wait for producer to finish this t-slice
            if (tid == 0) {
                while (*(volatile int*)&g_tdone[d * 512 + t] < 24) { }
            }
            NB_REC();
            const __half* gp = g_G + (((size_t)d * 512 + t) * 128 + b_glob) * H3 + ng * 16 + u0;
            uint2 vir = __ldcg((const uint2*)gp);
            uint2 viz = __ldcg((const uint2*)(gp + 512));
            uint2 vin = __ldcg((const uint2*)(gp + 1024));

            size_t hsrc = ((size_t)(ph * 2 + d) * 128 + bg * 64) * 512;
            k2_stage(sb + F_H,         hsrc, 0,   tid);
            k2_stage(sb + F_H + 17408, hsrc, 128, tid);

            float acc[3][4];
            #pragma unroll
            for (int n = 0; n < 3; n++)
                #pragma unroll
                for (int r = 0; r < 4; r++) acc[n][r] = 0.f;

            for (int c = 0; c < 4; c++) {
                if (c < 3) asm volatile("cp.async.wait_group 1;" ::: "memory");
                else       asm volatile("cp.async.wait_group 0;" ::: "memory");
                NB_REC();
                if (c + 2 < 4)
                    k2_stage(sb + F_H + ((c + 2) % 3) * 17408, hsrc, (c + 2) * 128, tid);
                uint32_t hb_hi = sb + F_H + (c % 3) * 17408;
                #pragma unroll
                for (int kt = 0; kt < 8; kt++) {
                    uint32_t koffH = kt * 32;
                    uint32_t koffW = (uint32_t)(c * 128 + kt * 16) * 2;
                    uint32_t ah[4], bh4[4], b2h[2];
                    ldsm4(ah, hb_hi + aoffA + koffH);
                    ldsm4(bh4, sb + F_WH + aoffB4 + koffW);
                    ldsm2(b2h, sb + F_WH + aoffB2 + koffW);
                    mma16816(acc[0], ah, bh4[0], bh4[1]);
                    mma16816(acc[1], ah, bh4[2], bh4[3]);
                    mma16816(acc[2], ah, b2h[0], b2h[1]);
                }
            }

            int grow = m0 + (lane >> 2);
            #pragma unroll
            for (int j = 0; j < 3; j++) {
                int col = n0w + j * 8 + (lane & 3) * 2;
                gsm[grow * 52 + col]           = acc[j][0];
                gsm[grow * 52 + col + 1]       = acc[j][1];
                gsm[(grow + 8) * 52 + col]     = acc[j][2];
                gsm[(grow + 8) * 52 + col + 1] = acc[j][3];
            }
            NB_REC();

            float gi_r[4], gi_z[4], gi_n[4];
            {
                __half2 h0 = *(__half2*)&vir.x, h1 = *(__half2*)&vir.y;
                float2 f0 = __half22float2(h0), f1 = __half22float2(h1);
                gi_r[0] = f0.x; gi_r[1] = f0.y; gi_r[2] = f1.x; gi_r[3] = f1.y;
                h0 = *(__half2*)&viz.x; h1 = *(__half2*)&viz.y;
                f0 = __half22float2(h0); f1 = __half22float2(h1);
                gi_z[0] = f0.x; gi_z[1] = f0.y; gi_z[2] = f1.x; gi_z[3] = f1.y;
                h0 = *(__half2*)&vin.x; h1 = *(__half2*)&vin.y;
                f0 = __half22float2(h0); f1 = __half22float2(h1);
                gi_n[0] = f0.x; gi_n[1] = f0.y; gi_n[2] = f1.x; gi_n[3] = f1.y;
            }
            bool m = (t < len_b);
            size_t hwb = ((size_t)((ph ^ 1) * 2 + d) * 128 + b_glob) * 512 + ng * 16;
            int orow = (d == 0) ? t : (m ? (len_b - 1 - t) : t);
            size_t ob = ((size_t)b_glob * 512 + orow) * 1024 + d * 512 + ng * 16;

            float hm[4], ov[4];
            #pragma unroll
            for (int j = 0; j < 4; j++) {
                int u = u0 + j;
                float ar = gsm[b_loc * 52 + u];
                float az = gsm[b_loc * 52 + 16 + u];
                float an = gsm[b_loc * 52 + 32 + u];
                float rr = 1.f / (1.f + expf(-(gi_r[j] + ar + bh_r[j])));
                float zz = 1.f / (1.f + expf(-(gi_z[j] + az + bh_z[j])));
                float nn = tanhf(gi_n[j] + rr * (an + bh_n[j]));
                float hn = (1.f - zz) * nn + zz * hprev[j];
                hm[j] = m ? hn : hprev[j];
                hprev[j] = hm[j];
                ov[j] = m ? hn : 0.f;
            }
            *(__half2*)(g_hbh + hwb + u0)     = __half2{__float2half_rn(hm[0]), __float2half_rn(hm[1])};
            *(__half2*)(g_hbh + hwb + u0 + 2) = __half2{__float2half_rn(hm[2]), __float2half_rn(hm[3])};
            *(float4*)(g_out + ob + u0) = make_float4(ov[0], ov[1], ov[2], ov[3]);
            *(__half2*)(g_outh + ob + u0)     = __half2{__float2half_rn(ov[0]), __float2half_rn(ov[1])};
            *(__half2*)(g_outh + ob + u0 + 2) = __half2{__float2half_rn(ov[2]), __float2half_rn(ov[3])};

            // group barrier (named-barrier version)
            NB_REC();
            if (tid == 0) {
                __threadfence();
                unsigned a = atomicAdd(&g_cnt4[gid], 1u) + 1u;
                if (a == (unsigned)(t + 1) * 32u) {
                    atomicAdd(&g_gen4[gid], 1u);
                } else {
                    while (*(volatile unsigned*)&g_gen4[gid] < (unsigned)(t + 1)) { }
                }
                __threadfence();
            }
            NB_REC();
        }

        if (tid == 0) {
            unsigned old = atomicAdd(&g_done, 1u);
            if (old == NCTA - 1) {
                #pragma unroll
                for (int g = 0; g < 4; g++) { g_cnt4[g] = 0; g_gen4[g] = 0; }
                g_done = 0;
                __threadfence();
            }
        }
    } else {
        // ======================= producer warps (threads 256..383) =======================
        int pw = wid - 8;          // 0..3
        int ptid = tid - 256;      // 0..127
        int wmP = (pw & 1) * 64;
        int wnP = (pw >> 1) * 32;
        int arow = (lane & 15);
        int ahk  = ((lane >> 4) & 1) * 16;
        int brow = (lane & 7) + ((lane >> 4) & 1) * 8;
        int bhk  = ((lane >> 3) & 1) * 16;

        for (int T = cid; T < 24576; T += 128) {
            int t  = T / 48;
            int r  = T % 48;
            int dd = r / 24;
            int nb = (r % 24) * 64;
            const __half* Xb = g_Xh + (size_t)dd * BT * 512;
            const __half* Wh = g_Wh + (size_t)(dd * 1536 + nb) * 512;
            const float* bias = (dd ? bihb : bihf) + nb;

            float acc[4][4][4];
            #pragma unroll
            for (int f = 0; f < 4; f++)
                #pragma unroll
                for (int n = 0; n < 4; n++)
                    #pragma unroll
                    for (int q = 0; q < 4; q++) acc[f][n][q] = 0.f;

            prod_stage(sb + F_PROD,         Xb, t, Wh, 0,  ptid);
            prod_stage(sb + F_PROD + 15360, Xb, t, Wh, 32, ptid);

            for (int c = 0; c < 16; c++) {
                if (c < 15) asm volatile("cp.async.wait_group 1;" ::: "memory");
                else        asm volatile("cp.async.wait_group 0;" ::: "memory");
                NB_PROD();
                uint32_t base = sb + F_PROD + (c & 1) * 15360;
                uint32_t aA = base +         (wmP + arow) * 80 + ahk;
                uint32_t aB = base + 10240 + (wnP + brow) * 80 + bhk;
                #pragma unroll
                for (int s = 0; s < 2; s++) {
                    uint32_t ah[4][4], bh[2][4];
                    #pragma unroll
                    for (int f = 0; f < 4; f++)
                        ldsm4(ah[f], aA + f * 16 * 80 + s * 32);
                    #pragma unroll
                    for (int g = 0; g < 2; g++)
                        ldsm4(bh[g], aB + g * 16 * 80 + s * 32);
                    #pragma unroll
                    for (int f = 0; f < 4; f++)
                        #pragma unroll
                        for (int n = 0; n < 4; n++)
                            mma16816(acc[f][n], ah[f], bh[n >> 1][(n & 1) * 2], bh[n >> 1][(n & 1) * 2 + 1]);
                }
                NB_PROD();
                if (c + 2 < 16)
                    prod_stage(base, Xb, t, Wh, (c + 2) * 32, ptid);
            }

            // epilogue: bias + fp16 store to t-major G
            #pragma unroll
            for (int f = 0; f < 4; f++) {
                int b = wmP + f * 16 + (lane >> 2);
                __half* gp0 = g_G + (((size_t)dd * 512 + t) * 128 + b) * H3 + nb;
                __half* gp1 = gp0 + (size_t)8 * H3;
                #pragma unroll
                for (int n = 0; n < 4; n++) {
                    int col = wnP + n * 8 + (lane & 3) * 2;
                    float b0 = __ldg(bias + col), b1 = __ldg(bias + col + 1);
                    *(__half2*)(gp0 + col) = __half2{__float2half_rn(acc[f][n][0] + b0),
                                                     __float2half_rn(acc[f][n][1] + b1)};
                    *(__half2*)(gp1 + col) = __half2{__float2half_rn(acc[f][n][2] + b0),
                                                     __float2half_rn(acc[f][n][3] + b1)};
                }
            }
            NB_PROD();
            if (ptid == 0) {
                __threadfence();
                atomicAdd(&g_tdone[dd * 512 + t], 1);
            }
        }
    }
}

// ---------------------------------------------------------------- K3: fp16 1-pass proj + fused ctx-dot (256x128)
#define TB2 30720
#define SMEM_TC2 (2 * TB2)
extern __shared__ char sm_tc[];

__device__ __forceinline__ void issue_chunk2(
    uint32_t sbase, const __half* Ah, const __half* Bh, int k0, int tid, int ldk)
{
    #pragma unroll
    for (int j = 0; j < 3; j++) {
        int L = tid + j * 512;
        if (L < 1024) {
            int row = L >> 2, q = L & 3;
            cp16(sbase + row * 80 + q * 16,
                 (const char*)(Ah + (size_t)row * ldk + k0) + q * 16);
        } else {
            int r = L - 1024;
            int row = r >> 2, q = r & 3;
            cp16(sbase + 20480 + row * 80 + q * 16,
                 (const char*)(Bh + (size_t)row * ldk + k0) + q * 16);
        }
    }
    cp_commit();
}

__global__ void __launch_bounds__(512) k_gemm_proj_tc(
    const float* __restrict__ bp, const float* __restrict__ ctx)
{
    uint32_t sb = smem_u32(sm_tc);
    int tid = threadIdx.x, wid = tid >> 5, lane = tid & 31;
    int mb = blockIdx.y * 256, nb = blockIdx.x * 128;

    const __half* Ah = g_outh + (size_t)mb * 1024;
    const __half* Bh = g_Wph + (size_t)nb * 1024;

    int wm = (wid & 3) * 64;
    int wn = (wid >> 2) * 32;

    float acc[4][4][4];
    #pragma unroll
    for (int f = 0; f < 4; f++)
        #pragma unroll
        for (int n = 0; n < 4; n++)
            #pragma unroll
            for (int r = 0; r < 4; r++) acc[f][n][r] = 0.f;

    issue_chunk2(sb,       Ah, Bh, 0,  tid, 1024);
    issue_chunk2(sb + TB2, Ah, Bh, 32, tid, 1024);

    int arow = (lane & 15);
    int ahk  = ((lane >> 4) & 1) * 16;
    int brow = (lane & 7) + ((lane >> 4) & 1) * 8;
    int bhk  = ((lane >> 3) & 1) * 16;

    for (int c = 0; c < 32; c++) {
        if (c < 31) asm volatile("cp.async.wait_group 1;" ::: "memory");
        else        asm volatile("cp.async.wait_group 0;" ::: "memory");
        __syncthreads();
        uint32_t base = sb + (c & 1) * TB2;
        uint32_t aA = base +         (wm + arow) * 80 + ahk;
        uint32_t aB = base + 20480 + (wn + brow) * 80 + bhk;

        #pragma unroll
        for (int s = 0; s < 2; s++) {
            uint32_t ah[4][4], bh[2][4];
            #pragma unroll
            for (int f = 0; f < 4; f++)
                ldsm4(ah[f], aA + f * 16 * 80 + s * 32);
            #pragma unroll
            for (int g = 0; g < 2; g++)
                ldsm4(bh[g], aB + g * 16 * 80 + s * 32);
            #pragma unroll
            for (int f = 0; f < 4; f++)
                #pragma unroll
                for (int n = 0; n < 4; n++)
                    mma16816(acc[f][n], ah[f], bh[n >> 1][(n & 1) * 2], bh[n >> 1][(n & 1) * 2 + 1]);
        }
        __syncthreads();
        if (c + 2 < 32)
            issue_chunk2(sb + (c & 1) * TB2, Ah, Bh, (c + 2) * 32, tid, 1024);
    }

    #pragma unroll
    for (int f = 0; f < 4; f++) {
        int r0 = mb + wm + f * 16 + (lane >> 2);
        float p0 = 0.f, p1 = 0.f;
        #pragma unroll
        for (int n = 0; n < 4; n++) {
            int col = nb + wn + n * 8 + (lane & 3) * 2;
            float c0 = __ldg(ctx + col), c1 = __ldg(ctx + col + 1);
            float b0 = __ldg(bp + col),  b1 = __ldg(bp + col + 1);
            p0 += tanhf(acc[f][n][0] + b0) * c0 + tanhf(acc[f][n][1] + b1) * c1;
            p1 += tanhf(acc[f][n][2] + b0) * c0 + tanhf(acc[f][n][3] + b1) * c1;
        }
        p0 += __shfl_xor_sync(0xffffffffu, p0, 1);
        p0 += __shfl_xor_sync(0xffffffffu, p0, 2);
        p1 += __shfl_xor_sync(0xffffffffu, p1, 1);
        p1 += __shfl_xor_sync(0xffffffffu, p1, 2);
        if ((lane & 3) == 0) {
            atomicAdd(&g_scores[r0], p0);
            atomicAdd(&g_scores[r0 + 8], p1);
        }
    }
}

// ---------------------------------------------------------------- K4: softmax + pooling + SELU + logits
__global__ void __launch_bounds__(512) k_final(
    const int* __restrict__ lengths,
    const float* __restrict__ Wl, const float* __restrict__ bl,
    float* __restrict__ out, int out_size)
{
    __shared__ float sh[512];
    __shared__ float attn[512];
    __shared__ float lg[2];
    int b = blockIdx.x, tid = threadIdx.x;
    int len = lengths[b];
    float s = (tid < len) ? g_scores[b * 512 + tid] : -1e30f;
    sh[tid] = s; __syncthreads();
    for (int o = 256; o > 0; o >>= 1) { if (tid < o) sh[tid] = fmaxf(sh[tid], sh[tid + o]); __syncthreads(); }
    float mx = sh[0]; __syncthreads();
    float e = (tid < len) ? expf(s - mx) : 0.f;
    sh[tid] = e; __syncthreads();
    for (int o = 256; o > 0; o >>= 1) { if (tid < o) sh[tid] += sh[tid + o]; __syncthreads(); }
    float a = e / sh[0];
    attn[tid] = a;
    int attn_ofs = (out_size >= 65792) ? 256 : 0;
    if (out_size != 256) out[attn_ofs + b * 512 + tid] = a;
    if (tid == 0) { lg[0] = 0.f; lg[1] = 0.f; }
    __syncthreads();

    const float* ob = g_out + (long)b * 512 * 1024;
    float s0 = 0.f, s1 = 0.f;
    for (int t = 0; t < 512; t++) {
        float at = attn[t];
        s0 = fmaf(at, ob[(long)t * 1024 + tid],       s0);
        s1 = fmaf(at, ob[(long)t * 1024 + 512 + tid], s1);
    }
    const float SC = 1.0507009873554805f, AL = 1.6732632423543772f;
    s0 = (s0 > 0.f) ? SC * s0 : SC * AL * (expf(s0) - 1.f);
    s1 = (s1 > 0.f) ? SC * s1 : SC * AL * (expf(s1) - 1.f);
    float p0 = s0 * Wl[tid]        + s1 * Wl[512 + tid];
    float p1 = s0 * Wl[1024 + tid] + s1 * Wl[1536 + tid];
    #pragma unroll
    for (int o = 16; o > 0; o >>= 1) {
        p0 += __shfl_xor_sync(0xffffffffu, p0, o);
        p1 += __shfl_xor_sync(0xffffffffu, p1, o);
    }
    if ((tid & 31) == 0) { atomicAdd(&lg[0], p0); atomicAdd(&lg[1], p1); }
    __syncthreads();
    if (tid < 2 && out_size != 65536) out[b * 2 + tid] = lg[tid] + bl[tid];
}

// ---------------------------------------------------------------- launch
extern "C" void kernel_launch(void* const* d_in, const int* in_sizes, int n_in,
                              void* d_out, int out_size)
{
    const int*   tokens  = (const int*)d_in[0];
    const int*   lengths = (const int*)d_in[1];
    const float* emb     = (const float*)d_in[2];
    const float* Wih_f   = (const float*)d_in[3];
    const float* Whh_f   = (const float*)d_in[4];
    const float* bih_f   = (const float*)d_in[5];
    const float* bhh_f   = (const float*)d_in[6];
    const float* Wih_b   = (const float*)d_in[7];
    const float* Whh_b   = (const float*)d_in[8];
    const float* bih_b   = (const float*)d_in[9];
    const float* bhh_b   = (const float*)d_in[10];
    const float* Wp      = (const float*)d_in[11];
    const float* bp      = (const float*)d_in[12];
    const float* ctx     = (const float*)d_in[13];
    const float* Wl      = (const float*)d_in[14];
    const float* bl      = (const float*)d_in[15];
    float* out = (float*)d_out;

    k_init<<<BT / 256, 256>>>(tokens, lengths);
    k_convW<<<1536, 256>>>(Wih_f, Wih_b);
    k_convX<<<65536, 256>>>(emb);
    k_convP<<<512, 256>>>(Wp);

    cudaFuncSetAttribute(k_fused, cudaFuncAttributeMaxDynamicSharedMemorySize, F_SMEM);
    k_fused<<<NCTA, 384, F_SMEM>>>(Whh_f, bhh_f, Whh_b, bhh_b, lengths, bih_f, bih_b);

    cudaFuncSetAttribute(k_gemm_proj_tc, cudaFuncAttributeMaxDynamicSharedMemorySize, SMEM_TC2);
    dim3 g3(4, 256);
    k_gemm_proj_tc<<<g3, 512, SMEM_TC2>>>(bp, ctx);

    k_final<<<Bsz, 512>>>(lengths, Wl, bl, out, out_size);
}

// round 14
// speedup vs baseline: 1.9260x; 1.0397x over previous
#include <cuda_runtime.h>
#include <cuda_fp16.h>
#include <math.h>
#include <stdint.h>

#define Bsz 128
#define Tt  512
#define H3  1536
#define BT  65536
#define NCTA 128

__device__ __half g_G[201326592];   // [d][t][b][1536] fp16 gate preactivations (t-major)
__device__ __half g_outh[67108864]; // [b][t][1024] fp16 out (K3 A-side + K4)
__device__ float g_scores[65536];
__device__ int   g_tok2[131072];
__device__ int   g_tdone[1024];     // [d][t] completed tiles (12 = ready)
__device__ unsigned g_cnt4[4], g_gen4[4], g_done;

__device__ __half g_Xh[67108864];   // [2*BT][512]
__device__ __half g_Wh[1572864];    // [2][1536][512]
__device__ __half g_Wph[524288];    // [512][1024]
__device__ __half g_hbh[262144];    // [ph][d][128][512]

// ---------------------------------------------------------------- helpers
__device__ __forceinline__ uint32_t smem_u32(const void* p)
{
    uint32_t a;
    asm("{ .reg .u64 t; cvta.to.shared.u64 t, %1; cvt.u32.u64 %0, t; }" : "=r"(a) : "l"(p));
    return a;
}
__device__ __forceinline__ void cp16(uint32_t dst, const void* src)
{
    asm volatile("cp.async.cg.shared.global [%0], [%1], 16;" :: "r"(dst), "l"(src) : "memory");
}
__device__ __forceinline__ void cp_commit()
{
    asm volatile("cp.async.commit_group;" ::: "memory");
}
__device__ __forceinline__ void ldsm4(uint32_t* r, uint32_t addr)
{
    asm volatile("ldmatrix.sync.aligned.m8n8.x4.shared.b16 {%0,%1,%2,%3}, [%4];"
                 : "=r"(r[0]), "=r"(r[1]), "=r"(r[2]), "=r"(r[3]) : "r"(addr));
}
__device__ __forceinline__ void ldsm2(uint32_t* r, uint32_t addr)
{
    asm volatile("ldmatrix.sync.aligned.m8n8.x2.shared.b16 {%0,%1}, [%2];"
                 : "=r"(r[0]), "=r"(r[1]) : "r"(addr));
}
__device__ __forceinline__ void mma16816(float* c, const uint32_t* a, uint32_t b0, uint32_t b1)
{
    asm volatile("mma.sync.aligned.m16n8k16.row.col.f32.f16.f16.f32 "
                 "{%0,%1,%2,%3}, {%4,%5,%6,%7}, {%8,%9}, {%0,%1,%2,%3};"
                 : "+f"(c[0]), "+f"(c[1]), "+f"(c[2]), "+f"(c[3])
                 : "r"(a[0]), "r"(a[1]), "r"(a[2]), "r"(a[3]), "r"(b0), "r"(b1));
}
#define NB_REC()  asm volatile("bar.sync 1, 256;" ::: "memory")
#define NB_PROD() asm volatile("bar.sync 2, 256;" ::: "memory")

// ---------------------------------------------------------------- K0
__global__ void k_init(const int* __restrict__ tokens, const int* __restrict__ lengths)
{
    int i = blockIdx.x * blockDim.x + threadIdx.x;
    if (i >= BT) return;
    int b = i >> 9, t = i & 511;
    g_tok2[i] = tokens[i];
    int rt = lengths[b] - 1 - t;
    if (rt < 0) rt = 0;
    g_tok2[BT + i] = tokens[(b << 9) + rt];
    g_scores[i] = 0.f;
    ((uint2*)g_hbh)[i] = make_uint2(0u, 0u);
    if (i < 1024) g_tdone[i] = 0;
}

// ---------------------------------------------------------------- conv kernels
__global__ void k_convX(const float* __restrict__ emb)
{
    size_t idx = (size_t)blockIdx.x * 256 + threadIdx.x;
    size_t e = idx * 4;
    size_t row = e >> 9;
    int k = (int)(e & 511);
    int tok = g_tok2[row];
    float4 v = *(const float4*)(emb + (size_t)tok * 512 + k);
    __half2* ph = (__half2*)(g_Xh + row * 512 + k);
    ph[0] = __half2{__float2half_rn(v.x), __float2half_rn(v.y)};
    ph[1] = __half2{__float2half_rn(v.z), __float2half_rn(v.w)};
}

__global__ void k_convW(const float* __restrict__ Wf, const float* __restrict__ Wb)
{
    size_t idx = (size_t)blockIdx.x * 256 + threadIdx.x;
    size_t e = idx * 4;
    size_t row = e >> 9;
    int k = (int)(e & 511);
    int d = (int)(row >= 1536);
    size_t n = row - (size_t)d * 1536;
    const float* W = d ? Wb : Wf;
    float4 v = *(const float4*)(W + n * 512 + k);
    __half2* ph = (__half2*)(g_Wh + row * 512 + k);
    ph[0] = __half2{__float2half_rn(v.x), __float2half_rn(v.y)};
    ph[1] = __half2{__float2half_rn(v.z), __float2half_rn(v.w)};
}

__global__ void k_convP(const float* __restrict__ Wp)
{
    size_t idx = (size_t)blockIdx.x * 256 + threadIdx.x;
    size_t e = idx * 4;
    float4 v = *(const float4*)(Wp + e);
    __half2* ph = (__half2*)(g_Wph + e);
    ph[0] = __half2{__float2half_rn(v.x), __float2half_rn(v.y)};
    ph[1] = __half2{__float2half_rn(v.z), __float2half_rn(v.w)};
}

// ---------------------------------------------------------------- fused kernel smem layout
#define F_WH   0        // 48 rows x 1040 B = 49920
#define F_H    49920    // 3 bufs x 17408
#define F_GATE 102144   // 64 x 52 fp32 = 13312
#define F_PROD 115456   // 2 bufs x 20480 (A 128x80 + B 128x80)
#define F_SMEM 156416
extern __shared__ char smf[];

__device__ __forceinline__ void k2_stage(uint32_t dsth, size_t hsrc, int kc, int tid)
{
    #pragma unroll
    for (int j = 0; j < 4; j++) {
        int L = tid + j * 256;
        int row = L >> 4, q = L & 15;
        cp16(dsth + row * 272 + q * 16,
             (const char*)(g_hbh + hsrc + (size_t)row * 512 + kc) + q * 16);
    }
    cp_commit();
}

__device__ __forceinline__ void prod_stage(uint32_t buf, const __half* Xb, int t,
                                           const __half* Wh, int k0, int ptid)
{
    #pragma unroll
    for (int j = 0; j < 4; j++) {
        int L = ptid + j * 256;          // 0..1023
        if (L < 512) {                   // A: 128 b-rows x 4 q
            int b = L >> 2, q = L & 3;
            cp16(buf + b * 80 + q * 16,
                 (const char*)(Xb + ((size_t)b * 512 + t) * 512 + k0) + q * 16);
        } else {                         // B: 128 rows x 4 q
            int r = L - 512;
            int row = r >> 2, q = r & 3;
            cp16(buf + 10240 + row * 80 + q * 16,
                 (const char*)(Wh + (size_t)row * 512 + k0) + q * 16);
        }
    }
    cp_commit();
}

// ---------------------------------------------------------------- fused: 8 producer warps + 8 recurrence warps
__global__ void __launch_bounds__(512, 1) k_fused(
    const float* __restrict__ Whh_f, const float* __restrict__ bhh_f,
    const float* __restrict__ Whh_b, const float* __restrict__ bhh_b,
    const int*   __restrict__ lengths,
    const float* __restrict__ bihf, const float* __restrict__ bihb)
{
    uint32_t sb = smem_u32(smf);
    int tid = threadIdx.x, wid = tid >> 5, lane = tid & 31;
    int cid = blockIdx.x;

    if (wid < 8) {
        // ======================= recurrence (threads 0..255) =======================
        int d = cid >> 6, bg = (cid >> 5) & 1, ng = cid & 31;
        int gid = d * 2 + bg;
        const float* Whh = d ? Whh_b : Whh_f;
        const float* bhh = d ? bhh_b : bhh_f;

        for (int i = tid; i < 48 * 128; i += 256) {
            int row = i >> 7, k4 = (i & 127) << 2;
            int g = row >> 4, ul = row & 15;
            float4 w = *(const float4*)(Whh + (size_t)(g * 512 + ng * 16 + ul) * 512 + k4);
            char* ph = smf + F_WH + row * 1040 + k4 * 2;
            *(__half2*)ph       = __half2{__float2half_rn(w.x), __float2half_rn(w.y)};
            *(__half2*)(ph + 4) = __half2{__float2half_rn(w.z), __float2half_rn(w.w)};
        }

        int b_loc  = tid >> 2;
        int u0     = (tid & 3) * 4;
        int b_glob = bg * 64 + b_loc;
        int len_b  = lengths[b_glob];
        float bh_r[4], bh_z[4], bh_n[4];
        #pragma unroll
        for (int j = 0; j < 4; j++) {
            int u = ng * 16 + u0 + j;
            bh_r[j] = bhh[u]; bh_z[j] = bhh[512 + u]; bh_n[j] = bhh[1024 + u];
        }
        float hprev[4] = {0.f, 0.f, 0.f, 0.f};

        int m0  = (wid & 3) * 16;
        int n0w = (wid >> 2) * 24;
        uint32_t aoffA  = (uint32_t)((m0 + (lane & 15)) * 272 + ((lane >> 4) & 1) * 16);
        uint32_t aoffB4 = (uint32_t)((n0w + (lane & 7) + ((lane >> 4) & 1) * 8) * 1040 + ((lane >> 3) & 1) * 16);
        uint32_t aoffB2 = (uint32_t)((n0w + 16 + (lane & 7)) * 1040 + ((lane >> 3) & 1) * 16);

        float* gsm = (float*)(smf + F_GATE);
        NB_REC();

        for (int t = 0; t < 512; t++) {
            int ph = t & 1;
            if (tid == 0) {
                while (*(volatile int*)&g_tdone[d * 512 + t] < 12) { }
            }
            NB_REC();
            const __half* gp = g_G + (((size_t)d * 512 + t) * 128 + b_glob) * H3 + ng * 16 + u0;
            uint2 vir = __ldcg((const uint2*)gp);
            uint2 viz = __ldcg((const uint2*)(gp + 512));
            uint2 vin = __ldcg((const uint2*)(gp + 1024));

            size_t hsrc = ((size_t)(ph * 2 + d) * 128 + bg * 64) * 512;
            k2_stage(sb + F_H,         hsrc, 0,   tid);
            k2_stage(sb + F_H + 17408, hsrc, 128, tid);

            float acc[3][4];
            #pragma unroll
            for (int n = 0; n < 3; n++)
                #pragma unroll
                for (int r = 0; r < 4; r++) acc[n][r] = 0.f;

            for (int c = 0; c < 4; c++) {
                if (c < 3) asm volatile("cp.async.wait_group 1;" ::: "memory");
                else       asm volatile("cp.async.wait_group 0;" ::: "memory");
                NB_REC();
                if (c + 2 < 4)
                    k2_stage(sb + F_H + ((c + 2) % 3) * 17408, hsrc, (c + 2) * 128, tid);
                uint32_t hb_hi = sb + F_H + (c % 3) * 17408;
                #pragma unroll
                for (int kt = 0; kt < 8; kt++) {
                    uint32_t koffH = kt * 32;
                    uint32_t koffW = (uint32_t)(c * 128 + kt * 16) * 2;
                    uint32_t ah[4], bh4[4], b2h[2];
                    ldsm4(ah, hb_hi + aoffA + koffH);
                    ldsm4(bh4, sb + F_WH + aoffB4 + koffW);
                    ldsm2(b2h, sb + F_WH + aoffB2 + koffW);
                    mma16816(acc[0], ah, bh4[0], bh4[1]);
                    mma16816(acc[1], ah, bh4[2], bh4[3]);
                    mma16816(acc[2], ah, b2h[0], b2h[1]);
                }
            }

            int grow = m0 + (lane >> 2);
            #pragma unroll
            for (int j = 0; j < 3; j++) {
                int col = n0w + j * 8 + (lane & 3) * 2;
                gsm[grow * 52 + col]           = acc[j][0];
                gsm[grow * 52 + col + 1]       = acc[j][1];
                gsm[(grow + 8) * 52 + col]     = acc[j][2];
                gsm[(grow + 8) * 52 + col + 1] = acc[j][3];
            }
            NB_REC();

            float gi_r[4], gi_z[4], gi_n[4];
            {
                __half2 h0 = *(__half2*)&vir.x, h1 = *(__half2*)&vir.y;
                float2 f0 = __half22float2(h0), f1 = __half22float2(h1);
                gi_r[0] = f0.x; gi_r[1] = f0.y; gi_r[2] = f1.x; gi_r[3] = f1.y;
                h0 = *(__half2*)&viz.x; h1 = *(__half2*)&viz.y;
                f0 = __half22float2(h0); f1 = __half22float2(h1);
                gi_z[0] = f0.x; gi_z[1] = f0.y; gi_z[2] = f1.x; gi_z[3] = f1.y;
                h0 = *(__half2*)&vin.x; h1 = *(__half2*)&vin.y;
                f0 = __half22float2(h0); f1 = __half22float2(h1);
                gi_n[0] = f0.x; gi_n[1] = f0.y; gi_n[2] = f1.x; gi_n[3] = f1.y;
            }
            bool m = (t < len_b);
            size_t hwb = ((size_t)((ph ^ 1) * 2 + d) * 128 + b_glob) * 512 + ng * 16;
            int orow = (d == 0) ? t : (m ? (len_b - 1 - t) : t);
            size_t ob = ((size_t)b_glob * 512 + orow) * 1024 + d * 512 + ng * 16;

            float hm[4], ov[4];
            #pragma unroll
            for (int j = 0; j < 4; j++) {
                int u = u0 + j;
                float ar = gsm[b_loc * 52 + u];
                float az = gsm[b_loc * 52 + 16 + u];
                float an = gsm[b_loc * 52 + 32 + u];
                float rr = 1.f / (1.f + expf(-(gi_r[j] + ar + bh_r[j])));
                float zz = 1.f / (1.f + expf(-(gi_z[j] + az + bh_z[j])));
                float nn = tanhf(gi_n[j] + rr * (an + bh_n[j]));
                float hn = (1.f - zz) * nn + zz * hprev[j];
                hm[j] = m ? hn : hprev[j];
                hprev[j] = hm[j];
                ov[j] = m ? hn : 0.f;
            }
            *(__half2*)(g_hbh + hwb + u0)     = __half2{__float2half_rn(hm[0]), __float2half_rn(hm[1])};
            *(__half2*)(g_hbh + hwb + u0 + 2) = __half2{__float2half_rn(hm[2]), __float2half_rn(hm[3])};
            *(__half2*)(g_outh + ob + u0)     = __half2{__float2half_rn(ov[0]), __float2half_rn(ov[1])};
            *(__half2*)(g_outh + ob + u0 + 2) = __half2{__float2half_rn(ov[2]), __float2half_rn(ov[3])};

            NB_REC();
            if (tid == 0) {
                __threadfence();
                unsigned a = atomicAdd(&g_cnt4[gid], 1u) + 1u;
                if (a == (unsigned)(t + 1) * 32u) {
                    atomicAdd(&g_gen4[gid], 1u);
                } else {
                    while (*(volatile unsigned*)&g_gen4[gid] < (unsigned)(t + 1)) { }
                }
                __threadfence();
            }
            NB_REC();
        }

        if (tid == 0) {
            unsigned old = atomicAdd(&g_done, 1u);
            if (old == NCTA - 1) {
                #pragma unroll
                for (int g = 0; g < 4; g++) { g_cnt4[g] = 0; g_gen4[g] = 0; }
                g_done = 0;
                __threadfence();
            }
        }
    } else {
        // ======================= producer warps (threads 256..511) =======================
        int pw = wid - 8;          // 0..7
        int ptid = tid - 256;      // 0..255
        int wmP = (pw & 1) * 64;
        int wnP = (pw >> 1) * 32;
        int arow = (lane & 15);
        int ahk  = ((lane >> 4) & 1) * 16;
        int brow = (lane & 7) + ((lane >> 4) & 1) * 8;
        int bhk  = ((lane >> 3) & 1) * 16;

        for (int T = cid; T < 12288; T += 128) {
            int t  = T / 24;
            int r  = T % 24;
            int dd = r / 12;
            int nb = (r % 12) * 128;
            const __half* Xb = g_Xh + (size_t)dd * BT * 512;
            const __half* Wh = g_Wh + (size_t)(dd * 1536 + nb) * 512;
            const float* bias = (dd ? bihb : bihf) + nb;

            float acc[4][4][4];
            #pragma unroll
            for (int f = 0; f < 4; f++)
                #pragma unroll
                for (int n = 0; n < 4; n++)
                    #pragma unroll
                    for (int q = 0; q < 4; q++) acc[f][n][q] = 0.f;

            prod_stage(sb + F_PROD,         Xb, t, Wh, 0,  ptid);
            prod_stage(sb + F_PROD + 20480, Xb, t, Wh, 32, ptid);

            for (int c = 0; c < 16; c++) {
                if (c < 15) asm volatile("cp.async.wait_group 1;" ::: "memory");
                else        asm volatile("cp.async.wait_group 0;" ::: "memory");
                NB_PROD();
                uint32_t base = sb + F_PROD + (c & 1) * 20480;
                uint32_t aA = base +         (wmP + arow) * 80 + ahk;
                uint32_t aB = base + 10240 + (wnP + brow) * 80 + bhk;
                #pragma unroll
                for (int s = 0; s < 2; s++) {
                    uint32_t ah[4][4], bh[2][4];
                    #pragma unroll
                    for (int f = 0; f < 4; f++)
                        ldsm4(ah[f], aA + f * 16 * 80 + s * 32);
                    #pragma unroll
                    for (int g = 0; g < 2; g++)
                        ldsm4(bh[g], aB + g * 16 * 80 + s * 32);
                    #pragma unroll
                    for (int f = 0; f < 4; f++)
                        #pragma unroll
                        for (int n = 0; n < 4; n++)
                            mma16816(acc[f][n], ah[f], bh[n >> 1][(n & 1) * 2], bh[n >> 1][(n & 1) * 2 + 1]);
                }
                NB_PROD();
                if (c + 2 < 16)
                    prod_stage(base, Xb, t, Wh, (c + 2) * 32, ptid);
            }

            #pragma unroll
            for (int f = 0; f < 4; f++) {
                int b = wmP + f * 16 + (lane >> 2);
                __half* gp0 = g_G + (((size_t)dd * 512 + t) * 128 + b) * H3 + nb;
                __half* gp1 = gp0 + (size_t)8 * H3;
                #pragma unroll
                for (int n = 0; n < 4; n++) {
                    int col = wnP + n * 8 + (lane & 3) * 2;
                    float b0 = __ldg(bias + col), b1 = __ldg(bias + col + 1);
                    *(__half2*)(gp0 + col) = __half2{__float2half_rn(acc[f][n][0] + b0),
                                                     __float2half_rn(acc[f][n][1] + b1)};
                    *(__half2*)(gp1 + col) = __half2{__float2half_rn(acc[f][n][2] + b0),
                                                     __float2half_rn(acc[f][n][3] + b1)};
                }
            }
            NB_PROD();
            if (ptid == 0) {
                __threadfence();
                atomicAdd(&g_tdone[dd * 512 + t], 1);
            }
        }
    }
}

// ---------------------------------------------------------------- K3: fp16 1-pass proj + fused ctx-dot (256x128)
#define TB2 30720
#define SMEM_TC2 (2 * TB2)
extern __shared__ char sm_tc[];

__device__ __forceinline__ void issue_chunk2(
    uint32_t sbase, const __half* Ah, const __half* Bh, int k0, int tid, int ldk)
{
    #pragma unroll
    for (int j = 0; j < 3; j++) {
        int L = tid + j * 512;
        if (L < 1024) {
            int row = L >> 2, q = L & 3;
            cp16(sbase + row * 80 + q * 16,
                 (const char*)(Ah + (size_t)row * ldk + k0) + q * 16);
        } else {
            int r = L - 1024;
            int row = r >> 2, q = r & 3;
            cp16(sbase + 20480 + row * 80 + q * 16,
                 (const char*)(Bh + (size_t)row * ldk + k0) + q * 16);
        }
    }
    cp_commit();
}

__global__ void __launch_bounds__(512) k_gemm_proj_tc(
    const float* __restrict__ bp, const float* __restrict__ ctx)
{
    uint32_t sb = smem_u32(sm_tc);
    int tid = threadIdx.x, wid = tid >> 5, lane = tid & 31;
    int mb = blockIdx.y * 256, nb = blockIdx.x * 128;

    const __half* Ah = g_outh + (size_t)mb * 1024;
    const __half* Bh = g_Wph + (size_t)nb * 1024;

    int wm = (wid & 3) * 64;
    int wn = (wid >> 2) * 32;

    float acc[4][4][4];
    #pragma unroll
    for (int f = 0; f < 4; f++)
        #pragma unroll
        for (int n = 0; n < 4; n++)
            #pragma unroll
            for (int r = 0; r < 4; r++) acc[f][n][r] = 0.f;

    issue_chunk2(sb,       Ah, Bh, 0,  tid, 1024);
    issue_chunk2(sb + TB2, Ah, Bh, 32, tid, 1024);

    int arow = (lane & 15);
    int ahk  = ((lane >> 4) & 1) * 16;
    int brow = (lane & 7) + ((lane >> 4) & 1) * 8;
    int bhk  = ((lane >> 3) & 1) * 16;

    for (int c = 0; c < 32; c++) {
        if (c < 31) asm volatile("cp.async.wait_group 1;" ::: "memory");
        else        asm volatile("cp.async.wait_group 0;" ::: "memory");
        __syncthreads();
        uint32_t base = sb + (c & 1) * TB2;
        uint32_t aA = base +         (wm + arow) * 80 + ahk;
        uint32_t aB = base + 20480 + (wn + brow) * 80 + bhk;

        #pragma unroll
        for (int s = 0; s < 2; s++) {
            uint32_t ah[4][4], bh[2][4];
            #pragma unroll
            for (int f = 0; f < 4; f++)
                ldsm4(ah[f], aA + f * 16 * 80 + s * 32);
            #pragma unroll
            for (int g = 0; g < 2; g++)
                ldsm4(bh[g], aB + g * 16 * 80 + s * 32);
            #pragma unroll
            for (int f = 0; f < 4; f++)
                #pragma unroll
                for (int n = 0; n < 4; n++)
                    mma16816(acc[f][n], ah[f], bh[n >> 1][(n & 1) * 2], bh[n >> 1][(n & 1) * 2 + 1]);
        }
        __syncthreads();
        if (c + 2 < 32)
            issue_chunk2(sb + (c & 1) * TB2, Ah, Bh, (c + 2) * 32, tid, 1024);
    }

    #pragma unroll
    for (int f = 0; f < 4; f++) {
        int r0 = mb + wm + f * 16 + (lane >> 2);
        float p0 = 0.f, p1 = 0.f;
        #pragma unroll
        for (int n = 0; n < 4; n++) {
            int col = nb + wn + n * 8 + (lane & 3) * 2;
            float c0 = __ldg(ctx + col), c1 = __ldg(ctx + col + 1);
            float b0 = __ldg(bp + col),  b1 = __ldg(bp + col + 1);
            p0 += tanhf(acc[f][n][0] + b0) * c0 + tanhf(acc[f][n][1] + b1) * c1;
            p1 += tanhf(acc[f][n][2] + b0) * c0 + tanhf(acc[f][n][3] + b1) * c1;
        }
        p0 += __shfl_xor_sync(0xffffffffu, p0, 1);
        p0 += __shfl_xor_sync(0xffffffffu, p0, 2);
        p1 += __shfl_xor_sync(0xffffffffu, p1, 1);
        p1 += __shfl_xor_sync(0xffffffffu, p1, 2);
        if ((lane & 3) == 0) {
            atomicAdd(&g_scores[r0], p0);
            atomicAdd(&g_scores[r0 + 8], p1);
        }
    }
}

// ---------------------------------------------------------------- K4: softmax + pooling + SELU + logits (fp16 reads)
__global__ void __launch_bounds__(512) k_final(
    const int* __restrict__ lengths,
    const float* __restrict__ Wl, const float* __restrict__ bl,
    float* __restrict__ out, int out_size)
{
    __shared__ float sh[512];
    __shared__ float attn[512];
    __shared__ float lg[2];
    int b = blockIdx.x, tid = threadIdx.x;
    int len = lengths[b];
    float s = (tid < len) ? g_scores[b * 512 + tid] : -1e30f;
    sh[tid] = s; __syncthreads();
    for (int o = 256; o > 0; o >>= 1) { if (tid < o) sh[tid] = fmaxf(sh[tid], sh[tid + o]); __syncthreads(); }
    float mx = sh[0]; __syncthreads();
    float e = (tid < len) ? expf(s - mx) : 0.f;
    sh[tid] = e; __syncthreads();
    for (int o = 256; o > 0; o >>= 1) { if (tid < o) sh[tid] += sh[tid + o]; __syncthreads(); }
    float a = e / sh[0];
    attn[tid] = a;
    int attn_ofs = (out_size >= 65792) ? 256 : 0;
    if (out_size != 256) out[attn_ofs + b * 512 + tid] = a;
    if (tid == 0) { lg[0] = 0.f; lg[1] = 0.f; }
    __syncthreads();

    const __half* ob = g_outh + (size_t)b * 512 * 1024;
    float s0 = 0.f, s1 = 0.f;
    for (int t = 0; t < 512; t++) {
        float at = attn[t];
        s0 = fmaf(at, __half2float(ob[(size_t)t * 1024 + tid]),       s0);
        s1 = fmaf(at, __half2float(ob[(size_t)t * 1024 + 512 + tid]), s1);
    }
    const float SC = 1.0507009873554805f, AL = 1.6732632423543772f;
    s0 = (s0 > 0.f) ? SC * s0 : SC * AL * (expf(s0) - 1.f);
    s1 = (s1 > 0.f) ? SC * s1 : SC * AL * (expf(s1) - 1.f);
    float p0 = s0 * Wl[tid]        + s1 * Wl[512 + tid];
    float p1 = s0 * Wl[1024 + tid] + s1 * Wl[1536 + tid];
    #pragma unroll
    for (int o = 16; o > 0; o >>= 1) {
        p0 += __shfl_xor_sync(0xffffffffu, p0, o);
        p1 += __shfl_xor_sync(0xffffffffu, p1, o);
    }
    if ((tid & 31) == 0) { atomicAdd(&lg[0], p0); atomicAdd(&lg[1], p1); }
    __syncthreads();
    if (tid < 2 && out_size != 65536) out[b * 2 + tid] = lg[tid] + bl[tid];
}

// ---------------------------------------------------------------- launch
extern "C" void kernel_launch(void* const* d_in, const int* in_sizes, int n_in,
                              void* d_out, int out_size)
{
    const int*   tokens  = (const int*)d_in[0];
    const int*   lengths = (const int*)d_in[1];
    const float* emb     = (const float*)d_in[2];
    const float* Wih_f   = (const float*)d_in[3];
    const float* Whh_f   = (const float*)d_in[4];
    const float* bih_f   = (const float*)d_in[5];
    const float* bhh_f   = (const float*)d_in[6];
    const float* Wih_b   = (const float*)d_in[7];
    const float* Whh_b   = (const float*)d_in[8];
    const float* bih_b   = (const float*)d_in[9];
    const float* bhh_b   = (const float*)d_in[10];
    const float* Wp      = (const float*)d_in[11];
    const float* bp      = (const float*)d_in[12];
    const float* ctx     = (const float*)d_in[13];
    const float* Wl      = (const float*)d_in[14];
    const float* bl      = (const float*)d_in[15];
    float* out = (float*)d_out;

    k_init<<<BT / 256, 256>>>(tokens, lengths);
    k_convW<<<1536, 256>>>(Wih_f, Wih_b);
    k_convX<<<65536, 256>>>(emb);
    k_convP<<<512, 256>>>(Wp);

    cudaFuncSetAttribute(k_fused, cudaFuncAttributeMaxDynamicSharedMemorySize, F_SMEM);
    k_fused<<<NCTA, 512, F_SMEM>>>(Whh_f, bhh_f, Whh_b, bhh_b, lengths, bih_f, bih_b);

    cudaFuncSetAttribute(k_gemm_proj_tc, cudaFuncAttributeMaxDynamicSharedMemorySize, SMEM_TC2);
    dim3 g3(4, 256);
    k_gemm_proj_tc<<<g3, 512, SMEM_TC2>>>(bp, ctx);

    k_final<<<Bsz, 512>>>(lengths, Wl, bl, out, out_size);
}